// round 3
// baseline (speedup 1.0000x reference)
#include <cuda_runtime.h>
#include <math.h>

#define NT 3072
#define NB 4
#define NC 128
#define MTOT (NB*NT)
#define EPSV 1e-5f
#define SCALEV 0.08838834764831845f  /* 1/sqrt(128) */

// ---------------- scratch (device globals; no allocations allowed) ----------
__device__ float g_vr[(size_t)NB*NT*NC];
__device__ float g_vs[(size_t)NB*NT*NC];
__device__ float g_q [(size_t)NB*NT*NC];
__device__ float g_on[(size_t)NB*NT*NC];
__device__ float g_S [(size_t)NB*NT*NT];   // scores, then P = attn/std in place
__device__ float g_T [(size_t)NB*NT*NT];   // std_rs
__device__ float g_mr[MTOT], g_ms[MTOT], g_varr[MTOT], g_vars[MTOT];
__device__ float g_sumq[MTOT], g_qvr[MTOT];
__device__ float g_rsP[MTOT], g_rPm[MTOT];

// ---------------- Kernel A: v_r / v_s / q projections -----------------------
__global__ void qkv_gemm(const float* __restrict__ x,
                         const float* __restrict__ recv,
                         const float* __restrict__ send,
                         const float* __restrict__ res_r,
                         const float* __restrict__ res_s,
                         const float* __restrict__ ra,
                         const float* __restrict__ qw)
{
    const int mode = blockIdx.y;
    const int r0 = blockIdx.x * 64;
    __shared__ float As[32][65];
    __shared__ float Ws[32][129];
    const int t = threadIdx.x;
    const int ty = t >> 5, tx = t & 31;

    float acc[8][4];
    #pragma unroll
    for (int i = 0; i < 8; i++)
        #pragma unroll
        for (int j = 0; j < 4; j++) acc[i][j] = 0.f;

    const int nsrc = (mode == 2) ? 1 : 2;
    for (int src = 0; src < nsrc; src++) {
        const float* A; const float* W; int ws;
        if (mode == 0) { A = src ? recv : x; W = src ? ra : ra + NC;   ws = 3*NC; }
        else if (mode == 1) { A = src ? send : x; W = src ? ra : ra + 2*NC; ws = 3*NC; }
        else { A = x; W = qw; ws = NC; }

        for (int k0 = 0; k0 < NC; k0 += 32) {
            #pragma unroll
            for (int s = 0; s < 8; s++) {
                int idx = t + 256 * s;
                int m = idx >> 5, k = idx & 31;
                int r = r0 + m;
                int b = r / NT, n = r % NT;
                As[k][m] = A[(size_t)n*NB*NC + b*NC + k0 + k];
            }
            #pragma unroll
            for (int s = 0; s < 16; s++) {
                int idx = t + 256 * s;
                int c = idx >> 5, k = idx & 31;
                Ws[k][c] = W[(size_t)c*ws + k0 + k];
            }
            __syncthreads();
            #pragma unroll
            for (int kk = 0; kk < 32; kk++) {
                float a[8], w[4];
                #pragma unroll
                for (int i = 0; i < 8; i++) a[i] = As[kk][ty + 8*i];
                #pragma unroll
                for (int j = 0; j < 4; j++) w[j] = Ws[kk][tx + 32*j];
                #pragma unroll
                for (int i = 0; i < 8; i++)
                    #pragma unroll
                    for (int j = 0; j < 4; j++) acc[i][j] = fmaf(a[i], w[j], acc[i][j]);
            }
            __syncthreads();
        }
    }

    float* out = (mode == 0) ? g_vr : (mode == 1) ? g_vs : g_q;
    const float* res = (mode == 0) ? res_r : (mode == 1) ? res_s : nullptr;
    #pragma unroll
    for (int i = 0; i < 8; i++) {
        int r = r0 + ty + 8*i;
        int b = r / NT, n = r % NT;
        #pragma unroll
        for (int j = 0; j < 4; j++) {
            int c = tx + 32*j;
            float v = acc[i][j];
            if (res) v += res[(size_t)n*NB*NC + b*NC + c];
            out[(size_t)b*NT*NC + (size_t)n*NC + c] = v;
        }
    }
}

// ---------------- Kernel A2: per-row stats ----------------------------------
__global__ void row_stats()
{
    const int r = blockIdx.x;
    const int c = threadIdx.x;           // 128 threads
    const size_t base = (size_t)r * NC + c;
    float vr = g_vr[base], vs = g_vs[base], q = g_q[base];
    __shared__ float sh[6][128];
    sh[0][c] = vr; sh[1][c] = vr*vr; sh[2][c] = vs;
    sh[3][c] = vs*vs; sh[4][c] = q; sh[5][c] = q*vr;
    __syncthreads();
    for (int off = 64; off > 0; off >>= 1) {
        if (c < off)
            #pragma unroll
            for (int i = 0; i < 6; i++) sh[i][c] += sh[i][c + off];
        __syncthreads();
    }
    if (c == 0) {
        float mr = sh[0][0] * (1.f/NC);
        float ms = sh[2][0] * (1.f/NC);
        g_mr[r] = mr;
        g_ms[r] = ms;
        g_varr[r] = sh[1][0] * (1.f/NC) - mr*mr;
        g_vars[r] = sh[3][0] * (1.f/NC) - ms*ms;
        g_sumq[r] = sh[4][0];
        g_qvr[r]  = sh[5][0];
    }
}

// ---------------- Kernel B: dual GEMM -> scores S and std T -----------------
// MASK IS int32 (bool inputs are uploaded as int32 by the harness)
__global__ void score_gemm(const int* __restrict__ mask)
{
    const int b  = blockIdx.z;
    const int i0 = blockIdx.y * 64;
    const int j0 = blockIdx.x * 64;
    __shared__ float Rs[32][65], Qs[32][65], Ss[32][65];
    const int t = threadIdx.x;
    const int ty = t >> 4, tx = t & 15;

    float accr[4][4], accq[4][4];
    #pragma unroll
    for (int i = 0; i < 4; i++)
        #pragma unroll
        for (int j = 0; j < 4; j++) { accr[i][j] = 0.f; accq[i][j] = 0.f; }

    const float* vr = g_vr + (size_t)b*NT*NC;
    const float* vs = g_vs + (size_t)b*NT*NC;
    const float* q  = g_q  + (size_t)b*NT*NC;

    for (int k0 = 0; k0 < NC; k0 += 32) {
        #pragma unroll
        for (int s = 0; s < 8; s++) {
            int idx = t + 256*s;
            int m = idx >> 5, k = idx & 31;
            Rs[k][m] = vr[(size_t)(i0+m)*NC + k0 + k];
            Qs[k][m] = q [(size_t)(i0+m)*NC + k0 + k];
            Ss[k][m] = vs[(size_t)(j0+m)*NC + k0 + k];
        }
        __syncthreads();
        #pragma unroll
        for (int kk = 0; kk < 32; kk++) {
            float ar[4], aq[4], bs[4];
            #pragma unroll
            for (int i = 0; i < 4; i++) { ar[i] = Rs[kk][ty + 16*i]; aq[i] = Qs[kk][ty + 16*i]; }
            #pragma unroll
            for (int j = 0; j < 4; j++) bs[j] = Ss[kk][tx + 16*j];
            #pragma unroll
            for (int i = 0; i < 4; i++)
                #pragma unroll
                for (int j = 0; j < 4; j++) {
                    accr[i][j] = fmaf(ar[i], bs[j], accr[i][j]);
                    accq[i][j] = fmaf(aq[i], bs[j], accq[i][j]);
                }
        }
        __syncthreads();
    }

    float mr[4], varr[4], sq[4], qvr[4], ms[4], vars[4];
    #pragma unroll
    for (int i = 0; i < 4; i++) {
        int row = b*NT + i0 + ty + 16*i;
        mr[i] = g_mr[row]; varr[i] = g_varr[row];
        sq[i] = g_sumq[row]; qvr[i] = g_qvr[row];
    }
    #pragma unroll
    for (int j = 0; j < 4; j++) {
        int col = b*NT + j0 + tx + 16*j;
        ms[j] = g_ms[col]; vars[j] = g_vars[col];
    }

    #pragma unroll
    for (int i = 0; i < 4; i++) {
        int gi = i0 + ty + 16*i;
        #pragma unroll
        for (int j = 0; j < 4; j++) {
            int gj = j0 + tx + 16*j;
            float cross = (accr[i][j] - (float)NC * mr[i] * ms[j]) * (2.0f/NC);
            float stdv  = sqrtf(varr[i] + vars[j] + cross + EPSV);
            float a = (qvr[i] + accq[i][j] - sq[i]*(mr[i]+ms[j])) / stdv * SCALEV;
            size_t o = (size_t)b*NT*NT + (size_t)gi*NT + gj;
            if (mask[o] != 0) a = -INFINITY;
            g_S[o] = a;
            g_T[o] = stdv;
        }
    }
}

// ---------------- Kernel C: masked softmax + /std + row sums ----------------
__global__ void softmax_row()
{
    const int b = blockIdx.y, i = blockIdx.x;
    const int t = threadIdx.x;                // 256
    const size_t base = (size_t)b*NT*NT + (size_t)i*NT;
    __shared__ float red[256];

    float s[12];
    float m = -INFINITY;
    #pragma unroll
    for (int jj = 0; jj < 12; jj++) {
        s[jj] = g_S[base + t + 256*jj];
        m = fmaxf(m, s[jj]);
    }
    red[t] = m; __syncthreads();
    for (int off = 128; off > 0; off >>= 1) {
        if (t < off) red[t] = fmaxf(red[t], red[t + off]);
        __syncthreads();
    }
    m = red[0]; __syncthreads();

    if (m == -INFINITY) {   // fully masked row: reference yields zeros
        #pragma unroll
        for (int jj = 0; jj < 12; jj++) g_S[base + t + 256*jj] = 0.f;
        if (t == 0) { g_rsP[b*NT+i] = 0.f; g_rPm[b*NT+i] = 0.f; }
        return;
    }

    float sum = 0.f;
    #pragma unroll
    for (int jj = 0; jj < 12; jj++) { s[jj] = expf(s[jj] - m); sum += s[jj]; }
    red[t] = sum; __syncthreads();
    for (int off = 128; off > 0; off >>= 1) {
        if (t < off) red[t] += red[t + off];
        __syncthreads();
    }
    const float inv = 1.f / red[0]; __syncthreads();

    const float mr_i = g_mr[b*NT + i];
    float rp = 0.f, rpm = 0.f;
    #pragma unroll
    for (int jj = 0; jj < 12; jj++) {
        int j = t + 256*jj;
        float p = s[jj] * inv / g_T[base + j];
        g_S[base + j] = p;
        rp  += p;
        rpm += p * (mr_i + g_ms[b*NT + j]);
    }
    red[t] = rp; __syncthreads();
    for (int off = 128; off > 0; off >>= 1) {
        if (t < off) red[t] += red[t + off];
        __syncthreads();
    }
    rp = red[0]; __syncthreads();
    red[t] = rpm; __syncthreads();
    for (int off = 128; off > 0; off >>= 1) {
        if (t < off) red[t] += red[t + off];
        __syncthreads();
    }
    if (t == 0) {
        g_rsP[b*NT+i] = rp;
        g_rPm[b*NT+i] = red[0];
    }
}

// ---------------- Kernel D: out = P@v_s + rsP*v_r - rPm, then LN ------------
__global__ void out_gemm(const float* __restrict__ nw, const float* __restrict__ nb)
{
    const int b  = blockIdx.y;
    const int i0 = blockIdx.x * 64;
    __shared__ float Ps[32][65];
    __shared__ float Vs[32][128];
    const int t = threadIdx.x;
    const int ty = t >> 5, tx = t & 31;

    float acc[8][4];
    #pragma unroll
    for (int i = 0; i < 8; i++)
        #pragma unroll
        for (int j = 0; j < 4; j++) acc[i][j] = 0.f;

    const float* P  = g_S  + (size_t)b*NT*NT;
    const float* vs = g_vs + (size_t)b*NT*NC;

    for (int k0 = 0; k0 < NT; k0 += 32) {
        #pragma unroll
        for (int s = 0; s < 8; s++) {
            int idx = t + 256*s;
            int m = idx >> 5, k = idx & 31;
            Ps[k][m] = P[(size_t)(i0+m)*NT + k0 + k];
        }
        #pragma unroll
        for (int s = 0; s < 16; s++) {
            int idx = t + 256*s;
            int d = idx & 127, k = idx >> 7;
            Vs[k][d] = vs[(size_t)(k0+k)*NC + d];
        }
        __syncthreads();
        #pragma unroll
        for (int kk = 0; kk < 32; kk++) {
            float a[8], w[4];
            #pragma unroll
            for (int i = 0; i < 8; i++) a[i] = Ps[kk][ty + 8*i];
            #pragma unroll
            for (int j = 0; j < 4; j++) w[j] = Vs[kk][tx + 32*j];
            #pragma unroll
            for (int i = 0; i < 8; i++)
                #pragma unroll
                for (int j = 0; j < 4; j++) acc[i][j] = fmaf(a[i], w[j], acc[i][j]);
        }
        __syncthreads();
    }

    #pragma unroll
    for (int i = 0; i < 8; i++) {
        int r = i0 + ty + 8*i;
        float rp  = g_rsP[b*NT + r];
        float rpm = g_rPm[b*NT + r];
        #pragma unroll
        for (int j = 0; j < 4; j++) {
            int d = tx + 32*j;
            float v = acc[i][j] + rp * g_vr[(size_t)b*NT*NC + (size_t)r*NC + d] - rpm;
            v = v * nw[d] + nb[d];
            g_on[(size_t)b*NT*NC + (size_t)r*NC + d] = v;
        }
    }
}

// ---------------- Kernel E: three output projections, transposed store ------
__global__ void proj_gemm(const float* __restrict__ pw, const float* __restrict__ pb,
                          const float* __restrict__ rw, const float* __restrict__ rb,
                          const float* __restrict__ sw, const float* __restrict__ sb,
                          float* __restrict__ out)
{
    const int mode = blockIdx.y;
    const int r0 = blockIdx.x * 64;
    const float* src = (mode == 0) ? g_on : (mode == 1) ? g_vr : g_vs;
    const float* W   = (mode == 0) ? pw   : (mode == 1) ? rw   : sw;
    const float* bia = (mode == 0) ? pb   : (mode == 1) ? rb   : sb;

    __shared__ float As[32][65];
    __shared__ float Ws[32][129];
    const int t = threadIdx.x;
    const int ty = t >> 5, tx = t & 31;

    float acc[8][4];
    #pragma unroll
    for (int i = 0; i < 8; i++)
        #pragma unroll
        for (int j = 0; j < 4; j++) acc[i][j] = 0.f;

    for (int k0 = 0; k0 < NC; k0 += 32) {
        #pragma unroll
        for (int s = 0; s < 8; s++) {
            int idx = t + 256*s;
            int m = idx >> 5, k = idx & 31;
            As[k][m] = src[(size_t)(r0+m)*NC + k0 + k];
        }
        #pragma unroll
        for (int s = 0; s < 16; s++) {
            int idx = t + 256*s;
            int c = idx >> 5, k = idx & 31;
            Ws[k][c] = W[(size_t)c*NC + k0 + k];
        }
        __syncthreads();
        #pragma unroll
        for (int kk = 0; kk < 32; kk++) {
            float a[8], w[4];
            #pragma unroll
            for (int i = 0; i < 8; i++) a[i] = As[kk][ty + 8*i];
            #pragma unroll
            for (int j = 0; j < 4; j++) w[j] = Ws[kk][tx + 32*j];
            #pragma unroll
            for (int i = 0; i < 8; i++)
                #pragma unroll
                for (int j = 0; j < 4; j++) acc[i][j] = fmaf(a[i], w[j], acc[i][j]);
        }
        __syncthreads();
    }

    const size_t obase = (size_t)mode * MTOT * NC;
    #pragma unroll
    for (int i = 0; i < 8; i++) {
        int r = r0 + ty + 8*i;
        int b = r / NT, n = r % NT;
        #pragma unroll
        for (int j = 0; j < 4; j++) {
            int c = tx + 32*j;
            out[obase + (size_t)n*NB*NC + b*NC + c] = acc[i][j] + bia[c];
        }
    }
}

// ---------------- launch ----------------------------------------------------
extern "C" void kernel_launch(void* const* d_in, const int* in_sizes, int n_in,
                              void* d_out, int out_size)
{
    const float* x    = (const float*)d_in[0];
    const int*   mask = (const int*)d_in[1];      // bool uploaded as int32
    const float* recv = (const float*)d_in[2];
    const float* send = (const float*)d_in[3];
    const float* resr = (const float*)d_in[4];
    const float* ress = (const float*)d_in[5];
    const float* ra   = (const float*)d_in[6];
    const float* qw   = (const float*)d_in[7];
    const float* pw   = (const float*)d_in[8];
    const float* pb   = (const float*)d_in[9];
    const float* rw   = (const float*)d_in[10];
    const float* rb   = (const float*)d_in[11];
    const float* sw   = (const float*)d_in[12];
    const float* sb   = (const float*)d_in[13];
    const float* nw   = (const float*)d_in[14];
    const float* nb   = (const float*)d_in[15];
    float* out = (float*)d_out;

    qkv_gemm<<<dim3(MTOT/64, 3), 256>>>(x, recv, send, resr, ress, ra, qw);
    row_stats<<<MTOT, 128>>>();
    score_gemm<<<dim3(NT/64, NT/64, NB), 256>>>(mask);
    softmax_row<<<dim3(NT, NB), 256>>>();
    out_gemm<<<dim3(NT/64, NB), 256>>>(nw, nb);
    proj_gemm<<<dim3(MTOT/64, 3), 256>>>(pw, pb, rw, rb, sw, sb, out);
}

// round 6
// speedup vs baseline: 1.4338x; 1.4338x over previous
#include <cuda_runtime.h>
#include <cuda_bf16.h>
#include <math.h>
#include <stdint.h>

#define NT 3072
#define NB 4
#define NC 128
#define MTOT (NB*NT)
#define EPSV 1e-5f
#define SCALEV 0.08838834764831845f  /* 1/sqrt(128) */

// ---------------- scratch (device globals; no allocations allowed) ----------
__device__ float g_vr[(size_t)NB*NT*NC];
__device__ float g_vs[(size_t)NB*NT*NC];
__device__ float g_q [(size_t)NB*NT*NC];
__device__ float g_on[(size_t)NB*NT*NC];
__device__ float g_S [(size_t)NB*NT*NT];   // scores, then P = attn/std in place
__device__ float g_T [(size_t)NB*NT*NT];   // std_rs
__device__ float g_mr[MTOT], g_ms[MTOT], g_varr[MTOT], g_vars[MTOT];
__device__ float g_sumq[MTOT], g_qvr[MTOT];
__device__ float g_rsP[MTOT], g_rPm[MTOT];

// ---------------- bf16 split helpers ----------------------------------------
__device__ __forceinline__ uint32_t pack_hi(float x, float y) {
    __nv_bfloat162 h;
    h.x = __float2bfloat16(x); h.y = __float2bfloat16(y);
    return *(uint32_t*)&h;
}
__device__ __forceinline__ uint32_t pack_lo(float x, float y) {
    __nv_bfloat162 h;
    h.x = __float2bfloat16(x - __bfloat162float(__float2bfloat16(x)));
    h.y = __float2bfloat16(y - __bfloat162float(__float2bfloat16(y)));
    return *(uint32_t*)&h;
}

#define MMA16816(d, a, b) \
    asm volatile("mma.sync.aligned.m16n8k16.row.col.f32.bf16.bf16.f32 " \
        "{%0,%1,%2,%3}, {%4,%5,%6,%7}, {%8,%9}, {%0,%1,%2,%3};" \
        : "+f"((d)[0]), "+f"((d)[1]), "+f"((d)[2]), "+f"((d)[3]) \
        : "r"((a)[0]), "r"((a)[1]), "r"((a)[2]), "r"((a)[3]), \
          "r"((b)[0]), "r"((b)[1]))

// ---------------- Kernel B: dual GEMM via HMMA -> scores S and std T --------
// smem planes: 128 rows x 64 bf16-pairs, row stride 68 words (bank-clean)
#define PLANE 8704            // 128*68 words
#define SC_SMEM ((6*PLANE + 6*128) * 4)

__global__ void __launch_bounds__(512, 1) score_mma(const int* __restrict__ mask)
{
    extern __shared__ __align__(16) uint32_t sm[];
    uint32_t* qh = sm;
    uint32_t* ql = qh + PLANE;
    uint32_t* rh = ql + PLANE;
    uint32_t* rl = rh + PLANE;
    uint32_t* bh = rl + PLANE;
    uint32_t* bl = bh + PLANE;
    float* s_mr   = (float*)(bl + PLANE);
    float* s_varr = s_mr + 128;
    float* s_sq   = s_varr + 128;
    float* s_qvr  = s_sq + 128;
    float* s_ms   = s_qvr + 128;
    float* s_vars = s_ms + 128;

    const int tid = threadIdx.x;
    const int wid = tid >> 5, lane = tid & 31;
    const int g = lane >> 2, t = lane & 3;
    const int wr = (wid & 3) * 32;        // warp m-offset in tile
    const int wc = (wid >> 2) * 32;       // warp n-offset in tile
    const int i0 = blockIdx.x * 128, b = blockIdx.y, js = blockIdx.z;

    // ---- A conversion (q, v_r -> hi/lo bf16 planes) + row stats
    const float* qsrc = g_q  + ((size_t)b*NT + i0) * NC;
    const float* rsrc = g_vr + ((size_t)b*NT + i0) * NC;
    for (int idx = tid; idx < 128*64; idx += 512) {
        const int row = idx >> 6, kp = idx & 63;
        float2 v = ((const float2*)(qsrc + (size_t)row*NC))[kp];
        qh[row*68 + kp] = pack_hi(v.x, v.y);
        ql[row*68 + kp] = pack_lo(v.x, v.y);
        float2 w = ((const float2*)(rsrc + (size_t)row*NC))[kp];
        rh[row*68 + kp] = pack_hi(w.x, w.y);
        rl[row*68 + kp] = pack_lo(w.x, w.y);
    }
    if (tid < 128) {
        const int r = b*NT + i0 + tid;
        s_mr[tid] = g_mr[r]; s_varr[tid] = g_varr[r];
        s_sq[tid] = g_sumq[r]; s_qvr[tid] = g_qvr[r];
    }

    for (int jt = 0; jt < 4; jt++) {
        const int j0 = (js * 4 + jt) * 128;
        __syncthreads();    // prior epilogue done / A planes ready

        // ---- B conversion (v_s -> hi/lo planes) + col stats
        const float* bsrc = g_vs + ((size_t)b*NT + j0) * NC;
        for (int idx = tid; idx < 128*64; idx += 512) {
            const int row = idx >> 6, kp = idx & 63;
            float2 v = ((const float2*)(bsrc + (size_t)row*NC))[kp];
            bh[row*68 + kp] = pack_hi(v.x, v.y);
            bl[row*68 + kp] = pack_lo(v.x, v.y);
        }
        if (tid < 128) {
            const int c = b*NT + j0 + tid;
            s_ms[tid] = g_ms[c]; s_vars[tid] = g_vars[c];
        }
        __syncthreads();

        // ---- MMA mainloop
        float dR[2][4][4], dQ[2][4][4];
        #pragma unroll
        for (int mt = 0; mt < 2; mt++)
            #pragma unroll
            for (int nt = 0; nt < 4; nt++)
                #pragma unroll
                for (int e = 0; e < 4; e++) { dR[mt][nt][e] = 0.f; dQ[mt][nt][e] = 0.f; }

        #pragma unroll
        for (int ks = 0; ks < 8; ks++) {
            const int kp0 = ks * 8 + t;
            uint32_t Bh[4][2], Bl[4][2];
            #pragma unroll
            for (int nt = 0; nt < 4; nt++) {
                const int br = (wc + nt*8 + g) * 68;
                Bh[nt][0] = bh[br + kp0]; Bh[nt][1] = bh[br + kp0 + 4];
                Bl[nt][0] = bl[br + kp0]; Bl[nt][1] = bl[br + kp0 + 4];
            }
            #pragma unroll
            for (int mt = 0; mt < 2; mt++) {
                const int ar = (wr + mt*16 + g) * 68;
                const int ar8 = ar + 8*68;
                uint32_t Ah[4], Al[4];
                // q
                Ah[0] = qh[ar + kp0];  Ah[1] = qh[ar8 + kp0];
                Ah[2] = qh[ar + kp0+4]; Ah[3] = qh[ar8 + kp0+4];
                Al[0] = ql[ar + kp0];  Al[1] = ql[ar8 + kp0];
                Al[2] = ql[ar + kp0+4]; Al[3] = ql[ar8 + kp0+4];
                #pragma unroll
                for (int nt = 0; nt < 4; nt++) {
                    MMA16816(dQ[mt][nt], Ah, Bh[nt]);
                    MMA16816(dQ[mt][nt], Ah, Bl[nt]);
                    MMA16816(dQ[mt][nt], Al, Bh[nt]);
                }
                // v_r
                Ah[0] = rh[ar + kp0];  Ah[1] = rh[ar8 + kp0];
                Ah[2] = rh[ar + kp0+4]; Ah[3] = rh[ar8 + kp0+4];
                Al[0] = rl[ar + kp0];  Al[1] = rl[ar8 + kp0];
                Al[2] = rl[ar + kp0+4]; Al[3] = rl[ar8 + kp0+4];
                #pragma unroll
                for (int nt = 0; nt < 4; nt++) {
                    MMA16816(dR[mt][nt], Ah, Bh[nt]);
                    MMA16816(dR[mt][nt], Ah, Bl[nt]);
                    MMA16816(dR[mt][nt], Al, Bh[nt]);
                }
            }
        }

        // ---- epilogue: std + score + mask, write S and T
        #pragma unroll
        for (int mt = 0; mt < 2; mt++) {
            #pragma unroll
            for (int rg = 0; rg < 2; rg++) {
                const int li = wr + mt*16 + g + rg*8;       // local row
                const float mr = s_mr[li], varr = s_varr[li];
                const float sq = s_sq[li], qvr = s_qvr[li];
                const size_t orow = ((size_t)b*NT + i0 + li) * NT + j0;
                #pragma unroll
                for (int nt = 0; nt < 4; nt++) {
                    const int lj = wc + nt*8 + t*2;         // local col (pair)
                    const int2 mk = *(const int2*)(mask + orow + lj);
                    float so[2], to[2];
                    #pragma unroll
                    for (int c = 0; c < 2; c++) {
                        const float msj = s_ms[lj + c], vars = s_vars[lj + c];
                        const float accr = dR[mt][nt][rg*2 + c];
                        const float accq = dQ[mt][nt][rg*2 + c];
                        const float cross = (accr - 128.f * mr * msj) * (2.f / 128.f);
                        const float stdv = sqrtf(varr + vars + cross + EPSV);
                        float a = (qvr + accq - sq * (mr + msj)) / stdv * SCALEV;
                        if ((c == 0 ? mk.x : mk.y) != 0) a = -INFINITY;
                        so[c] = a; to[c] = stdv;
                    }
                    *(float2*)(g_S + orow + lj) = make_float2(so[0], so[1]);
                    *(float2*)(g_T + orow + lj) = make_float2(to[0], to[1]);
                }
            }
        }
    }
}

// ---------------- Kernel A: v_r / v_s / q projections -----------------------
__global__ void qkv_gemm(const float* __restrict__ x,
                         const float* __restrict__ recv,
                         const float* __restrict__ send,
                         const float* __restrict__ res_r,
                         const float* __restrict__ res_s,
                         const float* __restrict__ ra,
                         const float* __restrict__ qw)
{
    const int mode = blockIdx.y;
    const int r0 = blockIdx.x * 64;
    __shared__ float As[32][65];
    __shared__ float Ws[32][129];
    const int t = threadIdx.x;
    const int ty = t >> 5, tx = t & 31;

    float acc[8][4];
    #pragma unroll
    for (int i = 0; i < 8; i++)
        #pragma unroll
        for (int j = 0; j < 4; j++) acc[i][j] = 0.f;

    const int nsrc = (mode == 2) ? 1 : 2;
    for (int src = 0; src < nsrc; src++) {
        const float* A; const float* W; int ws;
        if (mode == 0) { A = src ? recv : x; W = src ? ra : ra + NC;   ws = 3*NC; }
        else if (mode == 1) { A = src ? send : x; W = src ? ra : ra + 2*NC; ws = 3*NC; }
        else { A = x; W = qw; ws = NC; }

        for (int k0 = 0; k0 < NC; k0 += 32) {
            #pragma unroll
            for (int s = 0; s < 8; s++) {
                int idx = t + 256 * s;
                int m = idx >> 5, k = idx & 31;
                int r = r0 + m;
                int bb = r / NT, n = r % NT;
                As[k][m] = A[(size_t)n*NB*NC + bb*NC + k0 + k];
            }
            #pragma unroll
            for (int s = 0; s < 16; s++) {
                int idx = t + 256 * s;
                int c = idx >> 5, k = idx & 31;
                Ws[k][c] = W[(size_t)c*ws + k0 + k];
            }
            __syncthreads();
            #pragma unroll
            for (int kk = 0; kk < 32; kk++) {
                float a[8], w[4];
                #pragma unroll
                for (int i = 0; i < 8; i++) a[i] = As[kk][ty + 8*i];
                #pragma unroll
                for (int j = 0; j < 4; j++) w[j] = Ws[kk][tx + 32*j];
                #pragma unroll
                for (int i = 0; i < 8; i++)
                    #pragma unroll
                    for (int j = 0; j < 4; j++) acc[i][j] = fmaf(a[i], w[j], acc[i][j]);
            }
            __syncthreads();
        }
    }

    float* out = (mode == 0) ? g_vr : (mode == 1) ? g_vs : g_q;
    const float* res = (mode == 0) ? res_r : (mode == 1) ? res_s : nullptr;
    #pragma unroll
    for (int i = 0; i < 8; i++) {
        int r = r0 + ty + 8*i;
        int bb = r / NT, n = r % NT;
        #pragma unroll
        for (int j = 0; j < 4; j++) {
            int c = tx + 32*j;
            float v = acc[i][j];
            if (res) v += res[(size_t)n*NB*NC + bb*NC + c];
            out[(size_t)bb*NT*NC + (size_t)n*NC + c] = v;
        }
    }
}

// ---------------- Kernel A2: per-row stats ----------------------------------
__global__ void row_stats()
{
    const int r = blockIdx.x;
    const int c = threadIdx.x;           // 128 threads
    const size_t base = (size_t)r * NC + c;
    float vr = g_vr[base], vs = g_vs[base], q = g_q[base];
    __shared__ float sh[6][128];
    sh[0][c] = vr; sh[1][c] = vr*vr; sh[2][c] = vs;
    sh[3][c] = vs*vs; sh[4][c] = q; sh[5][c] = q*vr;
    __syncthreads();
    for (int off = 64; off > 0; off >>= 1) {
        if (c < off)
            #pragma unroll
            for (int i = 0; i < 6; i++) sh[i][c] += sh[i][c + off];
        __syncthreads();
    }
    if (c == 0) {
        float mr = sh[0][0] * (1.f/NC);
        float ms = sh[2][0] * (1.f/NC);
        g_mr[r] = mr;
        g_ms[r] = ms;
        g_varr[r] = sh[1][0] * (1.f/NC) - mr*mr;
        g_vars[r] = sh[3][0] * (1.f/NC) - ms*ms;
        g_sumq[r] = sh[4][0];
        g_qvr[r]  = sh[5][0];
    }
}

// ---------------- Kernel C: masked softmax + /std + row sums ----------------
__global__ void softmax_row()
{
    const int b = blockIdx.y, i = blockIdx.x;
    const int t = threadIdx.x;                // 256
    const size_t base = (size_t)b*NT*NT + (size_t)i*NT;
    __shared__ float red[256];

    float s[12];
    float m = -INFINITY;
    #pragma unroll
    for (int jj = 0; jj < 12; jj++) {
        s[jj] = g_S[base + t + 256*jj];
        m = fmaxf(m, s[jj]);
    }
    red[t] = m; __syncthreads();
    for (int off = 128; off > 0; off >>= 1) {
        if (t < off) red[t] = fmaxf(red[t], red[t + off]);
        __syncthreads();
    }
    m = red[0]; __syncthreads();

    if (m == -INFINITY) {
        #pragma unroll
        for (int jj = 0; jj < 12; jj++) g_S[base + t + 256*jj] = 0.f;
        if (t == 0) { g_rsP[b*NT+i] = 0.f; g_rPm[b*NT+i] = 0.f; }
        return;
    }

    float sum = 0.f;
    #pragma unroll
    for (int jj = 0; jj < 12; jj++) { s[jj] = expf(s[jj] - m); sum += s[jj]; }
    red[t] = sum; __syncthreads();
    for (int off = 128; off > 0; off >>= 1) {
        if (t < off) red[t] += red[t + off];
        __syncthreads();
    }
    const float inv = 1.f / red[0]; __syncthreads();

    const float mr_i = g_mr[b*NT + i];
    float rp = 0.f, rpm = 0.f;
    #pragma unroll
    for (int jj = 0; jj < 12; jj++) {
        int j = t + 256*jj;
        float p = s[jj] * inv / g_T[base + j];
        g_S[base + j] = p;
        rp  += p;
        rpm += p * (mr_i + g_ms[b*NT + j]);
    }
    red[t] = rp; __syncthreads();
    for (int off = 128; off > 0; off >>= 1) {
        if (t < off) red[t] += red[t + off];
        __syncthreads();
    }
    rp = red[0]; __syncthreads();
    red[t] = rpm; __syncthreads();
    for (int off = 128; off > 0; off >>= 1) {
        if (t < off) red[t] += red[t + off];
        __syncthreads();
    }
    if (t == 0) {
        g_rsP[b*NT+i] = rp;
        g_rPm[b*NT+i] = red[0];
    }
}

// ---------------- Kernel D: out = P@v_s + rsP*v_r - rPm, then LN ------------
__global__ void out_gemm(const float* __restrict__ nw, const float* __restrict__ nb)
{
    const int b  = blockIdx.y;
    const int i0 = blockIdx.x * 64;
    __shared__ float Ps[32][65];
    __shared__ float Vs[32][128];
    const int t = threadIdx.x;
    const int ty = t >> 5, tx = t & 31;

    float acc[8][4];
    #pragma unroll
    for (int i = 0; i < 8; i++)
        #pragma unroll
        for (int j = 0; j < 4; j++) acc[i][j] = 0.f;

    const float* P  = g_S  + (size_t)b*NT*NT;
    const float* vs = g_vs + (size_t)b*NT*NC;

    for (int k0 = 0; k0 < NT; k0 += 32) {
        #pragma unroll
        for (int s = 0; s < 8; s++) {
            int idx = t + 256*s;
            int m = idx >> 5, k = idx & 31;
            Ps[k][m] = P[(size_t)(i0+m)*NT + k0 + k];
        }
        #pragma unroll
        for (int s = 0; s < 16; s++) {
            int idx = t + 256*s;
            int d = idx & 127, k = idx >> 7;
            Vs[k][d] = vs[(size_t)(k0+k)*NC + d];
        }
        __syncthreads();
        #pragma unroll
        for (int kk = 0; kk < 32; kk++) {
            float a[8], w[4];
            #pragma unroll
            for (int i = 0; i < 8; i++) a[i] = Ps[kk][ty + 8*i];
            #pragma unroll
            for (int j = 0; j < 4; j++) w[j] = Vs[kk][tx + 32*j];
            #pragma unroll
            for (int i = 0; i < 8; i++)
                #pragma unroll
                for (int j = 0; j < 4; j++) acc[i][j] = fmaf(a[i], w[j], acc[i][j]);
        }
        __syncthreads();
    }

    #pragma unroll
    for (int i = 0; i < 8; i++) {
        int r = i0 + ty + 8*i;
        float rp  = g_rsP[b*NT + r];
        float rpm = g_rPm[b*NT + r];
        #pragma unroll
        for (int j = 0; j < 4; j++) {
            int d = tx + 32*j;
            float v = acc[i][j] + rp * g_vr[(size_t)b*NT*NC + (size_t)r*NC + d] - rpm;
            v = v * nw[d] + nb[d];
            g_on[(size_t)b*NT*NC + (size_t)r*NC + d] = v;
        }
    }
}

// ---------------- Kernel E: three output projections, transposed store ------
__global__ void proj_gemm(const float* __restrict__ pw, const float* __restrict__ pb,
                          const float* __restrict__ rw, const float* __restrict__ rb,
                          const float* __restrict__ sw, const float* __restrict__ sb,
                          float* __restrict__ out)
{
    const int mode = blockIdx.y;
    const int r0 = blockIdx.x * 64;
    const float* src = (mode == 0) ? g_on : (mode == 1) ? g_vr : g_vs;
    const float* W   = (mode == 0) ? pw   : (mode == 1) ? rw   : sw;
    const float* bia = (mode == 0) ? pb   : (mode == 1) ? rb   : sb;

    __shared__ float As[32][65];
    __shared__ float Ws[32][129];
    const int t = threadIdx.x;
    const int ty = t >> 5, tx = t & 31;

    float acc[8][4];
    #pragma unroll
    for (int i = 0; i < 8; i++)
        #pragma unroll
        for (int j = 0; j < 4; j++) acc[i][j] = 0.f;

    for (int k0 = 0; k0 < NC; k0 += 32) {
        #pragma unroll
        for (int s = 0; s < 8; s++) {
            int idx = t + 256*s;
            int m = idx >> 5, k = idx & 31;
            As[k][m] = src[(size_t)(r0+m)*NC + k0 + k];
        }
        #pragma unroll
        for (int s = 0; s < 16; s++) {
            int idx = t + 256*s;
            int c = idx >> 5, k = idx & 31;
            Ws[k][c] = W[(size_t)c*NC + k0 + k];
        }
        __syncthreads();
        #pragma unroll
        for (int kk = 0; kk < 32; kk++) {
            float a[8], w[4];
            #pragma unroll
            for (int i = 0; i < 8; i++) a[i] = As[kk][ty + 8*i];
            #pragma unroll
            for (int j = 0; j < 4; j++) w[j] = Ws[kk][tx + 32*j];
            #pragma unroll
            for (int i = 0; i < 8; i++)
                #pragma unroll
                for (int j = 0; j < 4; j++) acc[i][j] = fmaf(a[i], w[j], acc[i][j]);
        }
        __syncthreads();
    }

    const size_t obase = (size_t)mode * MTOT * NC;
    #pragma unroll
    for (int i = 0; i < 8; i++) {
        int r = r0 + ty + 8*i;
        int b = r / NT, n = r % NT;
        #pragma unroll
        for (int j = 0; j < 4; j++) {
            int c = tx + 32*j;
            out[obase + (size_t)n*NB*NC + b*NC + c] = acc[i][j] + bia[c];
        }
    }
}

// ---------------- launch ----------------------------------------------------
extern "C" void kernel_launch(void* const* d_in, const int* in_sizes, int n_in,
                              void* d_out, int out_size)
{
    const float* x    = (const float*)d_in[0];
    const int*   mask = (const int*)d_in[1];      // bool uploaded as int32
    const float* recv = (const float*)d_in[2];
    const float* send = (const float*)d_in[3];
    const float* resr = (const float*)d_in[4];
    const float* ress = (const float*)d_in[5];
    const float* ra   = (const float*)d_in[6];
    const float* qw   = (const float*)d_in[7];
    const float* pw   = (const float*)d_in[8];
    const float* pb   = (const float*)d_in[9];
    const float* rw   = (const float*)d_in[10];
    const float* rb   = (const float*)d_in[11];
    const float* sw   = (const float*)d_in[12];
    const float* sb   = (const float*)d_in[13];
    const float* nw   = (const float*)d_in[14];
    const float* nb   = (const float*)d_in[15];
    float* out = (float*)d_out;

    cudaFuncSetAttribute(score_mma, cudaFuncAttributeMaxDynamicSharedMemorySize, SC_SMEM);

    qkv_gemm<<<dim3(MTOT/64, 3), 256>>>(x, recv, send, resr, ress, ra, qw);
    row_stats<<<MTOT, 128>>>();
    score_mma<<<dim3(NT/128, NB, 6), 512, SC_SMEM>>>(mask);
    softmax_row<<<dim3(NT, NB), 256>>>();
    out_gemm<<<dim3(NT/64, NB), 256>>>(nw, nb);
    proj_gemm<<<dim3(MTOT/64, 3), 256>>>(pw, pb, rw, rb, sw, sb, out);
}

// round 7
// speedup vs baseline: 1.9379x; 1.3516x over previous
#include <cuda_runtime.h>
#include <cuda_bf16.h>
#include <math.h>
#include <stdint.h>

#define NT 3072
#define NB 4
#define NC 128
#define MTOT (NB*NT)
#define EPSV 1e-5f
#define SCALEV 0.08838834764831845f  /* 1/sqrt(128) */

// ---------------- scratch (device globals; no allocations allowed) ----------
__device__ float g_vr[(size_t)NB*NT*NC];
__device__ float g_vs[(size_t)NB*NT*NC];
__device__ float g_q [(size_t)NB*NT*NC];
__device__ float g_on[(size_t)NB*NT*NC];
__device__ float g_S [(size_t)NB*NT*NT];   // scores, then P = attn/std in place
__device__ float g_T [(size_t)NB*NT*NT];   // std_rs
__device__ float g_mr[MTOT], g_ms[MTOT], g_varr[MTOT], g_vars[MTOT];
__device__ float g_sumq[MTOT], g_qvr[MTOT];
__device__ float g_rsP[MTOT], g_rPm[MTOT];

// ---------------- bf16 split helpers ----------------------------------------
__device__ __forceinline__ uint32_t pack_hi(float x, float y) {
    __nv_bfloat162 h;
    h.x = __float2bfloat16(x); h.y = __float2bfloat16(y);
    return *(uint32_t*)&h;
}
__device__ __forceinline__ uint32_t pack_lo(float x, float y) {
    __nv_bfloat162 h;
    h.x = __float2bfloat16(x - __bfloat162float(__float2bfloat16(x)));
    h.y = __float2bfloat16(y - __bfloat162float(__float2bfloat16(y)));
    return *(uint32_t*)&h;
}

#define MMA16816(d, a, b) \
    asm volatile("mma.sync.aligned.m16n8k16.row.col.f32.bf16.bf16.f32 " \
        "{%0,%1,%2,%3}, {%4,%5,%6,%7}, {%8,%9}, {%0,%1,%2,%3};" \
        : "+f"((d)[0]), "+f"((d)[1]), "+f"((d)[2]), "+f"((d)[3]) \
        : "r"((a)[0]), "r"((a)[1]), "r"((a)[2]), "r"((a)[3]), \
          "r"((b)[0]), "r"((b)[1]))

// ---------------- Kernel B: dual GEMM via HMMA -> scores S and std T --------
// smem planes: 128 rows x 64 bf16-pairs, row stride 68 words (bank-clean)
#define PLANE 8704            // 128*68 words
#define SC_SMEM ((6*PLANE + 6*128) * 4)

__global__ void __launch_bounds__(512, 1) score_mma(const int* __restrict__ mask)
{
    extern __shared__ __align__(16) uint32_t sm[];
    uint32_t* qh = sm;
    uint32_t* ql = qh + PLANE;
    uint32_t* rh = ql + PLANE;
    uint32_t* rl = rh + PLANE;
    uint32_t* bh = rl + PLANE;
    uint32_t* bl = bh + PLANE;
    float* s_mr   = (float*)(bl + PLANE);
    float* s_varr = s_mr + 128;
    float* s_sq   = s_varr + 128;
    float* s_qvr  = s_sq + 128;
    float* s_ms   = s_qvr + 128;
    float* s_vars = s_ms + 128;

    const int tid = threadIdx.x;
    const int wid = tid >> 5, lane = tid & 31;
    const int g = lane >> 2, t = lane & 3;
    const int wr = (wid & 3) * 32;        // warp m-offset in tile
    const int wc = (wid >> 2) * 32;       // warp n-offset in tile
    const int i0 = blockIdx.x * 128, b = blockIdx.y, js = blockIdx.z;

    // ---- A conversion (q, v_r -> hi/lo bf16 planes) + row stats
    const float* qsrc = g_q  + ((size_t)b*NT + i0) * NC;
    const float* rsrc = g_vr + ((size_t)b*NT + i0) * NC;
    for (int idx = tid; idx < 128*64; idx += 512) {
        const int row = idx >> 6, kp = idx & 63;
        float2 v = ((const float2*)(qsrc + (size_t)row*NC))[kp];
        qh[row*68 + kp] = pack_hi(v.x, v.y);
        ql[row*68 + kp] = pack_lo(v.x, v.y);
        float2 w = ((const float2*)(rsrc + (size_t)row*NC))[kp];
        rh[row*68 + kp] = pack_hi(w.x, w.y);
        rl[row*68 + kp] = pack_lo(w.x, w.y);
    }
    if (tid < 128) {
        const int r = b*NT + i0 + tid;
        s_mr[tid] = g_mr[r]; s_varr[tid] = g_varr[r];
        s_sq[tid] = g_sumq[r]; s_qvr[tid] = g_qvr[r];
    }

    for (int jt = 0; jt < 4; jt++) {
        const int j0 = (js * 4 + jt) * 128;
        __syncthreads();    // prior epilogue done / A planes ready

        // ---- B conversion (v_s -> hi/lo planes) + col stats
        const float* bsrc = g_vs + ((size_t)b*NT + j0) * NC;
        for (int idx = tid; idx < 128*64; idx += 512) {
            const int row = idx >> 6, kp = idx & 63;
            float2 v = ((const float2*)(bsrc + (size_t)row*NC))[kp];
            bh[row*68 + kp] = pack_hi(v.x, v.y);
            bl[row*68 + kp] = pack_lo(v.x, v.y);
        }
        if (tid < 128) {
            const int c = b*NT + j0 + tid;
            s_ms[tid] = g_ms[c]; s_vars[tid] = g_vars[c];
        }
        __syncthreads();

        // ---- MMA mainloop
        float dR[2][4][4], dQ[2][4][4];
        #pragma unroll
        for (int mt = 0; mt < 2; mt++)
            #pragma unroll
            for (int nt = 0; nt < 4; nt++)
                #pragma unroll
                for (int e = 0; e < 4; e++) { dR[mt][nt][e] = 0.f; dQ[mt][nt][e] = 0.f; }

        #pragma unroll
        for (int ks = 0; ks < 8; ks++) {
            const int kp0 = ks * 8 + t;
            uint32_t Bh[4][2], Bl[4][2];
            #pragma unroll
            for (int nt = 0; nt < 4; nt++) {
                const int br = (wc + nt*8 + g) * 68;
                Bh[nt][0] = bh[br + kp0]; Bh[nt][1] = bh[br + kp0 + 4];
                Bl[nt][0] = bl[br + kp0]; Bl[nt][1] = bl[br + kp0 + 4];
            }
            #pragma unroll
            for (int mt = 0; mt < 2; mt++) {
                const int ar = (wr + mt*16 + g) * 68;
                const int ar8 = ar + 8*68;
                uint32_t Ah[4], Al[4];
                // q
                Ah[0] = qh[ar + kp0];  Ah[1] = qh[ar8 + kp0];
                Ah[2] = qh[ar + kp0+4]; Ah[3] = qh[ar8 + kp0+4];
                Al[0] = ql[ar + kp0];  Al[1] = ql[ar8 + kp0];
                Al[2] = ql[ar + kp0+4]; Al[3] = ql[ar8 + kp0+4];
                #pragma unroll
                for (int nt = 0; nt < 4; nt++) {
                    MMA16816(dQ[mt][nt], Ah, Bh[nt]);
                    MMA16816(dQ[mt][nt], Ah, Bl[nt]);
                    MMA16816(dQ[mt][nt], Al, Bh[nt]);
                }
                // v_r
                Ah[0] = rh[ar + kp0];  Ah[1] = rh[ar8 + kp0];
                Ah[2] = rh[ar + kp0+4]; Ah[3] = rh[ar8 + kp0+4];
                Al[0] = rl[ar + kp0];  Al[1] = rl[ar8 + kp0];
                Al[2] = rl[ar + kp0+4]; Al[3] = rl[ar8 + kp0+4];
                #pragma unroll
                for (int nt = 0; nt < 4; nt++) {
                    MMA16816(dR[mt][nt], Ah, Bh[nt]);
                    MMA16816(dR[mt][nt], Ah, Bl[nt]);
                    MMA16816(dR[mt][nt], Al, Bh[nt]);
                }
            }
        }

        // ---- epilogue: std + score + mask, write S and T
        #pragma unroll
        for (int mt = 0; mt < 2; mt++) {
            #pragma unroll
            for (int rg = 0; rg < 2; rg++) {
                const int li = wr + mt*16 + g + rg*8;       // local row
                const float mr = s_mr[li], varr = s_varr[li];
                const float sq = s_sq[li], qvr = s_qvr[li];
                const size_t orow = ((size_t)b*NT + i0 + li) * NT + j0;
                #pragma unroll
                for (int nt = 0; nt < 4; nt++) {
                    const int lj = wc + nt*8 + t*2;         // local col (pair)
                    const int2 mk = *(const int2*)(mask + orow + lj);
                    float so[2], to[2];
                    #pragma unroll
                    for (int c = 0; c < 2; c++) {
                        const float msj = s_ms[lj + c], vars = s_vars[lj + c];
                        const float accr = dR[mt][nt][rg*2 + c];
                        const float accq = dQ[mt][nt][rg*2 + c];
                        const float cross = (accr - 128.f * mr * msj) * (2.f / 128.f);
                        const float stdv = sqrtf(varr + vars + cross + EPSV);
                        float a = (qvr + accq - sq * (mr + msj)) / stdv * SCALEV;
                        if ((c == 0 ? mk.x : mk.y) != 0) a = -INFINITY;
                        so[c] = a; to[c] = stdv;
                    }
                    *(float2*)(g_S + orow + lj) = make_float2(so[0], so[1]);
                    *(float2*)(g_T + orow + lj) = make_float2(to[0], to[1]);
                }
            }
        }
    }
}

// ---------------- Kernel D: out = P@v_s + rsP*v_r - rPm, then LN (HMMA) -----
// planes: P hi/lo [i][kpair], v_s^T hi/lo [d][jpair]; stride 68 words
#define OUT_SMEM ((4*PLANE + 4*128) * 4)

__global__ void __launch_bounds__(512, 1) out_mma(const float* __restrict__ nw,
                                                  const float* __restrict__ nb)
{
    extern __shared__ __align__(16) uint32_t sm[];
    uint32_t* ph  = sm;
    uint32_t* pl  = ph + PLANE;
    uint32_t* bth = pl + PLANE;
    uint32_t* btl = bth + PLANE;
    float* s_rp  = (float*)(btl + PLANE);
    float* s_rpm = s_rp + 128;
    float* s_nw  = s_rpm + 128;
    float* s_nb  = s_nw + 128;

    const int tid = threadIdx.x;
    const int wid = tid >> 5, lane = tid & 31;
    const int g = lane >> 2, t = lane & 3;
    const int wr = (wid & 3) * 32;
    const int wc = (wid >> 2) * 32;
    const int i0 = blockIdx.x * 128, b = blockIdx.y;

    if (tid < 128) {
        s_rp[tid]  = g_rsP[b*NT + i0 + tid];
        s_rpm[tid] = g_rPm[b*NT + i0 + tid];
        s_nw[tid]  = nw[tid];
        s_nb[tid]  = nb[tid];
    }

    float dO[2][4][4];
    #pragma unroll
    for (int mt = 0; mt < 2; mt++)
        #pragma unroll
        for (int nt = 0; nt < 4; nt++)
            #pragma unroll
            for (int e = 0; e < 4; e++) dO[mt][nt][e] = 0.f;

    const float* Pbase  = g_S  + (size_t)b*NT*NT;
    const float* vsbase = g_vs + (size_t)b*NT*NC;

    for (int kt = 0; kt < 24; kt++) {
        const int k0 = kt * 128;
        __syncthreads();   // previous MMA consumed planes

        // ---- fill P planes: row i (local), kpair
        for (int idx = tid; idx < 128*64; idx += 512) {
            const int row = idx >> 6, kp = idx & 63;
            float2 v = ((const float2*)(Pbase + (size_t)(i0+row)*NT + k0))[kp];
            ph[row*68 + kp] = pack_hi(v.x, v.y);
            pl[row*68 + kp] = pack_lo(v.x, v.y);
        }
        // ---- fill v_s^T planes: bt[d][jpair] = (vs[j][d], vs[j+1][d])
        for (int idx = tid; idx < 128*64; idx += 512) {
            const int d = idx & 127, jp = idx >> 7;
            const int j = k0 + 2*jp;
            float v0 = vsbase[(size_t)j*NC + d];
            float v1 = vsbase[(size_t)(j+1)*NC + d];
            bth[d*68 + jp] = pack_hi(v0, v1);
            btl[d*68 + jp] = pack_lo(v0, v1);
        }
        __syncthreads();

        // ---- MMA: O += P @ vs^T  (A rows = i, B rows = d, K = 128 j's)
        #pragma unroll
        for (int ks = 0; ks < 8; ks++) {
            const int kp0 = ks * 8 + t;
            uint32_t Bh[4][2], Bl[4][2];
            #pragma unroll
            for (int nt = 0; nt < 4; nt++) {
                const int br = (wc + nt*8 + g) * 68;
                Bh[nt][0] = bth[br + kp0]; Bh[nt][1] = bth[br + kp0 + 4];
                Bl[nt][0] = btl[br + kp0]; Bl[nt][1] = btl[br + kp0 + 4];
            }
            #pragma unroll
            for (int mt = 0; mt < 2; mt++) {
                const int ar = (wr + mt*16 + g) * 68;
                const int ar8 = ar + 8*68;
                uint32_t Ah[4], Al[4];
                Ah[0] = ph[ar + kp0];   Ah[1] = ph[ar8 + kp0];
                Ah[2] = ph[ar + kp0+4]; Ah[3] = ph[ar8 + kp0+4];
                Al[0] = pl[ar + kp0];   Al[1] = pl[ar8 + kp0];
                Al[2] = pl[ar + kp0+4]; Al[3] = pl[ar8 + kp0+4];
                #pragma unroll
                for (int nt = 0; nt < 4; nt++) {
                    MMA16816(dO[mt][nt], Ah, Bh[nt]);
                    MMA16816(dO[mt][nt], Ah, Bl[nt]);
                    MMA16816(dO[mt][nt], Al, Bh[nt]);
                }
            }
        }
    }

    // ---- epilogue: + rp*v_r - rpm, LayerNorm affine, store g_on
    #pragma unroll
    for (int mt = 0; mt < 2; mt++) {
        #pragma unroll
        for (int rg = 0; rg < 2; rg++) {
            const int li = wr + mt*16 + g + rg*8;
            const float rp = s_rp[li], rpm = s_rpm[li];
            const size_t rbase = (size_t)(b*NT + i0 + li) * NC;
            #pragma unroll
            for (int nt = 0; nt < 4; nt++) {
                const int d0 = wc + nt*8 + t*2;
                const float2 vr2 = *(const float2*)(g_vr + rbase + d0);
                float v0 = dO[mt][nt][rg*2+0] + rp*vr2.x - rpm;
                float v1 = dO[mt][nt][rg*2+1] + rp*vr2.y - rpm;
                v0 = v0 * s_nw[d0]   + s_nb[d0];
                v1 = v1 * s_nw[d0+1] + s_nb[d0+1];
                *(float2*)(g_on + rbase + d0) = make_float2(v0, v1);
            }
        }
    }
}

// ---------------- Kernel A: v_r / v_s / q projections -----------------------
__global__ void qkv_gemm(const float* __restrict__ x,
                         const float* __restrict__ recv,
                         const float* __restrict__ send,
                         const float* __restrict__ res_r,
                         const float* __restrict__ res_s,
                         const float* __restrict__ ra,
                         const float* __restrict__ qw)
{
    const int mode = blockIdx.y;
    const int r0 = blockIdx.x * 64;
    __shared__ float As[32][65];
    __shared__ float Ws[32][129];
    const int t = threadIdx.x;
    const int ty = t >> 5, tx = t & 31;

    float acc[8][4];
    #pragma unroll
    for (int i = 0; i < 8; i++)
        #pragma unroll
        for (int j = 0; j < 4; j++) acc[i][j] = 0.f;

    const int nsrc = (mode == 2) ? 1 : 2;
    for (int src = 0; src < nsrc; src++) {
        const float* A; const float* W; int ws;
        if (mode == 0) { A = src ? recv : x; W = src ? ra : ra + NC;   ws = 3*NC; }
        else if (mode == 1) { A = src ? send : x; W = src ? ra : ra + 2*NC; ws = 3*NC; }
        else { A = x; W = qw; ws = NC; }

        for (int k0 = 0; k0 < NC; k0 += 32) {
            #pragma unroll
            for (int s = 0; s < 8; s++) {
                int idx = t + 256 * s;
                int m = idx >> 5, k = idx & 31;
                int r = r0 + m;
                int bb = r / NT, n = r % NT;
                As[k][m] = A[(size_t)n*NB*NC + bb*NC + k0 + k];
            }
            #pragma unroll
            for (int s = 0; s < 16; s++) {
                int idx = t + 256 * s;
                int c = idx >> 5, k = idx & 31;
                Ws[k][c] = W[(size_t)c*ws + k0 + k];
            }
            __syncthreads();
            #pragma unroll
            for (int kk = 0; kk < 32; kk++) {
                float a[8], w[4];
                #pragma unroll
                for (int i = 0; i < 8; i++) a[i] = As[kk][ty + 8*i];
                #pragma unroll
                for (int j = 0; j < 4; j++) w[j] = Ws[kk][tx + 32*j];
                #pragma unroll
                for (int i = 0; i < 8; i++)
                    #pragma unroll
                    for (int j = 0; j < 4; j++) acc[i][j] = fmaf(a[i], w[j], acc[i][j]);
            }
            __syncthreads();
        }
    }

    float* out = (mode == 0) ? g_vr : (mode == 1) ? g_vs : g_q;
    const float* res = (mode == 0) ? res_r : (mode == 1) ? res_s : nullptr;
    #pragma unroll
    for (int i = 0; i < 8; i++) {
        int r = r0 + ty + 8*i;
        int bb = r / NT, n = r % NT;
        #pragma unroll
        for (int j = 0; j < 4; j++) {
            int c = tx + 32*j;
            float v = acc[i][j];
            if (res) v += res[(size_t)n*NB*NC + bb*NC + c];
            out[(size_t)bb*NT*NC + (size_t)n*NC + c] = v;
        }
    }
}

// ---------------- Kernel A2: per-row stats ----------------------------------
__global__ void row_stats()
{
    const int r = blockIdx.x;
    const int c = threadIdx.x;           // 128 threads
    const size_t base = (size_t)r * NC + c;
    float vr = g_vr[base], vs = g_vs[base], q = g_q[base];
    __shared__ float sh[6][128];
    sh[0][c] = vr; sh[1][c] = vr*vr; sh[2][c] = vs;
    sh[3][c] = vs*vs; sh[4][c] = q; sh[5][c] = q*vr;
    __syncthreads();
    for (int off = 64; off > 0; off >>= 1) {
        if (c < off)
            #pragma unroll
            for (int i = 0; i < 6; i++) sh[i][c] += sh[i][c + off];
        __syncthreads();
    }
    if (c == 0) {
        float mr = sh[0][0] * (1.f/NC);
        float ms = sh[2][0] * (1.f/NC);
        g_mr[r] = mr;
        g_ms[r] = ms;
        g_varr[r] = sh[1][0] * (1.f/NC) - mr*mr;
        g_vars[r] = sh[3][0] * (1.f/NC) - ms*ms;
        g_sumq[r] = sh[4][0];
        g_qvr[r]  = sh[5][0];
    }
}

// ---------------- Kernel C: masked softmax + /std + row sums ----------------
__global__ void softmax_row()
{
    const int b = blockIdx.y, i = blockIdx.x;
    const int t = threadIdx.x;                // 256
    const size_t base = (size_t)b*NT*NT + (size_t)i*NT;
    __shared__ float red[256];

    float s[12];
    float m = -INFINITY;
    #pragma unroll
    for (int jj = 0; jj < 12; jj++) {
        s[jj] = g_S[base + t + 256*jj];
        m = fmaxf(m, s[jj]);
    }
    red[t] = m; __syncthreads();
    for (int off = 128; off > 0; off >>= 1) {
        if (t < off) red[t] = fmaxf(red[t], red[t + off]);
        __syncthreads();
    }
    m = red[0]; __syncthreads();

    if (m == -INFINITY) {
        #pragma unroll
        for (int jj = 0; jj < 12; jj++) g_S[base + t + 256*jj] = 0.f;
        if (t == 0) { g_rsP[b*NT+i] = 0.f; g_rPm[b*NT+i] = 0.f; }
        return;
    }

    float sum = 0.f;
    #pragma unroll
    for (int jj = 0; jj < 12; jj++) { s[jj] = __expf(s[jj] - m); sum += s[jj]; }
    red[t] = sum; __syncthreads();
    for (int off = 128; off > 0; off >>= 1) {
        if (t < off) red[t] += red[t + off];
        __syncthreads();
    }
    const float inv = 1.f / red[0]; __syncthreads();

    const float mr_i = g_mr[b*NT + i];
    float rp = 0.f, rpm = 0.f;
    #pragma unroll
    for (int jj = 0; jj < 12; jj++) {
        int j = t + 256*jj;
        float p = __fdividef(s[jj] * inv, g_T[base + j]);
        g_S[base + j] = p;
        rp  += p;
        rpm += p * (mr_i + g_ms[b*NT + j]);
    }
    red[t] = rp; __syncthreads();
    for (int off = 128; off > 0; off >>= 1) {
        if (t < off) red[t] += red[t + off];
        __syncthreads();
    }
    rp = red[0]; __syncthreads();
    red[t] = rpm; __syncthreads();
    for (int off = 128; off > 0; off >>= 1) {
        if (t < off) red[t] += red[t + off];
        __syncthreads();
    }
    if (t == 0) {
        g_rsP[b*NT+i] = rp;
        g_rPm[b*NT+i] = red[0];
    }
}

// ---------------- Kernel E: three output projections, transposed store ------
__global__ void proj_gemm(const float* __restrict__ pw, const float* __restrict__ pb,
                          const float* __restrict__ rw, const float* __restrict__ rb,
                          const float* __restrict__ sw, const float* __restrict__ sb,
                          float* __restrict__ out)
{
    const int mode = blockIdx.y;
    const int r0 = blockIdx.x * 64;
    const float* src = (mode == 0) ? g_on : (mode == 1) ? g_vr : g_vs;
    const float* W   = (mode == 0) ? pw   : (mode == 1) ? rw   : sw;
    const float* bia = (mode == 0) ? pb   : (mode == 1) ? rb   : sb;

    __shared__ float As[32][65];
    __shared__ float Ws[32][129];
    const int t = threadIdx.x;
    const int ty = t >> 5, tx = t & 31;

    float acc[8][4];
    #pragma unroll
    for (int i = 0; i < 8; i++)
        #pragma unroll
        for (int j = 0; j < 4; j++) acc[i][j] = 0.f;

    for (int k0 = 0; k0 < NC; k0 += 32) {
        #pragma unroll
        for (int s = 0; s < 8; s++) {
            int idx = t + 256*s;
            int m = idx >> 5, k = idx & 31;
            As[k][m] = src[(size_t)(r0+m)*NC + k0 + k];
        }
        #pragma unroll
        for (int s = 0; s < 16; s++) {
            int idx = t + 256*s;
            int c = idx >> 5, k = idx & 31;
            Ws[k][c] = W[(size_t)c*NC + k0 + k];
        }
        __syncthreads();
        #pragma unroll
        for (int kk = 0; kk < 32; kk++) {
            float a[8], w[4];
            #pragma unroll
            for (int i = 0; i < 8; i++) a[i] = As[kk][ty + 8*i];
            #pragma unroll
            for (int j = 0; j < 4; j++) w[j] = Ws[kk][tx + 32*j];
            #pragma unroll
            for (int i = 0; i < 8; i++)
                #pragma unroll
                for (int j = 0; j < 4; j++) acc[i][j] = fmaf(a[i], w[j], acc[i][j]);
        }
        __syncthreads();
    }

    const size_t obase = (size_t)mode * MTOT * NC;
    #pragma unroll
    for (int i = 0; i < 8; i++) {
        int r = r0 + ty + 8*i;
        int b = r / NT, n = r % NT;
        #pragma unroll
        for (int j = 0; j < 4; j++) {
            int c = tx + 32*j;
            out[obase + (size_t)n*NB*NC + b*NC + c] = acc[i][j] + bia[c];
        }
    }
}

// ---------------- launch ----------------------------------------------------
extern "C" void kernel_launch(void* const* d_in, const int* in_sizes, int n_in,
                              void* d_out, int out_size)
{
    const float* x    = (const float*)d_in[0];
    const int*   mask = (const int*)d_in[1];      // bool uploaded as int32
    const float* recv = (const float*)d_in[2];
    const float* send = (const float*)d_in[3];
    const float* resr = (const float*)d_in[4];
    const float* ress = (const float*)d_in[5];
    const float* ra   = (const float*)d_in[6];
    const float* qw   = (const float*)d_in[7];
    const float* pw   = (const float*)d_in[8];
    const float* pb   = (const float*)d_in[9];
    const float* rw   = (const float*)d_in[10];
    const float* rb   = (const float*)d_in[11];
    const float* sw   = (const float*)d_in[12];
    const float* sb   = (const float*)d_in[13];
    const float* nw   = (const float*)d_in[14];
    const float* nb   = (const float*)d_in[15];
    float* out = (float*)d_out;

    cudaFuncSetAttribute(score_mma, cudaFuncAttributeMaxDynamicSharedMemorySize, SC_SMEM);
    cudaFuncSetAttribute(out_mma,   cudaFuncAttributeMaxDynamicSharedMemorySize, OUT_SMEM);

    qkv_gemm<<<dim3(MTOT/64, 3), 256>>>(x, recv, send, resr, ress, ra, qw);
    row_stats<<<MTOT, 128>>>();
    score_mma<<<dim3(NT/128, NB, 6), 512, SC_SMEM>>>(mask);
    softmax_row<<<dim3(NT, NB), 256>>>();
    out_mma<<<dim3(NT/128, NB), 512, OUT_SMEM>>>(nw, nb);
    proj_gemm<<<dim3(MTOT/64, 3), 256>>>(pw, pb, rw, rb, sw, sb, out);
}

// round 8
// speedup vs baseline: 2.1900x; 1.1301x over previous
#include <cuda_runtime.h>
#include <cuda_bf16.h>
#include <math.h>
#include <stdint.h>

#define NT 3072
#define NB 4
#define NC 128
#define MTOT (NB*NT)
#define EPSV 1e-5f
#define SCALEV 0.08838834764831845f  /* 1/sqrt(128) */
#define NEGBIG -1e30f

// ---------------- scratch (device globals; no allocations allowed) ----------
__device__ float g_vr[(size_t)NB*NT*NC];
__device__ float g_vs[(size_t)NB*NT*NC];
__device__ float g_q [(size_t)NB*NT*NC];
__device__ float g_on[(size_t)NB*NT*NC];
__device__ float g_mr[MTOT], g_ms[MTOT], g_varr[MTOT], g_vars[MTOT];
__device__ float g_sumq[MTOT], g_qvr[MTOT];

// ---------------- helpers ----------------------------------------------------
__device__ __forceinline__ uint32_t smem_u32(const void* p) {
    uint32_t a;
    asm("{ .reg .u64 t; cvta.to.shared.u64 t, %1; cvt.u32.u64 %0, t; }"
        : "=r"(a) : "l"(p));
    return a;
}
__device__ __forceinline__ uint32_t pack_hi(float x, float y) {
    __nv_bfloat162 h;
    h.x = __float2bfloat16(x); h.y = __float2bfloat16(y);
    return *(uint32_t*)&h;
}
__device__ __forceinline__ uint32_t pack_lo(float x, float y) {
    __nv_bfloat162 h;
    h.x = __float2bfloat16(x - __bfloat162float(__float2bfloat16(x)));
    h.y = __float2bfloat16(y - __bfloat162float(__float2bfloat16(y)));
    return *(uint32_t*)&h;
}
#define MMA16816(d, a, b) \
    asm volatile("mma.sync.aligned.m16n8k16.row.col.f32.bf16.bf16.f32 " \
        "{%0,%1,%2,%3}, {%4,%5,%6,%7}, {%8,%9}, {%0,%1,%2,%3};" \
        : "+f"((d)[0]), "+f"((d)[1]), "+f"((d)[2]), "+f"((d)[3]) \
        : "r"((a)[0]), "r"((a)[1]), "r"((a)[2]), "r"((a)[3]), \
          "r"((b)[0]), "r"((b)[1]))
#define LDSMT(r0, r1, r2, r3, addr) \
    asm volatile("ldmatrix.sync.aligned.m8n8.x4.trans.shared.b16 {%0,%1,%2,%3}, [%4];" \
        : "=r"(r0), "=r"(r1), "=r"(r2), "=r"(r3) : "r"(addr))

// ======================= flash kernel =======================================
// i-tile 64 (4 warps x 16 rows), j-tile 64, 48 j-iterations.
// smem planes [rows][68] words: qh, ql, rh, rl (64 rows), bh, bl (64 rows)
#define PW 68
#define APLANE (64*PW)
#define FL_SMEM ((6*APLANE + 6*64 + 2*128) * 4)

__global__ void __launch_bounds__(128, 2) flash_mma(const int* __restrict__ mask,
                                                    const float* __restrict__ nw,
                                                    const float* __restrict__ nb)
{
    extern __shared__ __align__(16) uint32_t sm[];
    uint32_t* qh = sm;
    uint32_t* ql = qh + APLANE;
    uint32_t* rh = ql + APLANE;
    uint32_t* rl = rh + APLANE;
    uint32_t* bh = rl + APLANE;
    uint32_t* bl = bh + APLANE;
    float* s_mr   = (float*)(bl + APLANE);
    float* s_varr = s_mr + 64;
    float* s_sq   = s_varr + 64;
    float* s_qvr  = s_sq + 64;
    float* s_ms   = s_qvr + 64;
    float* s_vars = s_ms + 64;
    float* s_nw   = s_vars + 64;
    float* s_nb   = s_nw + 128;

    const uint32_t sb = smem_u32(sm);
    const uint32_t bh_addr = sb + 4u*APLANE*4u;   // byte addr of bh plane
    const uint32_t bl_addr = sb + 5u*APLANE*4u;

    const int tid = threadIdx.x;
    const int wid = tid >> 5, lane = tid & 31;
    const int g = lane >> 2, t = lane & 3;
    const int wr = wid * 16;
    const int i0 = blockIdx.x * 64, b = blockIdx.y;

    // ---- fill A planes (q, v_r hi/lo) + row stats + LN params
    {
        const float* qsrc = g_q  + ((size_t)b*NT + i0) * NC;
        const float* rsrc = g_vr + ((size_t)b*NT + i0) * NC;
        for (int idx = tid; idx < 64*64; idx += 128) {
            const int row = idx >> 6, kp = idx & 63;
            float2 v = ((const float2*)(qsrc + (size_t)row*NC))[kp];
            qh[row*PW + kp] = pack_hi(v.x, v.y);
            ql[row*PW + kp] = pack_lo(v.x, v.y);
            float2 w = ((const float2*)(rsrc + (size_t)row*NC))[kp];
            rh[row*PW + kp] = pack_hi(w.x, w.y);
            rl[row*PW + kp] = pack_lo(w.x, w.y);
        }
        if (tid < 64) {
            const int r = b*NT + i0 + tid;
            s_mr[tid] = g_mr[r]; s_varr[tid] = g_varr[r];
            s_sq[tid] = g_sumq[r]; s_qvr[tid] = g_qvr[r];
        }
        if (tid < 128) { s_nw[tid] = nw[tid]; s_nb[tid] = nb[tid]; }
    }
    __syncthreads();

    const float mr0 = s_mr[wr+g],   varr0 = s_varr[wr+g];
    const float sq0 = s_sq[wr+g],   qvr0  = s_qvr[wr+g];
    const float mr1 = s_mr[wr+g+8], varr1 = s_varr[wr+g+8];
    const float sq1 = s_sq[wr+g+8], qvr1  = s_qvr[wr+g+8];

    float m0 = NEGBIG, m1 = NEGBIG;
    float l0 = 0.f, rp0 = 0.f, rpm0 = 0.f;
    float l1 = 0.f, rp1 = 0.f, rpm1 = 0.f;
    float dO[16][4];
    #pragma unroll
    for (int n = 0; n < 16; n++)
        #pragma unroll
        for (int e = 0; e < 4; e++) dO[n][e] = 0.f;

    const size_t mrow0 = ((size_t)(b*NT + i0 + wr + g)) * NT;
    const size_t mrow1 = mrow0 + (size_t)8 * NT;

    for (int jt = 0; jt < NT/64; jt++) {
        const int j0 = jt * 64;
        __syncthreads();                  // previous tile's B reads done

        // ---- fill B planes (v_s hi/lo) + col stats
        {
            const float* bsrc = g_vs + ((size_t)b*NT + j0) * NC;
            for (int idx = tid; idx < 64*64; idx += 128) {
                const int row = idx >> 6, kp = idx & 63;
                float2 v = ((const float2*)(bsrc + (size_t)row*NC))[kp];
                bh[row*PW + kp] = pack_hi(v.x, v.y);
                bl[row*PW + kp] = pack_lo(v.x, v.y);
            }
            if (tid < 64) {
                const int c = b*NT + j0 + tid;
                s_ms[tid] = g_ms[c]; s_vars[tid] = g_vars[c];
            }
        }
        __syncthreads();

        // ---- score dual MMA (dR: vr.vs, dQ: q.vs)
        float dR[8][4], dQ[8][4];
        #pragma unroll
        for (int n = 0; n < 8; n++)
            #pragma unroll
            for (int e = 0; e < 4; e++) { dR[n][e] = 0.f; dQ[n][e] = 0.f; }

        #pragma unroll
        for (int ks = 0; ks < 8; ks++) {
            const int kp0 = ks*8 + t;
            const int ar = (wr + g)*PW, ar8 = ar + 8*PW;
            uint32_t QH[4] = { qh[ar+kp0], qh[ar8+kp0], qh[ar+kp0+4], qh[ar8+kp0+4] };
            uint32_t QL[4] = { ql[ar+kp0], ql[ar8+kp0], ql[ar+kp0+4], ql[ar8+kp0+4] };
            uint32_t RH[4] = { rh[ar+kp0], rh[ar8+kp0], rh[ar+kp0+4], rh[ar8+kp0+4] };
            uint32_t RL[4] = { rl[ar+kp0], rl[ar8+kp0], rl[ar+kp0+4], rl[ar8+kp0+4] };
            #pragma unroll
            for (int nt = 0; nt < 8; nt++) {
                const int br = (nt*8 + g)*PW;
                uint32_t BH[2] = { bh[br+kp0], bh[br+kp0+4] };
                uint32_t BL[2] = { bl[br+kp0], bl[br+kp0+4] };
                MMA16816(dQ[nt], QH, BH);
                MMA16816(dQ[nt], QH, BL);
                MMA16816(dQ[nt], QL, BH);
                MMA16816(dR[nt], RH, BH);
                MMA16816(dR[nt], RH, BL);
                MMA16816(dR[nt], RL, BH);
            }
        }

        // ---- scores + std + mask; track tile max (a -> dQ, stdv -> dR)
        float tmax0 = NEGBIG, tmax1 = NEGBIG;
        #pragma unroll
        for (int nt = 0; nt < 8; nt++) {
            const int2 mk0 = *(const int2*)(mask + mrow0 + j0 + nt*8 + t*2);
            const int2 mk1 = *(const int2*)(mask + mrow1 + j0 + nt*8 + t*2);
            #pragma unroll
            for (int c = 0; c < 2; c++) {
                const int j = nt*8 + t*2 + c;
                const float msj = s_ms[j], vars = s_vars[j];
                {
                    const float cross = (dR[nt][c] - 128.f*mr0*msj) * (2.f/128.f);
                    const float stdv = sqrtf(varr0 + vars + cross + EPSV);
                    float a = __fdividef(qvr0 + dQ[nt][c] - sq0*(mr0+msj), stdv) * SCALEV;
                    if ((c == 0 ? mk0.x : mk0.y) != 0) a = NEGBIG;
                    dQ[nt][c] = a; dR[nt][c] = stdv;
                    tmax0 = fmaxf(tmax0, a);
                }
                {
                    const float cross = (dR[nt][2+c] - 128.f*mr1*msj) * (2.f/128.f);
                    const float stdv = sqrtf(varr1 + vars + cross + EPSV);
                    float a = __fdividef(qvr1 + dQ[nt][2+c] - sq1*(mr1+msj), stdv) * SCALEV;
                    if ((c == 0 ? mk1.x : mk1.y) != 0) a = NEGBIG;
                    dQ[nt][2+c] = a; dR[nt][2+c] = stdv;
                    tmax1 = fmaxf(tmax1, a);
                }
            }
        }

        // ---- online max update (reduce over t-quad) + rescale
        tmax0 = fmaxf(tmax0, __shfl_xor_sync(0xffffffffu, tmax0, 1));
        tmax0 = fmaxf(tmax0, __shfl_xor_sync(0xffffffffu, tmax0, 2));
        tmax1 = fmaxf(tmax1, __shfl_xor_sync(0xffffffffu, tmax1, 1));
        tmax1 = fmaxf(tmax1, __shfl_xor_sync(0xffffffffu, tmax1, 2));
        const float mn0 = fmaxf(m0, tmax0), sc0 = __expf(m0 - mn0);
        const float mn1 = fmaxf(m1, tmax1), sc1 = __expf(m1 - mn1);
        m0 = mn0; m1 = mn1;
        l0 *= sc0; rp0 *= sc0; rpm0 *= sc0;
        l1 *= sc1; rp1 *= sc1; rpm1 *= sc1;
        #pragma unroll
        for (int n = 0; n < 16; n++) {
            dO[n][0] *= sc0; dO[n][1] *= sc0;
            dO[n][2] *= sc1; dO[n][3] *= sc1;
        }

        // ---- W = exp(a-m)/std; accumulate row scalars
        float W[8][4];
        #pragma unroll
        for (int nt = 0; nt < 8; nt++) {
            #pragma unroll
            for (int c = 0; c < 2; c++) {
                const int j = nt*8 + t*2 + c;
                const float msj = s_ms[j];
                const float u0 = __expf(dQ[nt][c] - m0);
                const float w0 = __fdividef(u0, dR[nt][c]);
                l0 += u0; rp0 += w0; rpm0 += w0 * (mr0 + msj);
                W[nt][c] = w0;
                const float u1 = __expf(dQ[nt][2+c] - m1);
                const float w1 = __fdividef(u1, dR[nt][2+c]);
                l1 += u1; rp1 += w1; rpm1 += w1 * (mr1 + msj);
                W[nt][2+c] = w1;
            }
        }

        // ---- O += W @ v_s  (A from registers; B via ldmatrix.trans on bh/bl)
        #pragma unroll
        for (int ks = 0; ks < 4; ks++) {
            uint32_t Ah[4] = {
                pack_hi(W[2*ks][0],   W[2*ks][1]),   pack_hi(W[2*ks][2],   W[2*ks][3]),
                pack_hi(W[2*ks+1][0], W[2*ks+1][1]), pack_hi(W[2*ks+1][2], W[2*ks+1][3]) };
            uint32_t Al[4] = {
                pack_lo(W[2*ks][0],   W[2*ks][1]),   pack_lo(W[2*ks][2],   W[2*ks][3]),
                pack_lo(W[2*ks+1][0], W[2*ks+1][1]), pack_lo(W[2*ks+1][2], W[2*ks+1][3]) };
            const uint32_t loff = ((uint32_t)(ks*16 + (lane & 15)) * PW
                                 + (uint32_t)((lane >> 4) * 4)) * 4u;
            #pragma unroll
            for (int dp = 0; dp < 8; dp++) {
                const uint32_t off = loff + (uint32_t)(dp*8) * 4u;
                uint32_t h0, h1, h2, h3, e0, e1, e2, e3;
                LDSMT(h0, h1, h2, h3, bh_addr + off);
                LDSMT(e0, e1, e2, e3, bl_addr + off);
                uint32_t BH0[2] = {h0, h1}, BH1[2] = {h2, h3};
                uint32_t BL0[2] = {e0, e1}, BL1[2] = {e2, e3};
                MMA16816(dO[2*dp],   Ah, BH0);
                MMA16816(dO[2*dp],   Ah, BL0);
                MMA16816(dO[2*dp],   Al, BH0);
                MMA16816(dO[2*dp+1], Ah, BH1);
                MMA16816(dO[2*dp+1], Ah, BL1);
                MMA16816(dO[2*dp+1], Al, BH1);
            }
        }
    }

    // ---- finalize: reduce scalars over t-quad, normalize, +rp*vr-rpm, LN
    l0   += __shfl_xor_sync(0xffffffffu, l0, 1);   l0   += __shfl_xor_sync(0xffffffffu, l0, 2);
    rp0  += __shfl_xor_sync(0xffffffffu, rp0, 1);  rp0  += __shfl_xor_sync(0xffffffffu, rp0, 2);
    rpm0 += __shfl_xor_sync(0xffffffffu, rpm0, 1); rpm0 += __shfl_xor_sync(0xffffffffu, rpm0, 2);
    l1   += __shfl_xor_sync(0xffffffffu, l1, 1);   l1   += __shfl_xor_sync(0xffffffffu, l1, 2);
    rp1  += __shfl_xor_sync(0xffffffffu, rp1, 1);  rp1  += __shfl_xor_sync(0xffffffffu, rp1, 2);
    rpm1 += __shfl_xor_sync(0xffffffffu, rpm1, 1); rpm1 += __shfl_xor_sync(0xffffffffu, rpm1, 2);
    const float inv0 = (l0 > 0.f) ? __fdividef(1.f, l0) : 0.f;
    const float inv1 = (l1 > 0.f) ? __fdividef(1.f, l1) : 0.f;

    const size_t rbase0 = ((size_t)(b*NT + i0 + wr + g)) * NC;
    const size_t rbase1 = rbase0 + (size_t)8 * NC;
    #pragma unroll
    for (int n = 0; n < 16; n++) {
        const int d0 = n*8 + t*2;
        const float2 vrA = *(const float2*)(g_vr + rbase0 + d0);
        float v0 = (dO[n][0] + rp0*vrA.x - rpm0) * inv0;
        float v1 = (dO[n][1] + rp0*vrA.y - rpm0) * inv0;
        v0 = v0 * s_nw[d0]   + s_nb[d0];
        v1 = v1 * s_nw[d0+1] + s_nb[d0+1];
        *(float2*)(g_on + rbase0 + d0) = make_float2(v0, v1);
        const float2 vrB = *(const float2*)(g_vr + rbase1 + d0);
        float w0 = (dO[n][2] + rp1*vrB.x - rpm1) * inv1;
        float w1 = (dO[n][3] + rp1*vrB.y - rpm1) * inv1;
        w0 = w0 * s_nw[d0]   + s_nb[d0];
        w1 = w1 * s_nw[d0+1] + s_nb[d0+1];
        *(float2*)(g_on + rbase1 + d0) = make_float2(w0, w1);
    }
}

// ---------------- Kernel A: v_r / v_s / q projections -----------------------
__global__ void qkv_gemm(const float* __restrict__ x,
                         const float* __restrict__ recv,
                         const float* __restrict__ send,
                         const float* __restrict__ res_r,
                         const float* __restrict__ res_s,
                         const float* __restrict__ ra,
                         const float* __restrict__ qw)
{
    const int mode = blockIdx.y;
    const int r0 = blockIdx.x * 64;
    __shared__ float As[32][65];
    __shared__ float Ws[32][129];
    const int t = threadIdx.x;
    const int ty = t >> 5, tx = t & 31;

    float acc[8][4];
    #pragma unroll
    for (int i = 0; i < 8; i++)
        #pragma unroll
        for (int j = 0; j < 4; j++) acc[i][j] = 0.f;

    const int nsrc = (mode == 2) ? 1 : 2;
    for (int src = 0; src < nsrc; src++) {
        const float* A; const float* W; int ws;
        if (mode == 0) { A = src ? recv : x; W = src ? ra : ra + NC;   ws = 3*NC; }
        else if (mode == 1) { A = src ? send : x; W = src ? ra : ra + 2*NC; ws = 3*NC; }
        else { A = x; W = qw; ws = NC; }

        for (int k0 = 0; k0 < NC; k0 += 32) {
            #pragma unroll
            for (int s = 0; s < 8; s++) {
                int idx = t + 256 * s;
                int m = idx >> 5, k = idx & 31;
                int r = r0 + m;
                int bb = r / NT, n = r % NT;
                As[k][m] = A[(size_t)n*NB*NC + bb*NC + k0 + k];
            }
            #pragma unroll
            for (int s = 0; s < 16; s++) {
                int idx = t + 256 * s;
                int c = idx >> 5, k = idx & 31;
                Ws[k][c] = W[(size_t)c*ws + k0 + k];
            }
            __syncthreads();
            #pragma unroll
            for (int kk = 0; kk < 32; kk++) {
                float a[8], w[4];
                #pragma unroll
                for (int i = 0; i < 8; i++) a[i] = As[kk][ty + 8*i];
                #pragma unroll
                for (int j = 0; j < 4; j++) w[j] = Ws[kk][tx + 32*j];
                #pragma unroll
                for (int i = 0; i < 8; i++)
                    #pragma unroll
                    for (int j = 0; j < 4; j++) acc[i][j] = fmaf(a[i], w[j], acc[i][j]);
            }
            __syncthreads();
        }
    }

    float* out = (mode == 0) ? g_vr : (mode == 1) ? g_vs : g_q;
    const float* res = (mode == 0) ? res_r : (mode == 1) ? res_s : nullptr;
    #pragma unroll
    for (int i = 0; i < 8; i++) {
        int r = r0 + ty + 8*i;
        int bb = r / NT, n = r % NT;
        #pragma unroll
        for (int j = 0; j < 4; j++) {
            int c = tx + 32*j;
            float v = acc[i][j];
            if (res) v += res[(size_t)n*NB*NC + bb*NC + c];
            out[(size_t)bb*NT*NC + (size_t)n*NC + c] = v;
        }
    }
}

// ---------------- Kernel A2: per-row stats ----------------------------------
__global__ void row_stats()
{
    const int r = blockIdx.x;
    const int c = threadIdx.x;           // 128 threads
    const size_t base = (size_t)r * NC + c;
    float vr = g_vr[base], vs = g_vs[base], q = g_q[base];
    __shared__ float sh[6][128];
    sh[0][c] = vr; sh[1][c] = vr*vr; sh[2][c] = vs;
    sh[3][c] = vs*vs; sh[4][c] = q; sh[5][c] = q*vr;
    __syncthreads();
    for (int off = 64; off > 0; off >>= 1) {
        if (c < off)
            #pragma unroll
            for (int i = 0; i < 6; i++) sh[i][c] += sh[i][c + off];
        __syncthreads();
    }
    if (c == 0) {
        float mr = sh[0][0] * (1.f/NC);
        float ms = sh[2][0] * (1.f/NC);
        g_mr[r] = mr;
        g_ms[r] = ms;
        g_varr[r] = sh[1][0] * (1.f/NC) - mr*mr;
        g_vars[r] = sh[3][0] * (1.f/NC) - ms*ms;
        g_sumq[r] = sh[4][0];
        g_qvr[r]  = sh[5][0];
    }
}

// ---------------- Kernel E: three output projections, transposed store ------
__global__ void proj_gemm(const float* __restrict__ pw, const float* __restrict__ pb,
                          const float* __restrict__ rw, const float* __restrict__ rb,
                          const float* __restrict__ sw, const float* __restrict__ sb,
                          float* __restrict__ out)
{
    const int mode = blockIdx.y;
    const int r0 = blockIdx.x * 64;
    const float* src = (mode == 0) ? g_on : (mode == 1) ? g_vr : g_vs;
    const float* W   = (mode == 0) ? pw   : (mode == 1) ? rw   : sw;
    const float* bia = (mode == 0) ? pb   : (mode == 1) ? rb   : sb;

    __shared__ float As[32][65];
    __shared__ float Ws[32][129];
    const int t = threadIdx.x;
    const int ty = t >> 5, tx = t & 31;

    float acc[8][4];
    #pragma unroll
    for (int i = 0; i < 8; i++)
        #pragma unroll
        for (int j = 0; j < 4; j++) acc[i][j] = 0.f;

    for (int k0 = 0; k0 < NC; k0 += 32) {
        #pragma unroll
        for (int s = 0; s < 8; s++) {
            int idx = t + 256*s;
            int m = idx >> 5, k = idx & 31;
            As[k][m] = src[(size_t)(r0+m)*NC + k0 + k];
        }
        #pragma unroll
        for (int s = 0; s < 16; s++) {
            int idx = t + 256*s;
            int c = idx >> 5, k = idx & 31;
            Ws[k][c] = W[(size_t)c*NC + k0 + k];
        }
        __syncthreads();
        #pragma unroll
        for (int kk = 0; kk < 32; kk++) {
            float a[8], w[4];
            #pragma unroll
            for (int i = 0; i < 8; i++) a[i] = As[kk][ty + 8*i];
            #pragma unroll
            for (int j = 0; j < 4; j++) w[j] = Ws[kk][tx + 32*j];
            #pragma unroll
            for (int i = 0; i < 8; i++)
                #pragma unroll
                for (int j = 0; j < 4; j++) acc[i][j] = fmaf(a[i], w[j], acc[i][j]);
        }
        __syncthreads();
    }

    const size_t obase = (size_t)mode * MTOT * NC;
    #pragma unroll
    for (int i = 0; i < 8; i++) {
        int r = r0 + ty + 8*i;
        int b = r / NT, n = r % NT;
        #pragma unroll
        for (int j = 0; j < 4; j++) {
            int c = tx + 32*j;
            out[obase + (size_t)n*NB*NC + b*NC + c] = acc[i][j] + bia[c];
        }
    }
}

// ---------------- launch ----------------------------------------------------
extern "C" void kernel_launch(void* const* d_in, const int* in_sizes, int n_in,
                              void* d_out, int out_size)
{
    const float* x    = (const float*)d_in[0];
    const int*   mask = (const int*)d_in[1];      // bool uploaded as int32
    const float* recv = (const float*)d_in[2];
    const float* send = (const float*)d_in[3];
    const float* resr = (const float*)d_in[4];
    const float* ress = (const float*)d_in[5];
    const float* ra   = (const float*)d_in[6];
    const float* qw   = (const float*)d_in[7];
    const float* pw   = (const float*)d_in[8];
    const float* pb   = (const float*)d_in[9];
    const float* rw   = (const float*)d_in[10];
    const float* rb   = (const float*)d_in[11];
    const float* sw   = (const float*)d_in[12];
    const float* sb   = (const float*)d_in[13];
    const float* nw   = (const float*)d_in[14];
    const float* nb   = (const float*)d_in[15];
    float* out = (float*)d_out;

    cudaFuncSetAttribute(flash_mma, cudaFuncAttributeMaxDynamicSharedMemorySize, FL_SMEM);

    qkv_gemm<<<dim3(MTOT/64, 3), 256>>>(x, recv, send, resr, ress, ra, qw);
    row_stats<<<MTOT, 128>>>();
    flash_mma<<<dim3(NT/64, NB), 128, FL_SMEM>>>(mask, nw, nb);
    proj_gemm<<<dim3(MTOT/64, 3), 256>>>(pw, pb, rw, rb, sw, sb, out);
}

// round 11
// speedup vs baseline: 2.7161x; 1.2402x over previous
#include <cuda_runtime.h>
#include <cuda_bf16.h>
#include <math.h>
#include <stdint.h>

#define NT 3072
#define NB 4
#define NC 128
#define MTOT (NB*NT)
#define EPSV 1e-5f
#define SCALEV 0.08838834764831845f  /* 1/sqrt(128) */
#define NEGBIG -1e30f

// ---------------- scratch (device globals; no allocations allowed) ----------
__device__ float g_vr[(size_t)NB*NT*NC];
__device__ float g_vs[(size_t)NB*NT*NC];
__device__ float g_q [(size_t)NB*NT*NC];
__device__ float g_on[(size_t)NB*NT*NC];
__device__ float g_mr[MTOT], g_ms[MTOT], g_varr[MTOT], g_vars[MTOT];
__device__ float g_sumq[MTOT], g_qvr[MTOT];

// ---------------- helpers ----------------------------------------------------
__device__ __forceinline__ uint32_t smem_u32(const void* p) {
    uint32_t a;
    asm("{ .reg .u64 t; cvta.to.shared.u64 t, %1; cvt.u32.u64 %0, t; }"
        : "=r"(a) : "l"(p));
    return a;
}
__device__ __forceinline__ uint32_t pack_hi(float x, float y) {
    __nv_bfloat162 h;
    h.x = __float2bfloat16(x); h.y = __float2bfloat16(y);
    return *(uint32_t*)&h;
}
__device__ __forceinline__ uint32_t pack_lo(float x, float y) {
    __nv_bfloat162 h;
    h.x = __float2bfloat16(x - __bfloat162float(__float2bfloat16(x)));
    h.y = __float2bfloat16(y - __bfloat162float(__float2bfloat16(y)));
    return *(uint32_t*)&h;
}
#define MMA16816(d, a, b) \
    asm volatile("mma.sync.aligned.m16n8k16.row.col.f32.bf16.bf16.f32 " \
        "{%0,%1,%2,%3}, {%4,%5,%6,%7}, {%8,%9}, {%0,%1,%2,%3};" \
        : "+f"((d)[0]), "+f"((d)[1]), "+f"((d)[2]), "+f"((d)[3]) \
        : "r"((a)[0]), "r"((a)[1]), "r"((a)[2]), "r"((a)[3]), \
          "r"((b)[0]), "r"((b)[1]))
#define LDSMT(r0, r1, r2, r3, addr) \
    asm volatile("ldmatrix.sync.aligned.m8n8.x4.trans.shared.b16 {%0,%1,%2,%3}, [%4];" \
        : "=r"(r0), "=r"(r1), "=r"(r2), "=r"(r3) : "r"(addr))

// ======================= flash kernel =======================================
// i-tile 64 (4 warps x 16 rows), j-tile 64, 48 j-iterations.
#define PW 68
#define APLANE (64*PW)
#define FL_SMEM ((6*APLANE + 6*64 + 2*128) * 4)

__global__ void __launch_bounds__(128, 2) flash_mma(const int* __restrict__ mask,
                                                    const float* __restrict__ nw,
                                                    const float* __restrict__ nb)
{
    extern __shared__ __align__(16) uint32_t sm[];
    uint32_t* qh = sm;
    uint32_t* ql = qh + APLANE;
    uint32_t* rh = ql + APLANE;
    uint32_t* rl = rh + APLANE;
    uint32_t* bh = rl + APLANE;
    uint32_t* bl = bh + APLANE;
    float* s_mr   = (float*)(bl + APLANE);
    float* s_varr = s_mr + 64;
    float* s_sq   = s_varr + 64;
    float* s_qvr  = s_sq + 64;
    float* s_ms   = s_qvr + 64;
    float* s_vars = s_ms + 64;
    float* s_nw   = s_vars + 64;
    float* s_nb   = s_nw + 128;

    const uint32_t sb = smem_u32(sm);
    const uint32_t bh_addr = sb + 4u*APLANE*4u;   // byte addr of bh plane
    const uint32_t bl_addr = sb + 5u*APLANE*4u;

    const int tid = threadIdx.x;
    const int wid = tid >> 5, lane = tid & 31;
    const int g = lane >> 2, t = lane & 3;
    const int wr = wid * 16;
    const int i0 = blockIdx.x * 64, b = blockIdx.y;

    // ---- fill A planes (q, v_r hi/lo) + row stats + LN params
    {
        const float* qsrc = g_q  + ((size_t)b*NT + i0) * NC;
        const float* rsrc = g_vr + ((size_t)b*NT + i0) * NC;
        for (int idx = tid; idx < 64*64; idx += 128) {
            const int row = idx >> 6, kp = idx & 63;
            float2 v = ((const float2*)(qsrc + (size_t)row*NC))[kp];
            qh[row*PW + kp] = pack_hi(v.x, v.y);
            ql[row*PW + kp] = pack_lo(v.x, v.y);
            float2 w = ((const float2*)(rsrc + (size_t)row*NC))[kp];
            rh[row*PW + kp] = pack_hi(w.x, w.y);
            rl[row*PW + kp] = pack_lo(w.x, w.y);
        }
        if (tid < 64) {
            const int r = b*NT + i0 + tid;
            s_mr[tid] = g_mr[r]; s_varr[tid] = g_varr[r];
            s_sq[tid] = g_sumq[r]; s_qvr[tid] = g_qvr[r];
        }
        if (tid < 128) { s_nw[tid] = nw[tid]; s_nb[tid] = nb[tid]; }
    }
    __syncthreads();

    const float mr0 = s_mr[wr+g],   varr0 = s_varr[wr+g];
    const float sq0 = s_sq[wr+g],   qvr0  = s_qvr[wr+g];
    const float mr1 = s_mr[wr+g+8], varr1 = s_varr[wr+g+8];
    const float sq1 = s_sq[wr+g+8], qvr1  = s_qvr[wr+g+8];

    float m0 = NEGBIG, m1 = NEGBIG;
    float l0 = 0.f, rp0 = 0.f, rpm0 = 0.f;
    float l1 = 0.f, rp1 = 0.f, rpm1 = 0.f;
    float dO[16][4];
    #pragma unroll
    for (int n = 0; n < 16; n++)
        #pragma unroll
        for (int e = 0; e < 4; e++) dO[n][e] = 0.f;

    const size_t mrow0 = ((size_t)(b*NT + i0 + wr + g)) * NT;
    const size_t mrow1 = mrow0 + (size_t)8 * NT;

    for (int jt = 0; jt < NT/64; jt++) {
        const int j0 = jt * 64;
        __syncthreads();                  // previous tile's B reads done

        // ---- fill B planes (v_s hi/lo) + col stats
        {
            const float* bsrc = g_vs + ((size_t)b*NT + j0) * NC;
            for (int idx = tid; idx < 64*64; idx += 128) {
                const int row = idx >> 6, kp = idx & 63;
                float2 v = ((const float2*)(bsrc + (size_t)row*NC))[kp];
                bh[row*PW + kp] = pack_hi(v.x, v.y);
                bl[row*PW + kp] = pack_lo(v.x, v.y);
            }
            if (tid < 64) {
                const int c = b*NT + j0 + tid;
                s_ms[tid] = g_ms[c]; s_vars[tid] = g_vars[c];
            }
        }
        __syncthreads();

        // ---- score dual MMA (dR: vr.vs, dQ: q.vs)
        float dR[8][4], dQ[8][4];
        #pragma unroll
        for (int n = 0; n < 8; n++)
            #pragma unroll
            for (int e = 0; e < 4; e++) { dR[n][e] = 0.f; dQ[n][e] = 0.f; }

        #pragma unroll
        for (int ks = 0; ks < 8; ks++) {
            const int kp0 = ks*8 + t;
            const int ar = (wr + g)*PW, ar8 = ar + 8*PW;
            uint32_t QH[4] = { qh[ar+kp0], qh[ar8+kp0], qh[ar+kp0+4], qh[ar8+kp0+4] };
            uint32_t QL[4] = { ql[ar+kp0], ql[ar8+kp0], ql[ar+kp0+4], ql[ar8+kp0+4] };
            uint32_t RH[4] = { rh[ar+kp0], rh[ar8+kp0], rh[ar+kp0+4], rh[ar8+kp0+4] };
            uint32_t RL[4] = { rl[ar+kp0], rl[ar8+kp0], rl[ar+kp0+4], rl[ar8+kp0+4] };
            #pragma unroll
            for (int nt = 0; nt < 8; nt++) {
                const int br = (nt*8 + g)*PW;
                uint32_t BH[2] = { bh[br+kp0], bh[br+kp0+4] };
                uint32_t BL[2] = { bl[br+kp0], bl[br+kp0+4] };
                MMA16816(dQ[nt], QH, BH);
                MMA16816(dQ[nt], QH, BL);
                MMA16816(dQ[nt], QL, BH);
                MMA16816(dR[nt], RH, BH);
                MMA16816(dR[nt], RH, BL);
                MMA16816(dR[nt], RL, BH);
            }
        }

        // ---- scores: rstd via rsqrt (a -> dQ, rstd -> dR); tile max
        float tmax0 = NEGBIG, tmax1 = NEGBIG;
        #pragma unroll
        for (int nt = 0; nt < 8; nt++) {
            const int2 mk0 = *(const int2*)(mask + mrow0 + j0 + nt*8 + t*2);
            const int2 mk1 = *(const int2*)(mask + mrow1 + j0 + nt*8 + t*2);
            #pragma unroll
            for (int c = 0; c < 2; c++) {
                const int j = nt*8 + t*2 + c;
                const float msj = s_ms[j], vars = s_vars[j];
                {
                    const float cross = (dR[nt][c] - 128.f*mr0*msj) * (2.f/128.f);
                    const float rstd = rsqrtf(varr0 + vars + cross + EPSV);
                    float a = (qvr0 + dQ[nt][c] - sq0*(mr0+msj)) * rstd * SCALEV;
                    if ((c == 0 ? mk0.x : mk0.y) != 0) a = NEGBIG;
                    dQ[nt][c] = a; dR[nt][c] = rstd;
                    tmax0 = fmaxf(tmax0, a);
                }
                {
                    const float cross = (dR[nt][2+c] - 128.f*mr1*msj) * (2.f/128.f);
                    const float rstd = rsqrtf(varr1 + vars + cross + EPSV);
                    float a = (qvr1 + dQ[nt][2+c] - sq1*(mr1+msj)) * rstd * SCALEV;
                    if ((c == 0 ? mk1.x : mk1.y) != 0) a = NEGBIG;
                    dQ[nt][2+c] = a; dR[nt][2+c] = rstd;
                    tmax1 = fmaxf(tmax1, a);
                }
            }
        }

        // ---- online max update (reduce over t-quad) + rescale
        tmax0 = fmaxf(tmax0, __shfl_xor_sync(0xffffffffu, tmax0, 1));
        tmax0 = fmaxf(tmax0, __shfl_xor_sync(0xffffffffu, tmax0, 2));
        tmax1 = fmaxf(tmax1, __shfl_xor_sync(0xffffffffu, tmax1, 1));
        tmax1 = fmaxf(tmax1, __shfl_xor_sync(0xffffffffu, tmax1, 2));
        const float mn0 = fmaxf(m0, tmax0), sc0 = __expf(m0 - mn0);
        const float mn1 = fmaxf(m1, tmax1), sc1 = __expf(m1 - mn1);
        m0 = mn0; m1 = mn1;
        l0 *= sc0; rp0 *= sc0; rpm0 *= sc0;
        l1 *= sc1; rp1 *= sc1; rpm1 *= sc1;
        #pragma unroll
        for (int n = 0; n < 16; n++) {
            dO[n][0] *= sc0; dO[n][1] *= sc0;
            dO[n][2] *= sc1; dO[n][3] *= sc1;
        }

        // ---- W = exp(a-m)*rstd; accumulate row scalars
        float W[8][4];
        #pragma unroll
        for (int nt = 0; nt < 8; nt++) {
            #pragma unroll
            for (int c = 0; c < 2; c++) {
                const int j = nt*8 + t*2 + c;
                const float msj = s_ms[j];
                const float u0 = __expf(dQ[nt][c] - m0);
                const float w0 = u0 * dR[nt][c];
                l0 += u0; rp0 += w0; rpm0 += w0 * (mr0 + msj);
                W[nt][c] = w0;
                const float u1 = __expf(dQ[nt][2+c] - m1);
                const float w1 = u1 * dR[nt][2+c];
                l1 += u1; rp1 += w1; rpm1 += w1 * (mr1 + msj);
                W[nt][2+c] = w1;
            }
        }

        // ---- O += W @ v_s  (A from registers; B via ldmatrix.trans on bh/bl)
        #pragma unroll
        for (int ks = 0; ks < 4; ks++) {
            uint32_t Ah[4] = {
                pack_hi(W[2*ks][0],   W[2*ks][1]),   pack_hi(W[2*ks][2],   W[2*ks][3]),
                pack_hi(W[2*ks+1][0], W[2*ks+1][1]), pack_hi(W[2*ks+1][2], W[2*ks+1][3]) };
            uint32_t Al[4] = {
                pack_lo(W[2*ks][0],   W[2*ks][1]),   pack_lo(W[2*ks][2],   W[2*ks][3]),
                pack_lo(W[2*ks+1][0], W[2*ks+1][1]), pack_lo(W[2*ks+1][2], W[2*ks+1][3]) };
            const uint32_t loff = ((uint32_t)(ks*16 + (lane & 15)) * PW
                                 + (uint32_t)((lane >> 4) * 4)) * 4u;
            #pragma unroll
            for (int dp = 0; dp < 8; dp++) {
                const uint32_t off = loff + (uint32_t)(dp*8) * 4u;
                uint32_t h0, h1, h2, h3, e0, e1, e2, e3;
                LDSMT(h0, h1, h2, h3, bh_addr + off);
                LDSMT(e0, e1, e2, e3, bl_addr + off);
                uint32_t BH0[2] = {h0, h1}, BH1[2] = {h2, h3};
                uint32_t BL0[2] = {e0, e1}, BL1[2] = {e2, e3};
                MMA16816(dO[2*dp],   Ah, BH0);
                MMA16816(dO[2*dp],   Ah, BL0);
                MMA16816(dO[2*dp],   Al, BH0);
                MMA16816(dO[2*dp+1], Ah, BH1);
                MMA16816(dO[2*dp+1], Ah, BL1);
                MMA16816(dO[2*dp+1], Al, BH1);
            }
        }
    }

    // ---- finalize: reduce scalars over t-quad, normalize, +rp*vr-rpm, LN
    l0   += __shfl_xor_sync(0xffffffffu, l0, 1);   l0   += __shfl_xor_sync(0xffffffffu, l0, 2);
    rp0  += __shfl_xor_sync(0xffffffffu, rp0, 1);  rp0  += __shfl_xor_sync(0xffffffffu, rp0, 2);
    rpm0 += __shfl_xor_sync(0xffffffffu, rpm0, 1); rpm0 += __shfl_xor_sync(0xffffffffu, rpm0, 2);
    l1   += __shfl_xor_sync(0xffffffffu, l1, 1);   l1   += __shfl_xor_sync(0xffffffffu, l1, 2);
    rp1  += __shfl_xor_sync(0xffffffffu, rp1, 1);  rp1  += __shfl_xor_sync(0xffffffffu, rp1, 2);
    rpm1 += __shfl_xor_sync(0xffffffffu, rpm1, 1); rpm1 += __shfl_xor_sync(0xffffffffu, rpm1, 2);
    const float inv0 = (l0 > 0.f) ? __fdividef(1.f, l0) : 0.f;
    const float inv1 = (l1 > 0.f) ? __fdividef(1.f, l1) : 0.f;

    const size_t rbase0 = ((size_t)(b*NT + i0 + wr + g)) * NC;
    const size_t rbase1 = rbase0 + (size_t)8 * NC;
    #pragma unroll
    for (int n = 0; n < 16; n++) {
        const int d0 = n*8 + t*2;
        const float2 vrA = *(const float2*)(g_vr + rbase0 + d0);
        float v0 = (dO[n][0] + rp0*vrA.x - rpm0) * inv0;
        float v1 = (dO[n][1] + rp0*vrA.y - rpm0) * inv0;
        v0 = v0 * s_nw[d0]   + s_nb[d0];
        v1 = v1 * s_nw[d0+1] + s_nb[d0+1];
        *(float2*)(g_on + rbase0 + d0) = make_float2(v0, v1);
        const float2 vrB = *(const float2*)(g_vr + rbase1 + d0);
        float w0 = (dO[n][2] + rp1*vrB.x - rpm1) * inv1;
        float w1 = (dO[n][3] + rp1*vrB.y - rpm1) * inv1;
        w0 = w0 * s_nw[d0]   + s_nb[d0];
        w1 = w1 * s_nw[d0+1] + s_nb[d0+1];
        *(float2*)(g_on + rbase1 + d0) = make_float2(w0, w1);
    }
}

// ---------------- Kernel A: v_r / v_s / q projections -----------------------
__global__ void qkv_gemm(const float* __restrict__ x,
                         const float* __restrict__ recv,
                         const float* __restrict__ send,
                         const float* __restrict__ res_r,
                         const float* __restrict__ res_s,
                         const float* __restrict__ ra,
                         const float* __restrict__ qw)
{
    const int mode = blockIdx.y;
    const int r0 = blockIdx.x * 64;
    __shared__ float As[32][65];
    __shared__ float Ws[32][129];
    const int t = threadIdx.x;
    const int ty = t >> 5, tx = t & 31;

    float acc[8][4];
    #pragma unroll
    for (int i = 0; i < 8; i++)
        #pragma unroll
        for (int j = 0; j < 4; j++) acc[i][j] = 0.f;

    const int nsrc = (mode == 2) ? 1 : 2;
    for (int src = 0; src < nsrc; src++) {
        const float* A; const float* W; int ws;
        if (mode == 0) { A = src ? recv : x; W = src ? ra : ra + NC;   ws = 3*NC; }
        else if (mode == 1) { A = src ? send : x; W = src ? ra : ra + 2*NC; ws = 3*NC; }
        else { A = x; W = qw; ws = NC; }

        for (int k0 = 0; k0 < NC; k0 += 32) {
            #pragma unroll
            for (int s = 0; s < 8; s++) {
                int idx = t + 256 * s;
                int m = idx >> 5, k = idx & 31;
                int r = r0 + m;
                int bb = r / NT, n = r % NT;
                As[k][m] = A[(size_t)n*NB*NC + bb*NC + k0 + k];
            }
            #pragma unroll
            for (int s = 0; s < 16; s++) {
                int idx = t + 256 * s;
                int c = idx >> 5, k = idx & 31;
                Ws[k][c] = W[(size_t)c*ws + k0 + k];
            }
            __syncthreads();
            #pragma unroll
            for (int kk = 0; kk < 32; kk++) {
                float a[8], w[4];
                #pragma unroll
                for (int i = 0; i < 8; i++) a[i] = As[kk][ty + 8*i];
                #pragma unroll
                for (int j = 0; j < 4; j++) w[j] = Ws[kk][tx + 32*j];
                #pragma unroll
                for (int i = 0; i < 8; i++)
                    #pragma unroll
                    for (int j = 0; j < 4; j++) acc[i][j] = fmaf(a[i], w[j], acc[i][j]);
            }
            __syncthreads();
        }
    }

    float* out = (mode == 0) ? g_vr : (mode == 1) ? g_vs : g_q;
    const float* res = (mode == 0) ? res_r : (mode == 1) ? res_s : nullptr;
    #pragma unroll
    for (int i = 0; i < 8; i++) {
        int r = r0 + ty + 8*i;
        int bb = r / NT, n = r % NT;
        #pragma unroll
        for (int j = 0; j < 4; j++) {
            int c = tx + 32*j;
            float v = acc[i][j];
            if (res) v += res[(size_t)n*NB*NC + bb*NC + c];
            out[(size_t)bb*NT*NC + (size_t)n*NC + c] = v;
        }
    }
}

// ---------------- Kernel A2: per-row stats ----------------------------------
__global__ void row_stats()
{
    const int r = blockIdx.x;
    const int c = threadIdx.x;           // 128 threads
    const size_t base = (size_t)r * NC + c;
    float vr = g_vr[base], vs = g_vs[base], q = g_q[base];
    __shared__ float sh[6][128];
    sh[0][c] = vr; sh[1][c] = vr*vr; sh[2][c] = vs;
    sh[3][c] = vs*vs; sh[4][c] = q; sh[5][c] = q*vr;
    __syncthreads();
    for (int off = 64; off > 0; off >>= 1) {
        if (c < off)
            #pragma unroll
            for (int i = 0; i < 6; i++) sh[i][c] += sh[i][c + off];
        __syncthreads();
    }
    if (c == 0) {
        float mr = sh[0][0] * (1.f/NC);
        float ms = sh[2][0] * (1.f/NC);
        g_mr[r] = mr;
        g_ms[r] = ms;
        g_varr[r] = sh[1][0] * (1.f/NC) - mr*mr;
        g_vars[r] = sh[3][0] * (1.f/NC) - ms*ms;
        g_sumq[r] = sh[4][0];
        g_qvr[r]  = sh[5][0];
    }
}

// ---------------- Kernel E: three output projections, transposed store ------
__global__ void proj_gemm(const float* __restrict__ pw, const float* __restrict__ pb,
                          const float* __restrict__ rw, const float* __restrict__ rb,
                          const float* __restrict__ sw, const float* __restrict__ sb,
                          float* __restrict__ out)
{
    const int mode = blockIdx.y;
    const int r0 = blockIdx.x * 64;
    const float* src = (mode == 0) ? g_on : (mode == 1) ? g_vr : g_vs;
    const float* W   = (mode == 0) ? pw   : (mode == 1) ? rw   : sw;
    const float* bia = (mode == 0) ? pb   : (mode == 1) ? rb   : sb;

    __shared__ float As[32][65];
    __shared__ float Ws[32][129];
    const int t = threadIdx.x;
    const int ty = t >> 5, tx = t & 31;

    float acc[8][4];
    #pragma unroll
    for (int i = 0; i < 8; i++)
        #pragma unroll
        for (int j = 0; j < 4; j++) acc[i][j] = 0.f;

    for (int k0 = 0; k0 < NC; k0 += 32) {
        #pragma unroll
        for (int s = 0; s < 8; s++) {
            int idx = t + 256*s;
            int m = idx >> 5, k = idx & 31;
            As[k][m] = src[(size_t)(r0+m)*NC + k0 + k];
        }
        #pragma unroll
        for (int s = 0; s < 16; s++) {
            int idx = t + 256*s;
            int c = idx >> 5, k = idx & 31;
            Ws[k][c] = W[(size_t)c*NC + k0 + k];
        }
        __syncthreads();
        #pragma unroll
        for (int kk = 0; kk < 32; kk++) {
            float a[8], w[4];
            #pragma unroll
            for (int i = 0; i < 8; i++) a[i] = As[kk][ty + 8*i];
            #pragma unroll
            for (int j = 0; j < 4; j++) w[j] = Ws[kk][tx + 32*j];
            #pragma unroll
            for (int i = 0; i < 8; i++)
                #pragma unroll
                for (int j = 0; j < 4; j++) acc[i][j] = fmaf(a[i], w[j], acc[i][j]);
        }
        __syncthreads();
    }

    const size_t obase = (size_t)mode * MTOT * NC;
    #pragma unroll
    for (int i = 0; i < 8; i++) {
        int r = r0 + ty + 8*i;
        int b = r / NT, n = r % NT;
        #pragma unroll
        for (int j = 0; j < 4; j++) {
            int c = tx + 32*j;
            out[obase + (size_t)n*NB*NC + b*NC + c] = acc[i][j] + bia[c];
        }
    }
}

// ---------------- launch ----------------------------------------------------
extern "C" void kernel_launch(void* const* d_in, const int* in_sizes, int n_in,
                              void* d_out, int out_size)
{
    const float* x    = (const float*)d_in[0];
    const int*   mask = (const int*)d_in[1];      // bool uploaded as int32
    const float* recv = (const float*)d_in[2];
    const float* send = (const float*)d_in[3];
    const float* resr = (const float*)d_in[4];
    const float* ress = (const float*)d_in[5];
    const float* ra   = (const float*)d_in[6];
    const float* qw   = (const float*)d_in[7];
    const float* pw   = (const float*)d_in[8];
    const float* pb   = (const float*)d_in[9];
    const float* rw   = (const float*)d_in[10];
    const float* rb   = (const float*)d_in[11];
    const float* sw   = (const float*)d_in[12];
    const float* sb   = (const float*)d_in[13];
    const float* nw   = (const float*)d_in[14];
    const float* nb   = (const float*)d_in[15];
    float* out = (float*)d_out;

    cudaFuncSetAttribute(flash_mma, cudaFuncAttributeMaxDynamicSharedMemorySize, FL_SMEM);

    qkv_gemm<<<dim3(MTOT/64, 3), 256>>>(x, recv, send, resr, ress, ra, qw);
    row_stats<<<MTOT, 128>>>();
    flash_mma<<<dim3(NT/64, NB), 128, FL_SMEM>>>(mask, nw, nb);
    proj_gemm<<<dim3(MTOT/64, 3), 256>>>(pw, pb, rw, rb, sw, sb, out);
}

// round 12
// speedup vs baseline: 3.2782x; 1.2070x over previous
#include <cuda_runtime.h>
#include <cuda_bf16.h>
#include <math.h>
#include <stdint.h>

#define NT 3072
#define NB 4
#define NC 128
#define MTOT (NB*NT)
#define EPSV 1e-5f
#define SCALEV 0.08838834764831845f  /* 1/sqrt(128) */
#define NEGBIG -1e30f

// ---------------- scratch (device globals; no allocations allowed) ----------
__device__ float g_vr[(size_t)NB*NT*NC];
__device__ float g_vs[(size_t)NB*NT*NC];
__device__ float g_q [(size_t)NB*NT*NC];
__device__ float g_on[(size_t)NB*NT*NC];
__device__ float g_mr[MTOT], g_ms[MTOT], g_varr[MTOT], g_vars[MTOT];
__device__ float g_sumq[MTOT], g_qvr[MTOT];

// ---------------- helpers ----------------------------------------------------
__device__ __forceinline__ uint32_t smem_u32(const void* p) {
    uint32_t a;
    asm("{ .reg .u64 t; cvta.to.shared.u64 t, %1; cvt.u32.u64 %0, t; }"
        : "=r"(a) : "l"(p));
    return a;
}
__device__ __forceinline__ uint32_t pack_hi(float x, float y) {
    __nv_bfloat162 h;
    h.x = __float2bfloat16(x); h.y = __float2bfloat16(y);
    return *(uint32_t*)&h;
}
__device__ __forceinline__ uint32_t pack_lo(float x, float y) {
    __nv_bfloat162 h;
    h.x = __float2bfloat16(x - __bfloat162float(__float2bfloat16(x)));
    h.y = __float2bfloat16(y - __bfloat162float(__float2bfloat16(y)));
    return *(uint32_t*)&h;
}
#define MMA16816(d, a, b) \
    asm volatile("mma.sync.aligned.m16n8k16.row.col.f32.bf16.bf16.f32 " \
        "{%0,%1,%2,%3}, {%4,%5,%6,%7}, {%8,%9}, {%0,%1,%2,%3};" \
        : "+f"((d)[0]), "+f"((d)[1]), "+f"((d)[2]), "+f"((d)[3]) \
        : "r"((a)[0]), "r"((a)[1]), "r"((a)[2]), "r"((a)[3]), \
          "r"((b)[0]), "r"((b)[1]))
#define LDSMT(r0, r1, r2, r3, addr) \
    asm volatile("ldmatrix.sync.aligned.m8n8.x4.trans.shared.b16 {%0,%1,%2,%3}, [%4];" \
        : "=r"(r0), "=r"(r1), "=r"(r2), "=r"(r3) : "r"(addr))

#define PW 68

// ======================= flash kernel =======================================
// i-tile 64 (4 warps x 16 rows), j-tile 64, 48 j-iterations.
#define APLANE (64*PW)
#define FL_SMEM ((6*APLANE + 6*64 + 2*128) * 4)

__global__ void __launch_bounds__(128, 2) flash_mma(const int* __restrict__ mask,
                                                    const float* __restrict__ nw,
                                                    const float* __restrict__ nb)
{
    extern __shared__ __align__(16) uint32_t sm[];
    uint32_t* qh = sm;
    uint32_t* ql = qh + APLANE;
    uint32_t* rh = ql + APLANE;
    uint32_t* rl = rh + APLANE;
    uint32_t* bh = rl + APLANE;
    uint32_t* bl = bh + APLANE;
    float* s_mr   = (float*)(bl + APLANE);
    float* s_varr = s_mr + 64;
    float* s_sq   = s_varr + 64;
    float* s_qvr  = s_sq + 64;
    float* s_ms   = s_qvr + 64;
    float* s_vars = s_ms + 64;
    float* s_nw   = s_vars + 64;
    float* s_nb   = s_nw + 128;

    const uint32_t sb = smem_u32(sm);
    const uint32_t bh_addr = sb + 4u*APLANE*4u;   // byte addr of bh plane

    const int tid = threadIdx.x;
    const int wid = tid >> 5, lane = tid & 31;
    const int g = lane >> 2, t = lane & 3;
    const int wr = wid * 16;
    const int i0 = blockIdx.x * 64, b = blockIdx.y;

    // ---- fill A planes (q, v_r hi/lo) + row stats + LN params
    {
        const float* qsrc = g_q  + ((size_t)b*NT + i0) * NC;
        const float* rsrc = g_vr + ((size_t)b*NT + i0) * NC;
        for (int idx = tid; idx < 64*64; idx += 128) {
            const int row = idx >> 6, kp = idx & 63;
            float2 v = ((const float2*)(qsrc + (size_t)row*NC))[kp];
            qh[row*PW + kp] = pack_hi(v.x, v.y);
            ql[row*PW + kp] = pack_lo(v.x, v.y);
            float2 w = ((const float2*)(rsrc + (size_t)row*NC))[kp];
            rh[row*PW + kp] = pack_hi(w.x, w.y);
            rl[row*PW + kp] = pack_lo(w.x, w.y);
        }
        if (tid < 64) {
            const int r = b*NT + i0 + tid;
            s_mr[tid] = g_mr[r]; s_varr[tid] = g_varr[r];
            s_sq[tid] = g_sumq[r]; s_qvr[tid] = g_qvr[r];
        }
        if (tid < 128) { s_nw[tid] = nw[tid]; s_nb[tid] = nb[tid]; }
    }
    __syncthreads();

    const float mr0 = s_mr[wr+g],   varr0 = s_varr[wr+g];
    const float sq0 = s_sq[wr+g],   qvr0  = s_qvr[wr+g];
    const float mr1 = s_mr[wr+g+8], varr1 = s_varr[wr+g+8];
    const float sq1 = s_sq[wr+g+8], qvr1  = s_qvr[wr+g+8];

    float m0 = NEGBIG, m1 = NEGBIG;
    float l0 = 0.f, rp0 = 0.f, rpm0 = 0.f;
    float l1 = 0.f, rp1 = 0.f, rpm1 = 0.f;
    float dO[16][4];
    #pragma unroll
    for (int n = 0; n < 16; n++)
        #pragma unroll
        for (int e = 0; e < 4; e++) dO[n][e] = 0.f;

    const size_t mrow0 = ((size_t)(b*NT + i0 + wr + g)) * NT;
    const size_t mrow1 = mrow0 + (size_t)8 * NT;

    for (int jt = 0; jt < NT/64; jt++) {
        const int j0 = jt * 64;
        __syncthreads();                  // previous tile's B reads done

        // ---- fill B planes (v_s hi/lo) + col stats
        {
            const float* bsrc = g_vs + ((size_t)b*NT + j0) * NC;
            for (int idx = tid; idx < 64*64; idx += 128) {
                const int row = idx >> 6, kp = idx & 63;
                float2 v = ((const float2*)(bsrc + (size_t)row*NC))[kp];
                bh[row*PW + kp] = pack_hi(v.x, v.y);
                bl[row*PW + kp] = pack_lo(v.x, v.y);
            }
            if (tid < 64) {
                const int c = b*NT + j0 + tid;
                s_ms[tid] = g_ms[c]; s_vars[tid] = g_vars[c];
            }
        }
        __syncthreads();

        // ---- score dual MMA (dR: vr.vs, dQ: q.vs)
        float dR[8][4], dQ[8][4];
        #pragma unroll
        for (int n = 0; n < 8; n++)
            #pragma unroll
            for (int e = 0; e < 4; e++) { dR[n][e] = 0.f; dQ[n][e] = 0.f; }

        #pragma unroll
        for (int ks = 0; ks < 8; ks++) {
            const int kp0 = ks*8 + t;
            const int ar = (wr + g)*PW, ar8 = ar + 8*PW;
            uint32_t QH[4] = { qh[ar+kp0], qh[ar8+kp0], qh[ar+kp0+4], qh[ar8+kp0+4] };
            uint32_t QL[4] = { ql[ar+kp0], ql[ar8+kp0], ql[ar+kp0+4], ql[ar8+kp0+4] };
            uint32_t RH[4] = { rh[ar+kp0], rh[ar8+kp0], rh[ar+kp0+4], rh[ar8+kp0+4] };
            uint32_t RL[4] = { rl[ar+kp0], rl[ar8+kp0], rl[ar+kp0+4], rl[ar8+kp0+4] };
            #pragma unroll
            for (int nt = 0; nt < 8; nt++) {
                const int br = (nt*8 + g)*PW;
                uint32_t BH[2] = { bh[br+kp0], bh[br+kp0+4] };
                uint32_t BL[2] = { bl[br+kp0], bl[br+kp0+4] };
                MMA16816(dQ[nt], QH, BH);
                MMA16816(dQ[nt], QH, BL);
                MMA16816(dQ[nt], QL, BH);
                MMA16816(dR[nt], RH, BH);
                MMA16816(dR[nt], RH, BL);
                MMA16816(dR[nt], RL, BH);
            }
        }

        // ---- scores: rstd via rsqrt (a -> dQ, rstd -> dR); tile max
        float tmax0 = NEGBIG, tmax1 = NEGBIG;
        #pragma unroll
        for (int nt = 0; nt < 8; nt++) {
            const int2 mk0 = *(const int2*)(mask + mrow0 + j0 + nt*8 + t*2);
            const int2 mk1 = *(const int2*)(mask + mrow1 + j0 + nt*8 + t*2);
            #pragma unroll
            for (int c = 0; c < 2; c++) {
                const int j = nt*8 + t*2 + c;
                const float msj = s_ms[j], vars = s_vars[j];
                {
                    const float cross = (dR[nt][c] - 128.f*mr0*msj) * (2.f/128.f);
                    const float rstd = rsqrtf(varr0 + vars + cross + EPSV);
                    float a = (qvr0 + dQ[nt][c] - sq0*(mr0+msj)) * rstd * SCALEV;
                    if ((c == 0 ? mk0.x : mk0.y) != 0) a = NEGBIG;
                    dQ[nt][c] = a; dR[nt][c] = rstd;
                    tmax0 = fmaxf(tmax0, a);
                }
                {
                    const float cross = (dR[nt][2+c] - 128.f*mr1*msj) * (2.f/128.f);
                    const float rstd = rsqrtf(varr1 + vars + cross + EPSV);
                    float a = (qvr1 + dQ[nt][2+c] - sq1*(mr1+msj)) * rstd * SCALEV;
                    if ((c == 0 ? mk1.x : mk1.y) != 0) a = NEGBIG;
                    dQ[nt][2+c] = a; dR[nt][2+c] = rstd;
                    tmax1 = fmaxf(tmax1, a);
                }
            }
        }

        // ---- online max update (reduce over t-quad) + rescale
        tmax0 = fmaxf(tmax0, __shfl_xor_sync(0xffffffffu, tmax0, 1));
        tmax0 = fmaxf(tmax0, __shfl_xor_sync(0xffffffffu, tmax0, 2));
        tmax1 = fmaxf(tmax1, __shfl_xor_sync(0xffffffffu, tmax1, 1));
        tmax1 = fmaxf(tmax1, __shfl_xor_sync(0xffffffffu, tmax1, 2));
        const float mn0 = fmaxf(m0, tmax0), sc0 = __expf(m0 - mn0);
        const float mn1 = fmaxf(m1, tmax1), sc1 = __expf(m1 - mn1);
        m0 = mn0; m1 = mn1;
        l0 *= sc0; rp0 *= sc0; rpm0 *= sc0;
        l1 *= sc1; rp1 *= sc1; rpm1 *= sc1;
        #pragma unroll
        for (int n = 0; n < 16; n++) {
            dO[n][0] *= sc0; dO[n][1] *= sc0;
            dO[n][2] *= sc1; dO[n][3] *= sc1;
        }

        // ---- W = exp(a-m)*rstd; accumulate row scalars
        float W[8][4];
        #pragma unroll
        for (int nt = 0; nt < 8; nt++) {
            #pragma unroll
            for (int c = 0; c < 2; c++) {
                const int j = nt*8 + t*2 + c;
                const float msj = s_ms[j];
                const float u0 = __expf(dQ[nt][c] - m0);
                const float w0 = u0 * dR[nt][c];
                l0 += u0; rp0 += w0; rpm0 += w0 * (mr0 + msj);
                W[nt][c] = w0;
                const float u1 = __expf(dQ[nt][2+c] - m1);
                const float w1 = u1 * dR[nt][2+c];
                l1 += u1; rp1 += w1; rpm1 += w1 * (mr1 + msj);
                W[nt][2+c] = w1;
            }
        }

        // ---- O += W @ v_s  (hi*hi only: P@v_s term is ~2.5% of output energy)
        #pragma unroll
        for (int ks = 0; ks < 4; ks++) {
            uint32_t Ah[4] = {
                pack_hi(W[2*ks][0],   W[2*ks][1]),   pack_hi(W[2*ks][2],   W[2*ks][3]),
                pack_hi(W[2*ks+1][0], W[2*ks+1][1]), pack_hi(W[2*ks+1][2], W[2*ks+1][3]) };
            const uint32_t loff = ((uint32_t)(ks*16 + (lane & 15)) * PW
                                 + (uint32_t)((lane >> 4) * 4)) * 4u;
            #pragma unroll
            for (int dp = 0; dp < 8; dp++) {
                const uint32_t off = loff + (uint32_t)(dp*8) * 4u;
                uint32_t h0, h1, h2, h3;
                LDSMT(h0, h1, h2, h3, bh_addr + off);
                uint32_t BH0[2] = {h0, h1}, BH1[2] = {h2, h3};
                MMA16816(dO[2*dp],   Ah, BH0);
                MMA16816(dO[2*dp+1], Ah, BH1);
            }
        }
    }

    // ---- finalize: reduce scalars over t-quad, normalize, +rp*vr-rpm, LN
    l0   += __shfl_xor_sync(0xffffffffu, l0, 1);   l0   += __shfl_xor_sync(0xffffffffu, l0, 2);
    rp0  += __shfl_xor_sync(0xffffffffu, rp0, 1);  rp0  += __shfl_xor_sync(0xffffffffu, rp0, 2);
    rpm0 += __shfl_xor_sync(0xffffffffu, rpm0, 1); rpm0 += __shfl_xor_sync(0xffffffffu, rpm0, 2);
    l1   += __shfl_xor_sync(0xffffffffu, l1, 1);   l1   += __shfl_xor_sync(0xffffffffu, l1, 2);
    rp1  += __shfl_xor_sync(0xffffffffu, rp1, 1);  rp1  += __shfl_xor_sync(0xffffffffu, rp1, 2);
    rpm1 += __shfl_xor_sync(0xffffffffu, rpm1, 1); rpm1 += __shfl_xor_sync(0xffffffffu, rpm1, 2);
    const float inv0 = (l0 > 0.f) ? __fdividef(1.f, l0) : 0.f;
    const float inv1 = (l1 > 0.f) ? __fdividef(1.f, l1) : 0.f;

    const size_t rbase0 = ((size_t)(b*NT + i0 + wr + g)) * NC;
    const size_t rbase1 = rbase0 + (size_t)8 * NC;
    #pragma unroll
    for (int n = 0; n < 16; n++) {
        const int d0 = n*8 + t*2;
        const float2 vrA = *(const float2*)(g_vr + rbase0 + d0);
        float v0 = (dO[n][0] + rp0*vrA.x - rpm0) * inv0;
        float v1 = (dO[n][1] + rp0*vrA.y - rpm0) * inv0;
        v0 = v0 * s_nw[d0]   + s_nb[d0];
        v1 = v1 * s_nw[d0+1] + s_nb[d0+1];
        *(float2*)(g_on + rbase0 + d0) = make_float2(v0, v1);
        const float2 vrB = *(const float2*)(g_vr + rbase1 + d0);
        float w0 = (dO[n][2] + rp1*vrB.x - rpm1) * inv1;
        float w1 = (dO[n][3] + rp1*vrB.y - rpm1) * inv1;
        w0 = w0 * s_nw[d0]   + s_nb[d0];
        w1 = w1 * s_nw[d0+1] + s_nb[d0+1];
        *(float2*)(g_on + rbase1 + d0) = make_float2(w0, w1);
    }
}

// ======================= qkv projections via HMMA ===========================
// 128-row x 128-col tile, K accumulated over 1-2 sources of 128.
#define QPLANE (128*PW)
#define QK_SMEM (4*QPLANE*4)

__global__ void __launch_bounds__(512, 1) qkv_mma(const float* __restrict__ x,
                                                  const float* __restrict__ recv,
                                                  const float* __restrict__ send,
                                                  const float* __restrict__ res_r,
                                                  const float* __restrict__ res_s,
                                                  const float* __restrict__ ra,
                                                  const float* __restrict__ qw)
{
    extern __shared__ __align__(16) uint32_t sm[];
    uint32_t* ah_ = sm;
    uint32_t* al_ = ah_ + QPLANE;
    uint32_t* wh_ = al_ + QPLANE;
    uint32_t* wl_ = wh_ + QPLANE;

    const int tid = threadIdx.x;
    const int wid = tid >> 5, lane = tid & 31;
    const int g = lane >> 2, t = lane & 3;
    const int wr = (wid & 3) * 32, wc = (wid >> 2) * 32;
    const int mode = blockIdx.y;
    const int r0 = blockIdx.x * 128;

    float acc[2][4][4];
    #pragma unroll
    for (int mt = 0; mt < 2; mt++)
        #pragma unroll
        for (int nt = 0; nt < 4; nt++)
            #pragma unroll
            for (int e = 0; e < 4; e++) acc[mt][nt][e] = 0.f;

    const int nsrc = (mode == 2) ? 1 : 2;
    for (int src = 0; src < nsrc; src++) {
        const float* A; const float* W; int ws;
        if (mode == 0)      { A = src ? recv : x; W = src ? ra : ra + NC;   ws = 3*NC; }
        else if (mode == 1) { A = src ? send : x; W = src ? ra : ra + 2*NC; ws = 3*NC; }
        else                { A = x; W = qw; ws = NC; }

        __syncthreads();     // prior MMA reads done
        for (int idx = tid; idx < 128*64; idx += 512) {
            const int row = idx >> 6, kp = idx & 63;
            const int r = r0 + row, bb = r / NT, n = r % NT;
            float2 v = ((const float2*)(A + (size_t)n*NB*NC + (size_t)bb*NC))[kp];
            ah_[row*PW + kp] = pack_hi(v.x, v.y);
            al_[row*PW + kp] = pack_lo(v.x, v.y);
            float2 w = ((const float2*)(W + (size_t)row*ws))[kp];
            wh_[row*PW + kp] = pack_hi(w.x, w.y);
            wl_[row*PW + kp] = pack_lo(w.x, w.y);
        }
        __syncthreads();

        #pragma unroll
        for (int ks = 0; ks < 8; ks++) {
            const int kp0 = ks*8 + t;
            uint32_t Bh[4][2], Bl[4][2];
            #pragma unroll
            for (int nt = 0; nt < 4; nt++) {
                const int br = (wc + nt*8 + g)*PW;
                Bh[nt][0] = wh_[br+kp0]; Bh[nt][1] = wh_[br+kp0+4];
                Bl[nt][0] = wl_[br+kp0]; Bl[nt][1] = wl_[br+kp0+4];
            }
            #pragma unroll
            for (int mt = 0; mt < 2; mt++) {
                const int ar = (wr + mt*16 + g)*PW, ar8 = ar + 8*PW;
                uint32_t Ah[4] = { ah_[ar+kp0], ah_[ar8+kp0], ah_[ar+kp0+4], ah_[ar8+kp0+4] };
                uint32_t Al[4] = { al_[ar+kp0], al_[ar8+kp0], al_[ar+kp0+4], al_[ar8+kp0+4] };
                #pragma unroll
                for (int nt = 0; nt < 4; nt++) {
                    MMA16816(acc[mt][nt], Ah, Bh[nt]);
                    MMA16816(acc[mt][nt], Ah, Bl[nt]);
                    MMA16816(acc[mt][nt], Al, Bh[nt]);
                }
            }
        }
    }

    float* out = (mode == 0) ? g_vr : (mode == 1) ? g_vs : g_q;
    const float* res = (mode == 0) ? res_r : (mode == 1) ? res_s : nullptr;
    #pragma unroll
    for (int mt = 0; mt < 2; mt++) {
        #pragma unroll
        for (int rg = 0; rg < 2; rg++) {
            const int li = wr + mt*16 + g + rg*8;
            const int r = r0 + li, bb = r / NT, n = r % NT;
            #pragma unroll
            for (int nt = 0; nt < 4; nt++) {
                const int c = wc + nt*8 + t*2;
                float v0 = acc[mt][nt][rg*2+0];
                float v1 = acc[mt][nt][rg*2+1];
                if (res) {
                    float2 rr = *(const float2*)(res + (size_t)n*NB*NC + (size_t)bb*NC + c);
                    v0 += rr.x; v1 += rr.y;
                }
                *(float2*)(out + ((size_t)bb*NT + n)*NC + c) = make_float2(v0, v1);
            }
        }
    }
}

// ======================= output projections via HMMA ========================
__global__ void __launch_bounds__(512, 1) proj_mma(const float* __restrict__ pw,
                                                   const float* __restrict__ pb,
                                                   const float* __restrict__ rw,
                                                   const float* __restrict__ rb,
                                                   const float* __restrict__ sw,
                                                   const float* __restrict__ sb,
                                                   float* __restrict__ out)
{
    extern __shared__ __align__(16) uint32_t sm[];
    uint32_t* ah_ = sm;
    uint32_t* al_ = ah_ + QPLANE;
    uint32_t* wh_ = al_ + QPLANE;
    uint32_t* wl_ = wh_ + QPLANE;

    const int tid = threadIdx.x;
    const int wid = tid >> 5, lane = tid & 31;
    const int g = lane >> 2, t = lane & 3;
    const int wr = (wid & 3) * 32, wc = (wid >> 2) * 32;
    const int mode = blockIdx.y;
    const int r0 = blockIdx.x * 128;

    const float* src = (mode == 0) ? g_on : (mode == 1) ? g_vr : g_vs;
    const float* W   = (mode == 0) ? pw   : (mode == 1) ? rw   : sw;
    const float* bia = (mode == 0) ? pb   : (mode == 1) ? rb   : sb;

    for (int idx = tid; idx < 128*64; idx += 512) {
        const int row = idx >> 6, kp = idx & 63;
        float2 v = ((const float2*)(src + (size_t)(r0+row)*NC))[kp];
        ah_[row*PW + kp] = pack_hi(v.x, v.y);
        al_[row*PW + kp] = pack_lo(v.x, v.y);
        float2 w = ((const float2*)(W + (size_t)row*NC))[kp];
        wh_[row*PW + kp] = pack_hi(w.x, w.y);
        wl_[row*PW + kp] = pack_lo(w.x, w.y);
    }
    __syncthreads();

    float acc[2][4][4];
    #pragma unroll
    for (int mt = 0; mt < 2; mt++)
        #pragma unroll
        for (int nt = 0; nt < 4; nt++)
            #pragma unroll
            for (int e = 0; e < 4; e++) acc[mt][nt][e] = 0.f;

    #pragma unroll
    for (int ks = 0; ks < 8; ks++) {
        const int kp0 = ks*8 + t;
        uint32_t Bh[4][2], Bl[4][2];
        #pragma unroll
        for (int nt = 0; nt < 4; nt++) {
            const int br = (wc + nt*8 + g)*PW;
            Bh[nt][0] = wh_[br+kp0]; Bh[nt][1] = wh_[br+kp0+4];
            Bl[nt][0] = wl_[br+kp0]; Bl[nt][1] = wl_[br+kp0+4];
        }
        #pragma unroll
        for (int mt = 0; mt < 2; mt++) {
            const int ar = (wr + mt*16 + g)*PW, ar8 = ar + 8*PW;
            uint32_t Ah[4] = { ah_[ar+kp0], ah_[ar8+kp0], ah_[ar+kp0+4], ah_[ar8+kp0+4] };
            uint32_t Al[4] = { al_[ar+kp0], al_[ar8+kp0], al_[ar+kp0+4], al_[ar8+kp0+4] };
            #pragma unroll
            for (int nt = 0; nt < 4; nt++) {
                MMA16816(acc[mt][nt], Ah, Bh[nt]);
                MMA16816(acc[mt][nt], Ah, Bl[nt]);
                MMA16816(acc[mt][nt], Al, Bh[nt]);
            }
        }
    }

    const size_t obase = (size_t)mode * MTOT * NC;
    #pragma unroll
    for (int mt = 0; mt < 2; mt++) {
        #pragma unroll
        for (int rg = 0; rg < 2; rg++) {
            const int li = wr + mt*16 + g + rg*8;
            const int r = r0 + li, bb = r / NT, n = r % NT;
            #pragma unroll
            for (int nt = 0; nt < 4; nt++) {
                const int c = wc + nt*8 + t*2;
                const float2 bb2 = *(const float2*)(bia + c);
                float v0 = acc[mt][nt][rg*2+0] + bb2.x;
                float v1 = acc[mt][nt][rg*2+1] + bb2.y;
                *(float2*)(out + obase + (size_t)n*NB*NC + (size_t)bb*NC + c) = make_float2(v0, v1);
            }
        }
    }
}

// ---------------- Kernel A2: per-row stats ----------------------------------
__global__ void row_stats()
{
    const int r = blockIdx.x;
    const int c = threadIdx.x;           // 128 threads
    const size_t base = (size_t)r * NC + c;
    float vr = g_vr[base], vs = g_vs[base], q = g_q[base];
    __shared__ float sh[6][128];
    sh[0][c] = vr; sh[1][c] = vr*vr; sh[2][c] = vs;
    sh[3][c] = vs*vs; sh[4][c] = q; sh[5][c] = q*vr;
    __syncthreads();
    for (int off = 64; off > 0; off >>= 1) {
        if (c < off)
            #pragma unroll
            for (int i = 0; i < 6; i++) sh[i][c] += sh[i][c + off];
        __syncthreads();
    }
    if (c == 0) {
        float mr = sh[0][0] * (1.f/NC);
        float ms = sh[2][0] * (1.f/NC);
        g_mr[r] = mr;
        g_ms[r] = ms;
        g_varr[r] = sh[1][0] * (1.f/NC) - mr*mr;
        g_vars[r] = sh[3][0] * (1.f/NC) - ms*ms;
        g_sumq[r] = sh[4][0];
        g_qvr[r]  = sh[5][0];
    }
}

// ---------------- launch ----------------------------------------------------
extern "C" void kernel_launch(void* const* d_in, const int* in_sizes, int n_in,
                              void* d_out, int out_size)
{
    const float* x    = (const float*)d_in[0];
    const int*   mask = (const int*)d_in[1];      // bool uploaded as int32
    const float* recv = (const float*)d_in[2];
    const float* send = (const float*)d_in[3];
    const float* resr = (const float*)d_in[4];
    const float* ress = (const float*)d_in[5];
    const float* ra   = (const float*)d_in[6];
    const float* qw   = (const float*)d_in[7];
    const float* pw   = (const float*)d_in[8];
    const float* pb   = (const float*)d_in[9];
    const float* rw   = (const float*)d_in[10];
    const float* rb   = (const float*)d_in[11];
    const float* sw   = (const float*)d_in[12];
    const float* sb   = (const float*)d_in[13];
    const float* nw   = (const float*)d_in[14];
    const float* nb   = (const float*)d_in[15];
    float* out = (float*)d_out;

    cudaFuncSetAttribute(flash_mma, cudaFuncAttributeMaxDynamicSharedMemorySize, FL_SMEM);
    cudaFuncSetAttribute(qkv_mma,   cudaFuncAttributeMaxDynamicSharedMemorySize, QK_SMEM);
    cudaFuncSetAttribute(proj_mma,  cudaFuncAttributeMaxDynamicSharedMemorySize, QK_SMEM);

    qkv_mma<<<dim3(MTOT/128, 3), 512, QK_SMEM>>>(x, recv, send, resr, ress, ra, qw);
    row_stats<<<MTOT, 128>>>();
    flash_mma<<<dim3(NT/64, NB), 128, FL_SMEM>>>(mask, nw, nb);
    proj_mma<<<dim3(MTOT/128, 3), 512, QK_SMEM>>>(pw, pb, rw, rb, sw, sb, out);
}

// round 13
// speedup vs baseline: 3.4776x; 1.0608x over previous
#include <cuda_runtime.h>
#include <cuda_bf16.h>
#include <math.h>
#include <stdint.h>

#define NT 3072
#define NB 4
#define NC 128
#define MTOT (NB*NT)
#define EPSV 1e-5f
#define SCALEV 0.08838834764831845f  /* 1/sqrt(128) */
#define NEGBIG -1e30f

// ---------------- scratch (device globals; no allocations allowed) ----------
__device__ float g_vr[(size_t)NB*NT*NC];
__device__ float g_vs[(size_t)NB*NT*NC];
__device__ float g_q [(size_t)NB*NT*NC];
__device__ float g_on[(size_t)NB*NT*NC];
__device__ float g_mr[MTOT], g_ms[MTOT], g_varr[MTOT], g_vars[MTOT];
__device__ float g_sumq[MTOT], g_qvr[MTOT];

// ---------------- helpers ----------------------------------------------------
__device__ __forceinline__ uint32_t smem_u32(const void* p) {
    uint32_t a;
    asm("{ .reg .u64 t; cvta.to.shared.u64 t, %1; cvt.u32.u64 %0, t; }"
        : "=r"(a) : "l"(p));
    return a;
}
__device__ __forceinline__ uint32_t pack_hi(float x, float y) {
    __nv_bfloat162 h;
    h.x = __float2bfloat16(x); h.y = __float2bfloat16(y);
    return *(uint32_t*)&h;
}
__device__ __forceinline__ uint32_t pack_lo(float x, float y) {
    __nv_bfloat162 h;
    h.x = __float2bfloat16(x - __bfloat162float(__float2bfloat16(x)));
    h.y = __float2bfloat16(y - __bfloat162float(__float2bfloat16(y)));
    return *(uint32_t*)&h;
}
#define MMA16816(d, a, b) \
    asm volatile("mma.sync.aligned.m16n8k16.row.col.f32.bf16.bf16.f32 " \
        "{%0,%1,%2,%3}, {%4,%5,%6,%7}, {%8,%9}, {%0,%1,%2,%3};" \
        : "+f"((d)[0]), "+f"((d)[1]), "+f"((d)[2]), "+f"((d)[3]) \
        : "r"((a)[0]), "r"((a)[1]), "r"((a)[2]), "r"((a)[3]), \
          "r"((b)[0]), "r"((b)[1]))
#define LDSMT(r0, r1, r2, r3, addr) \
    asm volatile("ldmatrix.sync.aligned.m8n8.x4.trans.shared.b16 {%0,%1,%2,%3}, [%4];" \
        : "=r"(r0), "=r"(r1), "=r"(r2), "=r"(r3) : "r"(addr))

#define PW 68

// ======================= flash kernel =======================================
// i-tile 64 (4 warps x 16 rows), j-tile 64, 48 j-iterations.
// planes: qh, rh (A hi only; B made exact via hi+lo), bh, bl
#define APLANE (64*PW)
#define FL_SMEM ((4*APLANE + 6*64 + 2*128) * 4)

__global__ void __launch_bounds__(128, 2) flash_mma(const int* __restrict__ mask,
                                                    const float* __restrict__ nw,
                                                    const float* __restrict__ nb)
{
    extern __shared__ __align__(16) uint32_t sm[];
    uint32_t* qh = sm;
    uint32_t* rh = qh + APLANE;
    uint32_t* bh = rh + APLANE;
    uint32_t* bl = bh + APLANE;
    float* s_mr   = (float*)(bl + APLANE);
    float* s_varr = s_mr + 64;
    float* s_sq   = s_varr + 64;
    float* s_qvr  = s_sq + 64;
    float* s_ms   = s_qvr + 64;
    float* s_vars = s_ms + 64;
    float* s_nw   = s_vars + 64;
    float* s_nb   = s_nw + 128;

    const uint32_t sb = smem_u32(sm);
    const uint32_t bh_addr = sb + 2u*APLANE*4u;   // byte addr of bh plane

    const int tid = threadIdx.x;
    const int wid = tid >> 5, lane = tid & 31;
    const int g = lane >> 2, t = lane & 3;
    const int wr = wid * 16;
    const int i0 = blockIdx.x * 64, b = blockIdx.y;

    // ---- fill A planes (q, v_r hi) + row stats + LN params
    {
        const float* qsrc = g_q  + ((size_t)b*NT + i0) * NC;
        const float* rsrc = g_vr + ((size_t)b*NT + i0) * NC;
        for (int idx = tid; idx < 64*64; idx += 128) {
            const int row = idx >> 6, kp = idx & 63;
            float2 v = ((const float2*)(qsrc + (size_t)row*NC))[kp];
            qh[row*PW + kp] = pack_hi(v.x, v.y);
            float2 w = ((const float2*)(rsrc + (size_t)row*NC))[kp];
            rh[row*PW + kp] = pack_hi(w.x, w.y);
        }
        if (tid < 64) {
            const int r = b*NT + i0 + tid;
            s_mr[tid] = g_mr[r]; s_varr[tid] = g_varr[r];
            s_sq[tid] = g_sumq[r]; s_qvr[tid] = g_qvr[r];
        }
        if (tid < 128) { s_nw[tid] = nw[tid]; s_nb[tid] = nb[tid]; }
    }
    __syncthreads();

    const float mr0 = s_mr[wr+g],   varr0 = s_varr[wr+g];
    const float sq0 = s_sq[wr+g],   qvr0  = s_qvr[wr+g];
    const float mr1 = s_mr[wr+g+8], varr1 = s_varr[wr+g+8];
    const float sq1 = s_sq[wr+g+8], qvr1  = s_qvr[wr+g+8];

    float m0 = NEGBIG, m1 = NEGBIG;
    float l0 = 0.f, rp0 = 0.f, rpm0 = 0.f;
    float l1 = 0.f, rp1 = 0.f, rpm1 = 0.f;
    float dO[16][4];
    #pragma unroll
    for (int n = 0; n < 16; n++)
        #pragma unroll
        for (int e = 0; e < 4; e++) dO[n][e] = 0.f;

    const size_t mrow0 = ((size_t)(b*NT + i0 + wr + g)) * NT;
    const size_t mrow1 = mrow0 + (size_t)8 * NT;

    for (int jt = 0; jt < NT/64; jt++) {
        const int j0 = jt * 64;
        __syncthreads();                  // previous tile's B reads done

        // ---- fill B planes (v_s hi/lo) + col stats
        {
            const float* bsrc = g_vs + ((size_t)b*NT + j0) * NC;
            for (int idx = tid; idx < 64*64; idx += 128) {
                const int row = idx >> 6, kp = idx & 63;
                float2 v = ((const float2*)(bsrc + (size_t)row*NC))[kp];
                bh[row*PW + kp] = pack_hi(v.x, v.y);
                bl[row*PW + kp] = pack_lo(v.x, v.y);
            }
            if (tid < 64) {
                const int c = b*NT + j0 + tid;
                s_ms[tid] = g_ms[c]; s_vars[tid] = g_vars[c];
            }
        }
        __syncthreads();

        // ---- score dual MMA (dR: vr.vs, dQ: q.vs), 2-term: A_hi x (B_hi + B_lo)
        float dR[8][4], dQ[8][4];
        #pragma unroll
        for (int n = 0; n < 8; n++)
            #pragma unroll
            for (int e = 0; e < 4; e++) { dR[n][e] = 0.f; dQ[n][e] = 0.f; }

        #pragma unroll
        for (int ks = 0; ks < 8; ks++) {
            const int kp0 = ks*8 + t;
            const int ar = (wr + g)*PW, ar8 = ar + 8*PW;
            uint32_t QH[4] = { qh[ar+kp0], qh[ar8+kp0], qh[ar+kp0+4], qh[ar8+kp0+4] };
            uint32_t RH[4] = { rh[ar+kp0], rh[ar8+kp0], rh[ar+kp0+4], rh[ar8+kp0+4] };
            #pragma unroll
            for (int nt = 0; nt < 8; nt++) {
                const int br = (nt*8 + g)*PW;
                uint32_t BH[2] = { bh[br+kp0], bh[br+kp0+4] };
                uint32_t BL[2] = { bl[br+kp0], bl[br+kp0+4] };
                MMA16816(dQ[nt], QH, BH);
                MMA16816(dQ[nt], QH, BL);
                MMA16816(dR[nt], RH, BH);
                MMA16816(dR[nt], RH, BL);
            }
        }

        // ---- scores: rstd via rsqrt (a -> dQ, rstd -> dR); tile max
        float tmax0 = NEGBIG, tmax1 = NEGBIG;
        #pragma unroll
        for (int nt = 0; nt < 8; nt++) {
            const int2 mk0 = *(const int2*)(mask + mrow0 + j0 + nt*8 + t*2);
            const int2 mk1 = *(const int2*)(mask + mrow1 + j0 + nt*8 + t*2);
            #pragma unroll
            for (int c = 0; c < 2; c++) {
                const int j = nt*8 + t*2 + c;
                const float msj = s_ms[j], vars = s_vars[j];
                {
                    const float cross = (dR[nt][c] - 128.f*mr0*msj) * (2.f/128.f);
                    const float rstd = rsqrtf(varr0 + vars + cross + EPSV);
                    float a = (qvr0 + dQ[nt][c] - sq0*(mr0+msj)) * rstd * SCALEV;
                    if ((c == 0 ? mk0.x : mk0.y) != 0) a = NEGBIG;
                    dQ[nt][c] = a; dR[nt][c] = rstd;
                    tmax0 = fmaxf(tmax0, a);
                }
                {
                    const float cross = (dR[nt][2+c] - 128.f*mr1*msj) * (2.f/128.f);
                    const float rstd = rsqrtf(varr1 + vars + cross + EPSV);
                    float a = (qvr1 + dQ[nt][2+c] - sq1*(mr1+msj)) * rstd * SCALEV;
                    if ((c == 0 ? mk1.x : mk1.y) != 0) a = NEGBIG;
                    dQ[nt][2+c] = a; dR[nt][2+c] = rstd;
                    tmax1 = fmaxf(tmax1, a);
                }
            }
        }

        // ---- online max update (reduce over t-quad) + rescale
        tmax0 = fmaxf(tmax0, __shfl_xor_sync(0xffffffffu, tmax0, 1));
        tmax0 = fmaxf(tmax0, __shfl_xor_sync(0xffffffffu, tmax0, 2));
        tmax1 = fmaxf(tmax1, __shfl_xor_sync(0xffffffffu, tmax1, 1));
        tmax1 = fmaxf(tmax1, __shfl_xor_sync(0xffffffffu, tmax1, 2));
        const float mn0 = fmaxf(m0, tmax0), sc0 = __expf(m0 - mn0);
        const float mn1 = fmaxf(m1, tmax1), sc1 = __expf(m1 - mn1);
        m0 = mn0; m1 = mn1;
        l0 *= sc0; rp0 *= sc0; rpm0 *= sc0;
        l1 *= sc1; rp1 *= sc1; rpm1 *= sc1;
        #pragma unroll
        for (int n = 0; n < 16; n++) {
            dO[n][0] *= sc0; dO[n][1] *= sc0;
            dO[n][2] *= sc1; dO[n][3] *= sc1;
        }

        // ---- W = exp(a-m)*rstd; accumulate row scalars
        float W[8][4];
        #pragma unroll
        for (int nt = 0; nt < 8; nt++) {
            #pragma unroll
            for (int c = 0; c < 2; c++) {
                const int j = nt*8 + t*2 + c;
                const float msj = s_ms[j];
                const float u0 = __expf(dQ[nt][c] - m0);
                const float w0 = u0 * dR[nt][c];
                l0 += u0; rp0 += w0; rpm0 += w0 * (mr0 + msj);
                W[nt][c] = w0;
                const float u1 = __expf(dQ[nt][2+c] - m1);
                const float w1 = u1 * dR[nt][2+c];
                l1 += u1; rp1 += w1; rpm1 += w1 * (mr1 + msj);
                W[nt][2+c] = w1;
            }
        }

        // ---- O += W @ v_s  (hi*hi only: P@v_s term is ~2.5% of output energy)
        #pragma unroll
        for (int ks = 0; ks < 4; ks++) {
            uint32_t Ah[4] = {
                pack_hi(W[2*ks][0],   W[2*ks][1]),   pack_hi(W[2*ks][2],   W[2*ks][3]),
                pack_hi(W[2*ks+1][0], W[2*ks+1][1]), pack_hi(W[2*ks+1][2], W[2*ks+1][3]) };
            const uint32_t loff = ((uint32_t)(ks*16 + (lane & 15)) * PW
                                 + (uint32_t)((lane >> 4) * 4)) * 4u;
            #pragma unroll
            for (int dp = 0; dp < 8; dp++) {
                const uint32_t off = loff + (uint32_t)(dp*8) * 4u;
                uint32_t h0, h1, h2, h3;
                LDSMT(h0, h1, h2, h3, bh_addr + off);
                uint32_t BH0[2] = {h0, h1}, BH1[2] = {h2, h3};
                MMA16816(dO[2*dp],   Ah, BH0);
                MMA16816(dO[2*dp+1], Ah, BH1);
            }
        }
    }

    // ---- finalize: reduce scalars over t-quad, normalize, +rp*vr-rpm, LN
    l0   += __shfl_xor_sync(0xffffffffu, l0, 1);   l0   += __shfl_xor_sync(0xffffffffu, l0, 2);
    rp0  += __shfl_xor_sync(0xffffffffu, rp0, 1);  rp0  += __shfl_xor_sync(0xffffffffu, rp0, 2);
    rpm0 += __shfl_xor_sync(0xffffffffu, rpm0, 1); rpm0 += __shfl_xor_sync(0xffffffffu, rpm0, 2);
    l1   += __shfl_xor_sync(0xffffffffu, l1, 1);   l1   += __shfl_xor_sync(0xffffffffu, l1, 2);
    rp1  += __shfl_xor_sync(0xffffffffu, rp1, 1);  rp1  += __shfl_xor_sync(0xffffffffu, rp1, 2);
    rpm1 += __shfl_xor_sync(0xffffffffu, rpm1, 1); rpm1 += __shfl_xor_sync(0xffffffffu, rpm1, 2);
    const float inv0 = (l0 > 0.f) ? __fdividef(1.f, l0) : 0.f;
    const float inv1 = (l1 > 0.f) ? __fdividef(1.f, l1) : 0.f;

    const size_t rbase0 = ((size_t)(b*NT + i0 + wr + g)) * NC;
    const size_t rbase1 = rbase0 + (size_t)8 * NC;
    #pragma unroll
    for (int n = 0; n < 16; n++) {
        const int d0 = n*8 + t*2;
        const float2 vrA = *(const float2*)(g_vr + rbase0 + d0);
        float v0 = (dO[n][0] + rp0*vrA.x - rpm0) * inv0;
        float v1 = (dO[n][1] + rp0*vrA.y - rpm0) * inv0;
        v0 = v0 * s_nw[d0]   + s_nb[d0];
        v1 = v1 * s_nw[d0+1] + s_nb[d0+1];
        *(float2*)(g_on + rbase0 + d0) = make_float2(v0, v1);
        const float2 vrB = *(const float2*)(g_vr + rbase1 + d0);
        float w0 = (dO[n][2] + rp1*vrB.x - rpm1) * inv1;
        float w1 = (dO[n][3] + rp1*vrB.y - rpm1) * inv1;
        w0 = w0 * s_nw[d0]   + s_nb[d0];
        w1 = w1 * s_nw[d0+1] + s_nb[d0+1];
        *(float2*)(g_on + rbase1 + d0) = make_float2(w0, w1);
    }
}

// ======================= qkv projections via HMMA ===========================
// 128-row x 128-col tile, K accumulated over 1-2 sources of 128.
#define QPLANE (128*PW)
#define QK_SMEM (4*QPLANE*4)

__global__ void __launch_bounds__(512, 1) qkv_mma(const float* __restrict__ x,
                                                  const float* __restrict__ recv,
                                                  const float* __restrict__ send,
                                                  const float* __restrict__ res_r,
                                                  const float* __restrict__ res_s,
                                                  const float* __restrict__ ra,
                                                  const float* __restrict__ qw)
{
    extern __shared__ __align__(16) uint32_t sm[];
    uint32_t* ah_ = sm;
    uint32_t* al_ = ah_ + QPLANE;
    uint32_t* wh_ = al_ + QPLANE;
    uint32_t* wl_ = wh_ + QPLANE;

    const int tid = threadIdx.x;
    const int wid = tid >> 5, lane = tid & 31;
    const int g = lane >> 2, t = lane & 3;
    const int wr = (wid & 3) * 32, wc = (wid >> 2) * 32;
    const int mode = blockIdx.y;
    const int r0 = blockIdx.x * 128;

    float acc[2][4][4];
    #pragma unroll
    for (int mt = 0; mt < 2; mt++)
        #pragma unroll
        for (int nt = 0; nt < 4; nt++)
            #pragma unroll
            for (int e = 0; e < 4; e++) acc[mt][nt][e] = 0.f;

    const int nsrc = (mode == 2) ? 1 : 2;
    for (int src = 0; src < nsrc; src++) {
        const float* A; const float* W; int ws;
        if (mode == 0)      { A = src ? recv : x; W = src ? ra : ra + NC;   ws = 3*NC; }
        else if (mode == 1) { A = src ? send : x; W = src ? ra : ra + 2*NC; ws = 3*NC; }
        else                { A = x; W = qw; ws = NC; }

        __syncthreads();     // prior MMA reads done
        for (int idx = tid; idx < 128*64; idx += 512) {
            const int row = idx >> 6, kp = idx & 63;
            const int r = r0 + row, bb = r / NT, n = r % NT;
            float2 v = ((const float2*)(A + (size_t)n*NB*NC + (size_t)bb*NC))[kp];
            ah_[row*PW + kp] = pack_hi(v.x, v.y);
            al_[row*PW + kp] = pack_lo(v.x, v.y);
            float2 w = ((const float2*)(W + (size_t)row*ws))[kp];
            wh_[row*PW + kp] = pack_hi(w.x, w.y);
            wl_[row*PW + kp] = pack_lo(w.x, w.y);
        }
        __syncthreads();

        #pragma unroll
        for (int ks = 0; ks < 8; ks++) {
            const int kp0 = ks*8 + t;
            uint32_t Bh[4][2], Bl[4][2];
            #pragma unroll
            for (int nt = 0; nt < 4; nt++) {
                const int br = (wc + nt*8 + g)*PW;
                Bh[nt][0] = wh_[br+kp0]; Bh[nt][1] = wh_[br+kp0+4];
                Bl[nt][0] = wl_[br+kp0]; Bl[nt][1] = wl_[br+kp0+4];
            }
            #pragma unroll
            for (int mt = 0; mt < 2; mt++) {
                const int ar = (wr + mt*16 + g)*PW, ar8 = ar + 8*PW;
                uint32_t Ah[4] = { ah_[ar+kp0], ah_[ar8+kp0], ah_[ar+kp0+4], ah_[ar8+kp0+4] };
                uint32_t Al[4] = { al_[ar+kp0], al_[ar8+kp0], al_[ar+kp0+4], al_[ar8+kp0+4] };
                #pragma unroll
                for (int nt = 0; nt < 4; nt++) {
                    MMA16816(acc[mt][nt], Ah, Bh[nt]);
                    MMA16816(acc[mt][nt], Ah, Bl[nt]);
                    MMA16816(acc[mt][nt], Al, Bh[nt]);
                }
            }
        }
    }

    float* out = (mode == 0) ? g_vr : (mode == 1) ? g_vs : g_q;
    const float* res = (mode == 0) ? res_r : (mode == 1) ? res_s : nullptr;
    #pragma unroll
    for (int mt = 0; mt < 2; mt++) {
        #pragma unroll
        for (int rg = 0; rg < 2; rg++) {
            const int li = wr + mt*16 + g + rg*8;
            const int r = r0 + li, bb = r / NT, n = r % NT;
            #pragma unroll
            for (int nt = 0; nt < 4; nt++) {
                const int c = wc + nt*8 + t*2;
                float v0 = acc[mt][nt][rg*2+0];
                float v1 = acc[mt][nt][rg*2+1];
                if (res) {
                    float2 rr = *(const float2*)(res + (size_t)n*NB*NC + (size_t)bb*NC + c);
                    v0 += rr.x; v1 += rr.y;
                }
                *(float2*)(out + ((size_t)bb*NT + n)*NC + c) = make_float2(v0, v1);
            }
        }
    }
}

// ======================= output projections via HMMA ========================
__global__ void __launch_bounds__(512, 1) proj_mma(const float* __restrict__ pw,
                                                   const float* __restrict__ pb,
                                                   const float* __restrict__ rw,
                                                   const float* __restrict__ rb,
                                                   const float* __restrict__ sw,
                                                   const float* __restrict__ sb,
                                                   float* __restrict__ out)
{
    extern __shared__ __align__(16) uint32_t sm[];
    uint32_t* ah_ = sm;
    uint32_t* al_ = ah_ + QPLANE;
    uint32_t* wh_ = al_ + QPLANE;
    uint32_t* wl_ = wh_ + QPLANE;

    const int tid = threadIdx.x;
    const int wid = tid >> 5, lane = tid & 31;
    const int g = lane >> 2, t = lane & 3;
    const int wr = (wid & 3) * 32, wc = (wid >> 2) * 32;
    const int mode = blockIdx.y;
    const int r0 = blockIdx.x * 128;

    const float* src = (mode == 0) ? g_on : (mode == 1) ? g_vr : g_vs;
    const float* W   = (mode == 0) ? pw   : (mode == 1) ? rw   : sw;
    const float* bia = (mode == 0) ? pb   : (mode == 1) ? rb   : sb;

    for (int idx = tid; idx < 128*64; idx += 512) {
        const int row = idx >> 6, kp = idx & 63;
        float2 v = ((const float2*)(src + (size_t)(r0+row)*NC))[kp];
        ah_[row*PW + kp] = pack_hi(v.x, v.y);
        al_[row*PW + kp] = pack_lo(v.x, v.y);
        float2 w = ((const float2*)(W + (size_t)row*NC))[kp];
        wh_[row*PW + kp] = pack_hi(w.x, w.y);
        wl_[row*PW + kp] = pack_lo(w.x, w.y);
    }
    __syncthreads();

    float acc[2][4][4];
    #pragma unroll
    for (int mt = 0; mt < 2; mt++)
        #pragma unroll
        for (int nt = 0; nt < 4; nt++)
            #pragma unroll
            for (int e = 0; e < 4; e++) acc[mt][nt][e] = 0.f;

    #pragma unroll
    for (int ks = 0; ks < 8; ks++) {
        const int kp0 = ks*8 + t;
        uint32_t Bh[4][2], Bl[4][2];
        #pragma unroll
        for (int nt = 0; nt < 4; nt++) {
            const int br = (wc + nt*8 + g)*PW;
            Bh[nt][0] = wh_[br+kp0]; Bh[nt][1] = wh_[br+kp0+4];
            Bl[nt][0] = wl_[br+kp0]; Bl[nt][1] = wl_[br+kp0+4];
        }
        #pragma unroll
        for (int mt = 0; mt < 2; mt++) {
            const int ar = (wr + mt*16 + g)*PW, ar8 = ar + 8*PW;
            uint32_t Ah[4] = { ah_[ar+kp0], ah_[ar8+kp0], ah_[ar+kp0+4], ah_[ar8+kp0+4] };
            uint32_t Al[4] = { al_[ar+kp0], al_[ar8+kp0], al_[ar+kp0+4], al_[ar8+kp0+4] };
            #pragma unroll
            for (int nt = 0; nt < 4; nt++) {
                MMA16816(acc[mt][nt], Ah, Bh[nt]);
                MMA16816(acc[mt][nt], Ah, Bl[nt]);
                MMA16816(acc[mt][nt], Al, Bh[nt]);
            }
        }
    }

    const size_t obase = (size_t)mode * MTOT * NC;
    #pragma unroll
    for (int mt = 0; mt < 2; mt++) {
        #pragma unroll
        for (int rg = 0; rg < 2; rg++) {
            const int li = wr + mt*16 + g + rg*8;
            const int r = r0 + li, bb = r / NT, n = r % NT;
            #pragma unroll
            for (int nt = 0; nt < 4; nt++) {
                const int c = wc + nt*8 + t*2;
                const float2 bb2 = *(const float2*)(bia + c);
                float v0 = acc[mt][nt][rg*2+0] + bb2.x;
                float v1 = acc[mt][nt][rg*2+1] + bb2.y;
                *(float2*)(out + obase + (size_t)n*NB*NC + (size_t)bb*NC + c) = make_float2(v0, v1);
            }
        }
    }
}

// ---------------- Kernel A2: per-row stats ----------------------------------
__global__ void row_stats()
{
    const int r = blockIdx.x;
    const int c = threadIdx.x;           // 128 threads
    const size_t base = (size_t)r * NC + c;
    float vr = g_vr[base], vs = g_vs[base], q = g_q[base];
    __shared__ float sh[6][128];
    sh[0][c] = vr; sh[1][c] = vr*vr; sh[2][c] = vs;
    sh[3][c] = vs*vs; sh[4][c] = q; sh[5][c] = q*vr;
    __syncthreads();
    for (int off = 64; off > 0; off >>= 1) {
        if (c < off)
            #pragma unroll
            for (int i = 0; i < 6; i++) sh[i][c] += sh[i][c + off];
        __syncthreads();
    }
    if (c == 0) {
        float mr = sh[0][0] * (1.f/NC);
        float ms = sh[2][0] * (1.f/NC);
        g_mr[r] = mr;
        g_ms[r] = ms;
        g_varr[r] = sh[1][0] * (1.f/NC) - mr*mr;
        g_vars[r] = sh[3][0] * (1.f/NC) - ms*ms;
        g_sumq[r] = sh[4][0];
        g_qvr[r]  = sh[5][0];
    }
}

// ---------------- launch ----------------------------------------------------
extern "C" void kernel_launch(void* const* d_in, const int* in_sizes, int n_in,
                              void* d_out, int out_size)
{
    const float* x    = (const float*)d_in[0];
    const int*   mask = (const int*)d_in[1];      // bool uploaded as int32
    const float* recv = (const float*)d_in[2];
    const float* send = (const float*)d_in[3];
    const float* resr = (const float*)d_in[4];
    const float* ress = (const float*)d_in[5];
    const float* ra   = (const float*)d_in[6];
    const float* qw   = (const float*)d_in[7];
    const float* pw   = (const float*)d_in[8];
    const float* pb   = (const float*)d_in[9];
    const float* rw   = (const float*)d_in[10];
    const float* rb   = (const float*)d_in[11];
    const float* sw   = (const float*)d_in[12];
    const float* sb   = (const float*)d_in[13];
    const float* nw   = (const float*)d_in[14];
    const float* nb   = (const float*)d_in[15];
    float* out = (float*)d_out;

    cudaFuncSetAttribute(flash_mma, cudaFuncAttributeMaxDynamicSharedMemorySize, FL_SMEM);
    cudaFuncSetAttribute(qkv_mma,   cudaFuncAttributeMaxDynamicSharedMemorySize, QK_SMEM);
    cudaFuncSetAttribute(proj_mma,  cudaFuncAttributeMaxDynamicSharedMemorySize, QK_SMEM);

    qkv_mma<<<dim3(MTOT/128, 3), 512, QK_SMEM>>>(x, recv, send, resr, ress, ra, qw);
    row_stats<<<MTOT, 128>>>();
    flash_mma<<<dim3(NT/64, NB), 128, FL_SMEM>>>(mask, nw, nb);
    proj_mma<<<dim3(MTOT/128, 3), 512, QK_SMEM>>>(pw, pb, rw, rb, sw, sb, out);
}

// round 16
// speedup vs baseline: 3.5947x; 1.0337x over previous
#include <cuda_runtime.h>
#include <cuda_bf16.h>
#include <math.h>
#include <stdint.h>

#define NT 3072
#define NB 4
#define NC 128
#define MTOT (NB*NT)
#define EPSV 1e-5f
#define SCALEV 0.08838834764831845f  /* 1/sqrt(128) */
#define NEGBIG -1e30f

// ---------------- scratch (device globals; established set only) ------------
__device__ float g_vr[(size_t)NB*NT*NC];
__device__ float g_vs[(size_t)NB*NT*NC];
__device__ float g_q [(size_t)NB*NT*NC];
__device__ float g_on[(size_t)NB*NT*NC];
__device__ float g_mr[MTOT], g_ms[MTOT], g_varr[MTOT], g_vars[MTOT];
__device__ float g_sumq[MTOT], g_qvr[MTOT];

// ---------------- helpers ----------------------------------------------------
__device__ __forceinline__ uint32_t smem_u32(const void* p) {
    uint32_t a;
    asm("{ .reg .u64 t; cvta.to.shared.u64 t, %1; cvt.u32.u64 %0, t; }"
        : "=r"(a) : "l"(p));
    return a;
}
__device__ __forceinline__ uint32_t pack_hi(float x, float y) {
    __nv_bfloat162 h;
    h.x = __float2bfloat16(x); h.y = __float2bfloat16(y);
    return *(uint32_t*)&h;
}
__device__ __forceinline__ uint32_t pack_lo(float x, float y) {
    __nv_bfloat162 h;
    h.x = __float2bfloat16(x - __bfloat162float(__float2bfloat16(x)));
    h.y = __float2bfloat16(y - __bfloat162float(__float2bfloat16(y)));
    return *(uint32_t*)&h;
}
#define MMA16816(d, a, b) \
    asm volatile("mma.sync.aligned.m16n8k16.row.col.f32.bf16.bf16.f32 " \
        "{%0,%1,%2,%3}, {%4,%5,%6,%7}, {%8,%9}, {%0,%1,%2,%3};" \
        : "+f"((d)[0]), "+f"((d)[1]), "+f"((d)[2]), "+f"((d)[3]) \
        : "r"((a)[0]), "r"((a)[1]), "r"((a)[2]), "r"((a)[3]), \
          "r"((b)[0]), "r"((b)[1]))
#define LDSMT(r0, r1, r2, r3, addr) \
    asm volatile("ldmatrix.sync.aligned.m8n8.x4.trans.shared.b16 {%0,%1,%2,%3}, [%4];" \
        : "=r"(r0), "=r"(r1), "=r"(r2), "=r"(r3) : "r"(addr))

#define PW 68

// ======================= flash kernel (8 warps, in-block j-split) ============
// i-tile 64; warp (rg=w&3, jh=w>>2): rows 16*rg..+15, j-half 32*jh..+31.
#define APLANE (64*PW)
#define FL_SMEM ((4*APLANE + 6*64 + 2*128 + 4*128) * 4)

__global__ void __launch_bounds__(256, 2) flash_mma(const int* __restrict__ mask,
                                                    const float* __restrict__ nw,
                                                    const float* __restrict__ nb)
{
    extern __shared__ __align__(16) uint32_t sm[];
    uint32_t* qh = sm;
    uint32_t* rh = qh + APLANE;
    uint32_t* bh = rh + APLANE;
    uint32_t* bl = bh + APLANE;
    float* s_mr   = (float*)(bl + APLANE);
    float* s_varr = s_mr + 64;
    float* s_sq   = s_varr + 64;
    float* s_qvr  = s_sq + 64;
    float* s_ms   = s_qvr + 64;
    float* s_vars = s_ms + 64;
    float* s_nw   = s_vars + 64;
    float* s_nb   = s_nw + 128;
    float* s_tm   = s_nb + 128;     // [jh*64 + row] tile max exchange
    float* s_l    = s_tm + 128;     // final scalar exchange
    float* s_rp   = s_l + 128;
    float* s_rpm  = s_rp + 128;

    const uint32_t sb = smem_u32(sm);
    const uint32_t bh_addr = sb + 2u*APLANE*4u;

    const int tid = threadIdx.x;
    const int wid = tid >> 5, lane = tid & 31;
    const int g = lane >> 2, t = lane & 3;
    const int rg = wid & 3, jh = wid >> 2;
    const int wr = rg * 16;
    const int jb = jh * 32;
    const int i0 = blockIdx.x * 64, b = blockIdx.y;

    // ---- fill A planes (q, v_r hi) + row stats + LN params
    {
        const float* qsrc = g_q  + ((size_t)b*NT + i0) * NC;
        const float* rsrc = g_vr + ((size_t)b*NT + i0) * NC;
        for (int idx = tid; idx < 64*64; idx += 256) {
            const int row = idx >> 6, kp = idx & 63;
            float2 v = ((const float2*)(qsrc + (size_t)row*NC))[kp];
            qh[row*PW + kp] = pack_hi(v.x, v.y);
            float2 w = ((const float2*)(rsrc + (size_t)row*NC))[kp];
            rh[row*PW + kp] = pack_hi(w.x, w.y);
        }
        if (tid < 64) {
            const int r = b*NT + i0 + tid;
            s_mr[tid] = g_mr[r]; s_varr[tid] = g_varr[r];
            s_sq[tid] = g_sumq[r]; s_qvr[tid] = g_qvr[r];
        }
        if (tid < 128) { s_nw[tid] = nw[tid]; s_nb[tid] = nb[tid]; }
    }
    __syncthreads();

    const float mr0 = s_mr[wr+g],   varr0 = s_varr[wr+g];
    const float sq0 = s_sq[wr+g],   qvr0  = s_qvr[wr+g];
    const float mr1 = s_mr[wr+g+8], varr1 = s_varr[wr+g+8];
    const float sq1 = s_sq[wr+g+8], qvr1  = s_qvr[wr+g+8];

    float m0 = NEGBIG, m1 = NEGBIG;
    float l0 = 0.f, rp0 = 0.f, rpm0 = 0.f;
    float l1 = 0.f, rp1 = 0.f, rpm1 = 0.f;
    float dO[16][4];
    #pragma unroll
    for (int n = 0; n < 16; n++)
        #pragma unroll
        for (int e = 0; e < 4; e++) dO[n][e] = 0.f;

    const size_t mrow0 = ((size_t)(b*NT + i0 + wr + g)) * NT;
    const size_t mrow1 = mrow0 + (size_t)8 * NT;

    for (int jt = 0; jt < NT/64; jt++) {
        const int j0 = jt * 64;
        __syncthreads();                  // prior tile's B reads + s_tm reads done

        // ---- fill B planes (v_s hi/lo) + col stats
        {
            const float* bsrc = g_vs + ((size_t)b*NT + j0) * NC;
            for (int idx = tid; idx < 64*64; idx += 256) {
                const int row = idx >> 6, kp = idx & 63;
                float2 v = ((const float2*)(bsrc + (size_t)row*NC))[kp];
                bh[row*PW + kp] = pack_hi(v.x, v.y);
                bl[row*PW + kp] = pack_lo(v.x, v.y);
            }
            if (tid < 64) {
                const int c = b*NT + j0 + tid;
                s_ms[tid] = g_ms[c]; s_vars[tid] = g_vars[c];
            }
        }
        __syncthreads();

        // ---- score dual MMA on this warp's j-half (4 n-tiles)
        float dR[4][4], dQ[4][4];
        #pragma unroll
        for (int n = 0; n < 4; n++)
            #pragma unroll
            for (int e = 0; e < 4; e++) { dR[n][e] = 0.f; dQ[n][e] = 0.f; }

        #pragma unroll
        for (int ks = 0; ks < 8; ks++) {
            const int kp0 = ks*8 + t;
            const int ar = (wr + g)*PW, ar8 = ar + 8*PW;
            uint32_t QH[4] = { qh[ar+kp0], qh[ar8+kp0], qh[ar+kp0+4], qh[ar8+kp0+4] };
            uint32_t RH[4] = { rh[ar+kp0], rh[ar8+kp0], rh[ar+kp0+4], rh[ar8+kp0+4] };
            #pragma unroll
            for (int nt = 0; nt < 4; nt++) {
                const int br = (jb + nt*8 + g)*PW;
                uint32_t BH[2] = { bh[br+kp0], bh[br+kp0+4] };
                uint32_t BL[2] = { bl[br+kp0], bl[br+kp0+4] };
                MMA16816(dQ[nt], QH, BH);
                MMA16816(dQ[nt], QH, BL);
                MMA16816(dR[nt], RH, BH);
                MMA16816(dR[nt], RH, BL);
            }
        }

        // ---- scores: rstd via rsqrt (a -> dQ, rstd -> dR); half-tile max
        float tmax0 = NEGBIG, tmax1 = NEGBIG;
        #pragma unroll
        for (int nt = 0; nt < 4; nt++) {
            const int2 mk0 = *(const int2*)(mask + mrow0 + j0 + jb + nt*8 + t*2);
            const int2 mk1 = *(const int2*)(mask + mrow1 + j0 + jb + nt*8 + t*2);
            #pragma unroll
            for (int c = 0; c < 2; c++) {
                const int j = jb + nt*8 + t*2 + c;
                const float msj = s_ms[j], vars = s_vars[j];
                {
                    const float cross = (dR[nt][c] - 128.f*mr0*msj) * (2.f/128.f);
                    const float rstd = rsqrtf(varr0 + vars + cross + EPSV);
                    float a = (qvr0 + dQ[nt][c] - sq0*(mr0+msj)) * rstd * SCALEV;
                    if ((c == 0 ? mk0.x : mk0.y) != 0) a = NEGBIG;
                    dQ[nt][c] = a; dR[nt][c] = rstd;
                    tmax0 = fmaxf(tmax0, a);
                }
                {
                    const float cross = (dR[nt][2+c] - 128.f*mr1*msj) * (2.f/128.f);
                    const float rstd = rsqrtf(varr1 + vars + cross + EPSV);
                    float a = (qvr1 + dQ[nt][2+c] - sq1*(mr1+msj)) * rstd * SCALEV;
                    if ((c == 0 ? mk1.x : mk1.y) != 0) a = NEGBIG;
                    dQ[nt][2+c] = a; dR[nt][2+c] = rstd;
                    tmax1 = fmaxf(tmax1, a);
                }
            }
        }
        tmax0 = fmaxf(tmax0, __shfl_xor_sync(0xffffffffu, tmax0, 1));
        tmax0 = fmaxf(tmax0, __shfl_xor_sync(0xffffffffu, tmax0, 2));
        tmax1 = fmaxf(tmax1, __shfl_xor_sync(0xffffffffu, tmax1, 1));
        tmax1 = fmaxf(tmax1, __shfl_xor_sync(0xffffffffu, tmax1, 2));

        // ---- exchange half-tile maxes between partner warps (same rows)
        if (t == 0) {
            s_tm[jh*64 + wr + g]     = tmax0;
            s_tm[jh*64 + wr + g + 8] = tmax1;
        }
        __syncthreads();
        const float ptm0 = s_tm[(jh^1)*64 + wr + g];
        const float ptm1 = s_tm[(jh^1)*64 + wr + g + 8];

        const float mn0 = fmaxf(m0, fmaxf(tmax0, ptm0)), sc0 = __expf(m0 - mn0);
        const float mn1 = fmaxf(m1, fmaxf(tmax1, ptm1)), sc1 = __expf(m1 - mn1);
        m0 = mn0; m1 = mn1;
        l0 *= sc0; rp0 *= sc0; rpm0 *= sc0;
        l1 *= sc1; rp1 *= sc1; rpm1 *= sc1;
        #pragma unroll
        for (int n = 0; n < 16; n++) {
            dO[n][0] *= sc0; dO[n][1] *= sc0;
            dO[n][2] *= sc1; dO[n][3] *= sc1;
        }

        // ---- W = exp(a-m)*rstd; accumulate row scalars (this half)
        float W[4][4];
        #pragma unroll
        for (int nt = 0; nt < 4; nt++) {
            #pragma unroll
            for (int c = 0; c < 2; c++) {
                const int j = jb + nt*8 + t*2 + c;
                const float msj = s_ms[j];
                const float u0 = __expf(dQ[nt][c] - m0);
                const float w0 = u0 * dR[nt][c];
                l0 += u0; rp0 += w0; rpm0 += w0 * (mr0 + msj);
                W[nt][c] = w0;
                const float u1 = __expf(dQ[nt][2+c] - m1);
                const float w1 = u1 * dR[nt][2+c];
                l1 += u1; rp1 += w1; rpm1 += w1 * (mr1 + msj);
                W[nt][2+c] = w1;
            }
        }

        // ---- O += W @ v_s over this j-half (hi*hi only), k = 32
        #pragma unroll
        for (int ks = 0; ks < 2; ks++) {
            uint32_t Ah[4] = {
                pack_hi(W[2*ks][0],   W[2*ks][1]),   pack_hi(W[2*ks][2],   W[2*ks][3]),
                pack_hi(W[2*ks+1][0], W[2*ks+1][1]), pack_hi(W[2*ks+1][2], W[2*ks+1][3]) };
            const uint32_t loff = ((uint32_t)(jb + ks*16 + (lane & 15)) * PW
                                 + (uint32_t)((lane >> 4) * 4)) * 4u;
            #pragma unroll
            for (int dp = 0; dp < 8; dp++) {
                const uint32_t off = loff + (uint32_t)(dp*8) * 4u;
                uint32_t h0, h1, h2, h3;
                LDSMT(h0, h1, h2, h3, bh_addr + off);
                uint32_t BH0[2] = {h0, h1}, BH1[2] = {h2, h3};
                MMA16816(dO[2*dp],   Ah, BH0);
                MMA16816(dO[2*dp+1], Ah, BH1);
            }
        }
    }

    // ---- finalize: reduce scalars over t-quad; combine halves (same m -> add)
    l0   += __shfl_xor_sync(0xffffffffu, l0, 1);   l0   += __shfl_xor_sync(0xffffffffu, l0, 2);
    rp0  += __shfl_xor_sync(0xffffffffu, rp0, 1);  rp0  += __shfl_xor_sync(0xffffffffu, rp0, 2);
    rpm0 += __shfl_xor_sync(0xffffffffu, rpm0, 1); rpm0 += __shfl_xor_sync(0xffffffffu, rpm0, 2);
    l1   += __shfl_xor_sync(0xffffffffu, l1, 1);   l1   += __shfl_xor_sync(0xffffffffu, l1, 2);
    rp1  += __shfl_xor_sync(0xffffffffu, rp1, 1);  rp1  += __shfl_xor_sync(0xffffffffu, rp1, 2);
    rpm1 += __shfl_xor_sync(0xffffffffu, rpm1, 1); rpm1 += __shfl_xor_sync(0xffffffffu, rpm1, 2);

    if (t == 0) {
        s_l[jh*64 + wr+g] = l0;    s_l[jh*64 + wr+g+8] = l1;
        s_rp[jh*64 + wr+g] = rp0;  s_rp[jh*64 + wr+g+8] = rp1;
        s_rpm[jh*64 + wr+g] = rpm0; s_rpm[jh*64 + wr+g+8] = rpm1;
    }
    __syncthreads();   // scalars posted; planes dead -> reuse qh/rh as float buffer

    float* fx = (float*)sm;   // 64 rows x 128 d = 32 KB (fits in qh+rh planes)
    if (jh == 1) {
        #pragma unroll
        for (int n = 0; n < 16; n++) {
            const int d0 = n*8 + t*2;
            *(float2*)(fx + (wr+g)*128 + d0)   = make_float2(dO[n][0], dO[n][1]);
            *(float2*)(fx + (wr+g+8)*128 + d0) = make_float2(dO[n][2], dO[n][3]);
        }
    }
    __syncthreads();

    if (jh == 0) {
        const float L0   = l0   + s_l[64 + wr+g];
        const float RP0  = rp0  + s_rp[64 + wr+g];
        const float RPM0 = rpm0 + s_rpm[64 + wr+g];
        const float L1   = l1   + s_l[64 + wr+g+8];
        const float RP1  = rp1  + s_rp[64 + wr+g+8];
        const float RPM1 = rpm1 + s_rpm[64 + wr+g+8];
        const float inv0 = (L0 > 0.f) ? __fdividef(1.f, L0) : 0.f;
        const float inv1 = (L1 > 0.f) ? __fdividef(1.f, L1) : 0.f;

        const size_t rbase0 = ((size_t)(b*NT + i0 + wr + g)) * NC;
        const size_t rbase1 = rbase0 + (size_t)8 * NC;
        #pragma unroll
        for (int n = 0; n < 16; n++) {
            const int d0 = n*8 + t*2;
            const float2 oA = *(const float2*)(fx + (wr+g)*128 + d0);
            const float2 vrA = *(const float2*)(g_vr + rbase0 + d0);
            float v0 = (dO[n][0] + oA.x + RP0*vrA.x - RPM0) * inv0;
            float v1 = (dO[n][1] + oA.y + RP0*vrA.y - RPM0) * inv0;
            v0 = v0 * s_nw[d0]   + s_nb[d0];
            v1 = v1 * s_nw[d0+1] + s_nb[d0+1];
            *(float2*)(g_on + rbase0 + d0) = make_float2(v0, v1);
            const float2 oB = *(const float2*)(fx + (wr+g+8)*128 + d0);
            const float2 vrB = *(const float2*)(g_vr + rbase1 + d0);
            float w0 = (dO[n][2] + oB.x + RP1*vrB.x - RPM1) * inv1;
            float w1 = (dO[n][3] + oB.y + RP1*vrB.y - RPM1) * inv1;
            w0 = w0 * s_nw[d0]   + s_nb[d0];
            w1 = w1 * s_nw[d0+1] + s_nb[d0+1];
            *(float2*)(g_on + rbase1 + d0) = make_float2(w0, w1);
        }
    }
}

// ======================= qkv projections via HMMA ===========================
#define QPLANE (128*PW)
#define QK_SMEM (4*QPLANE*4)

__global__ void __launch_bounds__(512, 1) qkv_mma(const float* __restrict__ x,
                                                  const float* __restrict__ recv,
                                                  const float* __restrict__ send,
                                                  const float* __restrict__ res_r,
                                                  const float* __restrict__ res_s,
                                                  const float* __restrict__ ra,
                                                  const float* __restrict__ qw)
{
    extern __shared__ __align__(16) uint32_t sm[];
    uint32_t* ah_ = sm;
    uint32_t* al_ = ah_ + QPLANE;
    uint32_t* wh_ = al_ + QPLANE;
    uint32_t* wl_ = wh_ + QPLANE;

    const int tid = threadIdx.x;
    const int wid = tid >> 5, lane = tid & 31;
    const int g = lane >> 2, t = lane & 3;
    const int wr = (wid & 3) * 32, wc = (wid >> 2) * 32;
    const int mode = blockIdx.y;
    const int r0 = blockIdx.x * 128;

    float acc[2][4][4];
    #pragma unroll
    for (int mt = 0; mt < 2; mt++)
        #pragma unroll
        for (int nt = 0; nt < 4; nt++)
            #pragma unroll
            for (int e = 0; e < 4; e++) acc[mt][nt][e] = 0.f;

    const int nsrc = (mode == 2) ? 1 : 2;
    for (int src = 0; src < nsrc; src++) {
        const float* A; const float* W; int ws;
        if (mode == 0)      { A = src ? recv : x; W = src ? ra : ra + NC;   ws = 3*NC; }
        else if (mode == 1) { A = src ? send : x; W = src ? ra : ra + 2*NC; ws = 3*NC; }
        else                { A = x; W = qw; ws = NC; }

        __syncthreads();
        for (int idx = tid; idx < 128*64; idx += 512) {
            const int row = idx >> 6, kp = idx & 63;
            const int r = r0 + row, bb = r / NT, n = r % NT;
            float2 v = ((const float2*)(A + (size_t)n*NB*NC + (size_t)bb*NC))[kp];
            ah_[row*PW + kp] = pack_hi(v.x, v.y);
            al_[row*PW + kp] = pack_lo(v.x, v.y);
            float2 w = ((const float2*)(W + (size_t)row*ws))[kp];
            wh_[row*PW + kp] = pack_hi(w.x, w.y);
            wl_[row*PW + kp] = pack_lo(w.x, w.y);
        }
        __syncthreads();

        #pragma unroll
        for (int ks = 0; ks < 8; ks++) {
            const int kp0 = ks*8 + t;
            uint32_t Bh[4][2], Bl[4][2];
            #pragma unroll
            for (int nt = 0; nt < 4; nt++) {
                const int br = (wc + nt*8 + g)*PW;
                Bh[nt][0] = wh_[br+kp0]; Bh[nt][1] = wh_[br+kp0+4];
                Bl[nt][0] = wl_[br+kp0]; Bl[nt][1] = wl_[br+kp0+4];
            }
            #pragma unroll
            for (int mt = 0; mt < 2; mt++) {
                const int ar = (wr + mt*16 + g)*PW, ar8 = ar + 8*PW;
                uint32_t Ah[4] = { ah_[ar+kp0], ah_[ar8+kp0], ah_[ar+kp0+4], ah_[ar8+kp0+4] };
                uint32_t Al[4] = { al_[ar+kp0], al_[ar8+kp0], al_[ar+kp0+4], al_[ar8+kp0+4] };
                #pragma unroll
                for (int nt = 0; nt < 4; nt++) {
                    MMA16816(acc[mt][nt], Ah, Bh[nt]);
                    MMA16816(acc[mt][nt], Ah, Bl[nt]);
                    MMA16816(acc[mt][nt], Al, Bh[nt]);
                }
            }
        }
    }

    float* out = (mode == 0) ? g_vr : (mode == 1) ? g_vs : g_q;
    const float* res = (mode == 0) ? res_r : (mode == 1) ? res_s : nullptr;
    #pragma unroll
    for (int mt = 0; mt < 2; mt++) {
        #pragma unroll
        for (int rg = 0; rg < 2; rg++) {
            const int li = wr + mt*16 + g + rg*8;
            const int r = r0 + li, bb = r / NT, n = r % NT;
            #pragma unroll
            for (int nt = 0; nt < 4; nt++) {
                const int c = wc + nt*8 + t*2;
                float v0 = acc[mt][nt][rg*2+0];
                float v1 = acc[mt][nt][rg*2+1];
                if (res) {
                    float2 rr = *(const float2*)(res + (size_t)n*NB*NC + (size_t)bb*NC + c);
                    v0 += rr.x; v1 += rr.y;
                }
                *(float2*)(out + ((size_t)bb*NT + n)*NC + c) = make_float2(v0, v1);
            }
        }
    }
}

// ======================= output projections via HMMA ========================
__global__ void __launch_bounds__(512, 1) proj_mma(const float* __restrict__ pw,
                                                   const float* __restrict__ pb,
                                                   const float* __restrict__ rw,
                                                   const float* __restrict__ rb,
                                                   const float* __restrict__ sw,
                                                   const float* __restrict__ sb,
                                                   float* __restrict__ out)
{
    extern __shared__ __align__(16) uint32_t sm[];
    uint32_t* ah_ = sm;
    uint32_t* al_ = ah_ + QPLANE;
    uint32_t* wh_ = al_ + QPLANE;
    uint32_t* wl_ = wh_ + QPLANE;

    const int tid = threadIdx.x;
    const int wid = tid >> 5, lane = tid & 31;
    const int g = lane >> 2, t = lane & 3;
    const int wr = (wid & 3) * 32, wc = (wid >> 2) * 32;
    const int mode = blockIdx.y;
    const int r0 = blockIdx.x * 128;

    const float* src = (mode == 0) ? g_on : (mode == 1) ? g_vr : g_vs;
    const float* W   = (mode == 0) ? pw   : (mode == 1) ? rw   : sw;
    const float* bia = (mode == 0) ? pb   : (mode == 1) ? rb   : sb;

    for (int idx = tid; idx < 128*64; idx += 512) {
        const int row = idx >> 6, kp = idx & 63;
        float2 v = ((const float2*)(src + (size_t)(r0+row)*NC))[kp];
        ah_[row*PW + kp] = pack_hi(v.x, v.y);
        al_[row*PW + kp] = pack_lo(v.x, v.y);
        float2 w = ((const float2*)(W + (size_t)row*NC))[kp];
        wh_[row*PW + kp] = pack_hi(w.x, w.y);
        wl_[row*PW + kp] = pack_lo(w.x, w.y);
    }
    __syncthreads();

    float acc[2][4][4];
    #pragma unroll
    for (int mt = 0; mt < 2; mt++)
        #pragma unroll
        for (int nt = 0; nt < 4; nt++)
            #pragma unroll
            for (int e = 0; e < 4; e++) acc[mt][nt][e] = 0.f;

    #pragma unroll
    for (int ks = 0; ks < 8; ks++) {
        const int kp0 = ks*8 + t;
        uint32_t Bh[4][2], Bl[4][2];
        #pragma unroll
        for (int nt = 0; nt < 4; nt++) {
            const int br = (wc + nt*8 + g)*PW;
            Bh[nt][0] = wh_[br+kp0]; Bh[nt][1] = wh_[br+kp0+4];
            Bl[nt][0] = wl_[br+kp0]; Bl[nt][1] = wl_[br+kp0+4];
        }
        #pragma unroll
        for (int mt = 0; mt < 2; mt++) {
            const int ar = (wr + mt*16 + g)*PW, ar8 = ar + 8*PW;
            uint32_t Ah[4] = { ah_[ar+kp0], ah_[ar8+kp0], ah_[ar+kp0+4], ah_[ar8+kp0+4] };
            uint32_t Al[4] = { al_[ar+kp0], al_[ar8+kp0], al_[ar+kp0+4], al_[ar8+kp0+4] };
            #pragma unroll
            for (int nt = 0; nt < 4; nt++) {
                MMA16816(acc[mt][nt], Ah, Bh[nt]);
                MMA16816(acc[mt][nt], Ah, Bl[nt]);
                MMA16816(acc[mt][nt], Al, Bh[nt]);
            }
        }
    }

    const size_t obase = (size_t)mode * MTOT * NC;
    #pragma unroll
    for (int mt = 0; mt < 2; mt++) {
        #pragma unroll
        for (int rg = 0; rg < 2; rg++) {
            const int li = wr + mt*16 + g + rg*8;
            const int r = r0 + li, bb = r / NT, n = r % NT;
            #pragma unroll
            for (int nt = 0; nt < 4; nt++) {
                const int c = wc + nt*8 + t*2;
                const float2 bb2 = *(const float2*)(bia + c);
                float v0 = acc[mt][nt][rg*2+0] + bb2.x;
                float v1 = acc[mt][nt][rg*2+1] + bb2.y;
                *(float2*)(out + obase + (size_t)n*NB*NC + (size_t)bb*NC + c) = make_float2(v0, v1);
            }
        }
    }
}

// ---------------- per-row stats ----------------------------------------------
__global__ void row_stats()
{
    const int r = blockIdx.x;
    const int c = threadIdx.x;           // 128 threads
    const size_t base = (size_t)r * NC + c;
    float vr = g_vr[base], vs = g_vs[base], q = g_q[base];
    __shared__ float sh[6][128];
    sh[0][c] = vr; sh[1][c] = vr*vr; sh[2][c] = vs;
    sh[3][c] = vs*vs; sh[4][c] = q; sh[5][c] = q*vr;
    __syncthreads();
    for (int off = 64; off > 0; off >>= 1) {
        if (c < off)
            #pragma unroll
            for (int i = 0; i < 6; i++) sh[i][c] += sh[i][c + off];
        __syncthreads();
    }
    if (c == 0) {
        float mr = sh[0][0] * (1.f/NC);
        float ms = sh[2][0] * (1.f/NC);
        g_mr[r] = mr;
        g_ms[r] = ms;
        g_varr[r] = sh[1][0] * (1.f/NC) - mr*mr;
        g_vars[r] = sh[3][0] * (1.f/NC) - ms*ms;
        g_sumq[r] = sh[4][0];
        g_qvr[r]  = sh[5][0];
    }
}

// ---------------- launch ----------------------------------------------------
extern "C" void kernel_launch(void* const* d_in, const int* in_sizes, int n_in,
                              void* d_out, int out_size)
{
    const float* x    = (const float*)d_in[0];
    const int*   mask = (const int*)d_in[1];      // bool uploaded as int32
    const float* recv = (const float*)d_in[2];
    const float* send = (const float*)d_in[3];
    const float* resr = (const float*)d_in[4];
    const float* ress = (const float*)d_in[5];
    const float* ra   = (const float*)d_in[6];
    const float* qw   = (const float*)d_in[7];
    const float* pw   = (const float*)d_in[8];
    const float* pb   = (const float*)d_in[9];
    const float* rw   = (const float*)d_in[10];
    const float* rb   = (const float*)d_in[11];
    const float* sw   = (const float*)d_in[12];
    const float* sb   = (const float*)d_in[13];
    const float* nw   = (const float*)d_in[14];
    const float* nb   = (const float*)d_in[15];
    float* out = (float*)d_out;

    cudaFuncSetAttribute(flash_mma, cudaFuncAttributeMaxDynamicSharedMemorySize, FL_SMEM);
    cudaFuncSetAttribute(qkv_mma,   cudaFuncAttributeMaxDynamicSharedMemorySize, QK_SMEM);
    cudaFuncSetAttribute(proj_mma,  cudaFuncAttributeMaxDynamicSharedMemorySize, QK_SMEM);

    qkv_mma<<<dim3(MTOT/128, 3), 512, QK_SMEM>>>(x, recv, send, resr, ress, ra, qw);
    row_stats<<<MTOT, 128>>>();
    flash_mma<<<dim3(NT/64, NB), 256, FL_SMEM>>>(mask, nw, nb);
    proj_mma<<<dim3(MTOT/128, 3), 512, QK_SMEM>>>(pw, pb, rw, rb, sw, sb, out);
}

// round 17
// speedup vs baseline: 3.9182x; 1.0900x over previous
#include <cuda_runtime.h>
#include <cuda_bf16.h>
#include <math.h>
#include <stdint.h>

#define NT 3072
#define NB 4
#define NC 128
#define MTOT (NB*NT)
#define EPSV 1e-5f
#define SCALEV 0.08838834764831845f  /* 1/sqrt(128) */
#define NEGBIG -1e30f

// ---------------- scratch (device globals; established set only) ------------
__device__ float g_vr[(size_t)NB*NT*NC];
__device__ float g_vs[(size_t)NB*NT*NC];
__device__ float g_q [(size_t)NB*NT*NC];
__device__ float g_on[(size_t)NB*NT*NC];
__device__ float g_mr[MTOT], g_ms[MTOT], g_varr[MTOT], g_vars[MTOT];
__device__ float g_sumq[MTOT], g_qvr[MTOT];

// ---------------- helpers ----------------------------------------------------
__device__ __forceinline__ uint32_t smem_u32(const void* p) {
    uint32_t a;
    asm("{ .reg .u64 t; cvta.to.shared.u64 t, %1; cvt.u32.u64 %0, t; }"
        : "=r"(a) : "l"(p));
    return a;
}
// packed bf16x2: low half = x, high half = y (1 instruction)
__device__ __forceinline__ uint32_t pack_hi(float x, float y) {
    uint32_t r;
    asm("cvt.rn.bf16x2.f32 %0, %1, %2;" : "=r"(r) : "f"(y), "f"(x));
    return r;
}
__device__ __forceinline__ uint32_t pack_lo(float x, float y) {
    const uint32_t h = pack_hi(x, y);
    const float fx = __uint_as_float(h << 16);
    const float fy = __uint_as_float(h & 0xffff0000u);
    return pack_hi(x - fx, y - fy);
}
__device__ __forceinline__ void pack_both(float x, float y, uint32_t& h, uint32_t& l) {
    h = pack_hi(x, y);
    const float fx = __uint_as_float(h << 16);
    const float fy = __uint_as_float(h & 0xffff0000u);
    l = pack_hi(x - fx, y - fy);
}
#define MMA16816(d, a, b) \
    asm volatile("mma.sync.aligned.m16n8k16.row.col.f32.bf16.bf16.f32 " \
        "{%0,%1,%2,%3}, {%4,%5,%6,%7}, {%8,%9}, {%0,%1,%2,%3};" \
        : "+f"((d)[0]), "+f"((d)[1]), "+f"((d)[2]), "+f"((d)[3]) \
        : "r"((a)[0]), "r"((a)[1]), "r"((a)[2]), "r"((a)[3]), \
          "r"((b)[0]), "r"((b)[1]))
#define LDSMT(r0, r1, r2, r3, addr) \
    asm volatile("ldmatrix.sync.aligned.m8n8.x4.trans.shared.b16 {%0,%1,%2,%3}, [%4];" \
        : "=r"(r0), "=r"(r1), "=r"(r2), "=r"(r3) : "r"(addr))
#define LDSM4(r, addr) \
    asm volatile("ldmatrix.sync.aligned.m8n8.x4.shared.b16 {%0,%1,%2,%3}, [%4];" \
        : "=r"((r)[0]), "=r"((r)[1]), "=r"((r)[2]), "=r"((r)[3]) : "r"(addr))

#define PW 68

// ======================= flash kernel (8 warps, in-block j-split) ============
// i-tile 64; warp (rg=w&3, jh=w>>2): rows 16*rg..+15, j-half 32*jh..+31.
#define APLANE (64*PW)
#define FL_SMEM ((4*APLANE + 6*64 + 2*128 + 4*128) * 4)

__global__ void __launch_bounds__(256, 2) flash_mma(const int* __restrict__ mask,
                                                    const float* __restrict__ nw,
                                                    const float* __restrict__ nb)
{
    extern __shared__ __align__(16) uint32_t sm[];
    uint32_t* qh = sm;
    uint32_t* rh = qh + APLANE;
    uint32_t* bh = rh + APLANE;
    uint32_t* bl = bh + APLANE;
    float* s_mr   = (float*)(bl + APLANE);
    float* s_varr = s_mr + 64;
    float* s_sq   = s_varr + 64;
    float* s_qvr  = s_sq + 64;
    float* s_ms   = s_qvr + 64;
    float* s_vars = s_ms + 64;
    float* s_nw   = s_vars + 64;
    float* s_nb   = s_nw + 128;
    float* s_tm   = s_nb + 128;     // [jh*64 + row] tile max exchange
    float* s_l    = s_tm + 128;     // final scalar exchange
    float* s_rp   = s_l + 128;
    float* s_rpm  = s_rp + 128;

    const uint32_t sb = smem_u32(sm);
    const uint32_t bh_addr = sb + 2u*APLANE*4u;

    const int tid = threadIdx.x;
    const int wid = tid >> 5, lane = tid & 31;
    const int g = lane >> 2, t = lane & 3;
    const int rg = wid & 3, jh = wid >> 2;
    const int wr = rg * 16;
    const int jb = jh * 32;
    const int i0 = blockIdx.x * 64, b = blockIdx.y;

    // ldmatrix address bases (A: rows by lane&15, k-half by lane>>4;
    //  B: nt pair by lane>>4, k-half by (lane>>3)&1, row by lane&7)
    const uint32_t aq_base = sb + (((uint32_t)(wr + (lane & 15)) * PW
                                  + (uint32_t)((lane >> 4) * 4)) * 4u);
    const uint32_t ar_base = aq_base + (uint32_t)APLANE * 4u;
    const uint32_t b_base0 = bh_addr + (((uint32_t)(jb + (lane >> 4) * 8 + (lane & 7)) * PW
                                  + (uint32_t)(((lane >> 3) & 1) * 4)) * 4u);
    const uint32_t b_base1 = b_base0 + (uint32_t)(16 * PW) * 4u;
    const uint32_t bl_off  = (uint32_t)APLANE * 4u;

    // ---- fill A planes (q, v_r hi) + row stats + LN params
    {
        const float* qsrc = g_q  + ((size_t)b*NT + i0) * NC;
        const float* rsrc = g_vr + ((size_t)b*NT + i0) * NC;
        for (int idx = tid; idx < 64*64; idx += 256) {
            const int row = idx >> 6, kp = idx & 63;
            float2 v = ((const float2*)(qsrc + (size_t)row*NC))[kp];
            qh[row*PW + kp] = pack_hi(v.x, v.y);
            float2 w = ((const float2*)(rsrc + (size_t)row*NC))[kp];
            rh[row*PW + kp] = pack_hi(w.x, w.y);
        }
        if (tid < 64) {
            const int r = b*NT + i0 + tid;
            s_mr[tid] = g_mr[r]; s_varr[tid] = g_varr[r];
            s_sq[tid] = g_sumq[r]; s_qvr[tid] = g_qvr[r];
        }
        if (tid < 128) { s_nw[tid] = nw[tid]; s_nb[tid] = nb[tid]; }
    }
    __syncthreads();

    const float mr0 = s_mr[wr+g],   varr0 = s_varr[wr+g];
    const float sq0 = s_sq[wr+g],   qvr0  = s_qvr[wr+g];
    const float mr1 = s_mr[wr+g+8], varr1 = s_varr[wr+g+8];
    const float sq1 = s_sq[wr+g+8], qvr1  = s_qvr[wr+g+8];

    float m0 = NEGBIG, m1 = NEGBIG;
    float l0 = 0.f, rp0 = 0.f, rpm0 = 0.f;
    float l1 = 0.f, rp1 = 0.f, rpm1 = 0.f;
    float dO[16][4];
    #pragma unroll
    for (int n = 0; n < 16; n++)
        #pragma unroll
        for (int e = 0; e < 4; e++) dO[n][e] = 0.f;

    const size_t mrow0 = ((size_t)(b*NT + i0 + wr + g)) * NT;
    const size_t mrow1 = mrow0 + (size_t)8 * NT;

    for (int jt = 0; jt < NT/64; jt++) {
        const int j0 = jt * 64;
        __syncthreads();                  // prior tile's B reads + s_tm reads done

        // ---- fill B planes (v_s hi/lo) + col stats
        {
            const float* bsrc = g_vs + ((size_t)b*NT + j0) * NC;
            for (int idx = tid; idx < 64*64; idx += 256) {
                const int row = idx >> 6, kp = idx & 63;
                float2 v = ((const float2*)(bsrc + (size_t)row*NC))[kp];
                uint32_t h, l;
                pack_both(v.x, v.y, h, l);
                bh[row*PW + kp] = h;
                bl[row*PW + kp] = l;
            }
            if (tid < 64) {
                const int c = b*NT + j0 + tid;
                s_ms[tid] = g_ms[c]; s_vars[tid] = g_vars[c];
            }
        }
        __syncthreads();

        // ---- score dual MMA on this warp's j-half (4 n-tiles), ldmatrix frags
        float dR[4][4], dQ[4][4];
        #pragma unroll
        for (int n = 0; n < 4; n++)
            #pragma unroll
            for (int e = 0; e < 4; e++) { dR[n][e] = 0.f; dQ[n][e] = 0.f; }

        #pragma unroll
        for (int ks = 0; ks < 8; ks++) {
            const uint32_t ko = (uint32_t)ks * 32u;    // 8 words = 32 bytes
            uint32_t QH[4], RH[4], B0[4], B1[4], C0[4], C1[4];
            LDSM4(QH, aq_base + ko);
            LDSM4(RH, ar_base + ko);
            LDSM4(B0, b_base0 + ko);            // BH nt0, nt1
            LDSM4(B1, b_base1 + ko);            // BH nt2, nt3
            LDSM4(C0, b_base0 + bl_off + ko);   // BL nt0, nt1
            LDSM4(C1, b_base1 + bl_off + ko);   // BL nt2, nt3
            uint32_t BH0[2] = {B0[0], B0[1]}, BH1[2] = {B0[2], B0[3]};
            uint32_t BH2[2] = {B1[0], B1[1]}, BH3[2] = {B1[2], B1[3]};
            uint32_t BL0[2] = {C0[0], C0[1]}, BL1[2] = {C0[2], C0[3]};
            uint32_t BL2[2] = {C1[0], C1[1]}, BL3[2] = {C1[2], C1[3]};
            MMA16816(dQ[0], QH, BH0); MMA16816(dQ[0], QH, BL0);
            MMA16816(dR[0], RH, BH0); MMA16816(dR[0], RH, BL0);
            MMA16816(dQ[1], QH, BH1); MMA16816(dQ[1], QH, BL1);
            MMA16816(dR[1], RH, BH1); MMA16816(dR[1], RH, BL1);
            MMA16816(dQ[2], QH, BH2); MMA16816(dQ[2], QH, BL2);
            MMA16816(dR[2], RH, BH2); MMA16816(dR[2], RH, BL2);
            MMA16816(dQ[3], QH, BH3); MMA16816(dQ[3], QH, BL3);
            MMA16816(dR[3], RH, BH3); MMA16816(dR[3], RH, BL3);
        }

        // ---- scores: rstd via rsqrt (a -> dQ, rstd -> dR); half-tile max
        float tmax0 = NEGBIG, tmax1 = NEGBIG;
        #pragma unroll
        for (int nt = 0; nt < 4; nt++) {
            const int2 mk0 = *(const int2*)(mask + mrow0 + j0 + jb + nt*8 + t*2);
            const int2 mk1 = *(const int2*)(mask + mrow1 + j0 + jb + nt*8 + t*2);
            #pragma unroll
            for (int c = 0; c < 2; c++) {
                const int j = jb + nt*8 + t*2 + c;
                const float msj = s_ms[j], vars = s_vars[j];
                {
                    const float cross = (dR[nt][c] - 128.f*mr0*msj) * (2.f/128.f);
                    const float rstd = rsqrtf(varr0 + vars + cross + EPSV);
                    float a = (qvr0 + dQ[nt][c] - sq0*(mr0+msj)) * rstd * SCALEV;
                    if ((c == 0 ? mk0.x : mk0.y) != 0) a = NEGBIG;
                    dQ[nt][c] = a; dR[nt][c] = rstd;
                    tmax0 = fmaxf(tmax0, a);
                }
                {
                    const float cross = (dR[nt][2+c] - 128.f*mr1*msj) * (2.f/128.f);
                    const float rstd = rsqrtf(varr1 + vars + cross + EPSV);
                    float a = (qvr1 + dQ[nt][2+c] - sq1*(mr1+msj)) * rstd * SCALEV;
                    if ((c == 0 ? mk1.x : mk1.y) != 0) a = NEGBIG;
                    dQ[nt][2+c] = a; dR[nt][2+c] = rstd;
                    tmax1 = fmaxf(tmax1, a);
                }
            }
        }
        tmax0 = fmaxf(tmax0, __shfl_xor_sync(0xffffffffu, tmax0, 1));
        tmax0 = fmaxf(tmax0, __shfl_xor_sync(0xffffffffu, tmax0, 2));
        tmax1 = fmaxf(tmax1, __shfl_xor_sync(0xffffffffu, tmax1, 1));
        tmax1 = fmaxf(tmax1, __shfl_xor_sync(0xffffffffu, tmax1, 2));

        // ---- exchange half-tile maxes between partner warps (same rows)
        if (t == 0) {
            s_tm[jh*64 + wr + g]     = tmax0;
            s_tm[jh*64 + wr + g + 8] = tmax1;
        }
        __syncthreads();
        const float ptm0 = s_tm[(jh^1)*64 + wr + g];
        const float ptm1 = s_tm[(jh^1)*64 + wr + g + 8];

        const float mn0 = fmaxf(m0, fmaxf(tmax0, ptm0)), sc0 = __expf(m0 - mn0);
        const float mn1 = fmaxf(m1, fmaxf(tmax1, ptm1)), sc1 = __expf(m1 - mn1);
        m0 = mn0; m1 = mn1;
        l0 *= sc0; rp0 *= sc0; rpm0 *= sc0;
        l1 *= sc1; rp1 *= sc1; rpm1 *= sc1;
        #pragma unroll
        for (int n = 0; n < 16; n++) {
            dO[n][0] *= sc0; dO[n][1] *= sc0;
            dO[n][2] *= sc1; dO[n][3] *= sc1;
        }

        // ---- W = exp(a-m)*rstd; accumulate row scalars (this half)
        float W[4][4];
        #pragma unroll
        for (int nt = 0; nt < 4; nt++) {
            #pragma unroll
            for (int c = 0; c < 2; c++) {
                const int j = jb + nt*8 + t*2 + c;
                const float msj = s_ms[j];
                const float u0 = __expf(dQ[nt][c] - m0);
                const float w0 = u0 * dR[nt][c];
                l0 += u0; rp0 += w0; rpm0 += w0 * (mr0 + msj);
                W[nt][c] = w0;
                const float u1 = __expf(dQ[nt][2+c] - m1);
                const float w1 = u1 * dR[nt][2+c];
                l1 += u1; rp1 += w1; rpm1 += w1 * (mr1 + msj);
                W[nt][2+c] = w1;
            }
        }

        // ---- O += W @ v_s over this j-half (hi*hi only), k = 32
        #pragma unroll
        for (int ks = 0; ks < 2; ks++) {
            uint32_t Ah[4] = {
                pack_hi(W[2*ks][0],   W[2*ks][1]),   pack_hi(W[2*ks][2],   W[2*ks][3]),
                pack_hi(W[2*ks+1][0], W[2*ks+1][1]), pack_hi(W[2*ks+1][2], W[2*ks+1][3]) };
            const uint32_t loff = ((uint32_t)(jb + ks*16 + (lane & 15)) * PW
                                 + (uint32_t)((lane >> 4) * 4)) * 4u;
            #pragma unroll
            for (int dp = 0; dp < 8; dp++) {
                const uint32_t off = loff + (uint32_t)(dp*8) * 4u;
                uint32_t h0, h1, h2, h3;
                LDSMT(h0, h1, h2, h3, bh_addr + off);
                uint32_t BH0[2] = {h0, h1}, BH1[2] = {h2, h3};
                MMA16816(dO[2*dp],   Ah, BH0);
                MMA16816(dO[2*dp+1], Ah, BH1);
            }
        }
    }

    // ---- finalize: reduce scalars over t-quad; combine halves (same m -> add)
    l0   += __shfl_xor_sync(0xffffffffu, l0, 1);   l0   += __shfl_xor_sync(0xffffffffu, l0, 2);
    rp0  += __shfl_xor_sync(0xffffffffu, rp0, 1);  rp0  += __shfl_xor_sync(0xffffffffu, rp0, 2);
    rpm0 += __shfl_xor_sync(0xffffffffu, rpm0, 1); rpm0 += __shfl_xor_sync(0xffffffffu, rpm0, 2);
    l1   += __shfl_xor_sync(0xffffffffu, l1, 1);   l1   += __shfl_xor_sync(0xffffffffu, l1, 2);
    rp1  += __shfl_xor_sync(0xffffffffu, rp1, 1);  rp1  += __shfl_xor_sync(0xffffffffu, rp1, 2);
    rpm1 += __shfl_xor_sync(0xffffffffu, rpm1, 1); rpm1 += __shfl_xor_sync(0xffffffffu, rpm1, 2);

    if (t == 0) {
        s_l[jh*64 + wr+g] = l0;    s_l[jh*64 + wr+g+8] = l1;
        s_rp[jh*64 + wr+g] = rp0;  s_rp[jh*64 + wr+g+8] = rp1;
        s_rpm[jh*64 + wr+g] = rpm0; s_rpm[jh*64 + wr+g+8] = rpm1;
    }
    __syncthreads();   // scalars posted; planes dead -> reuse qh/rh as float buffer

    float* fx = (float*)sm;   // 64 rows x 128 d = 32 KB (fits in qh+rh planes)
    if (jh == 1) {
        #pragma unroll
        for (int n = 0; n < 16; n++) {
            const int d0 = n*8 + t*2;
            *(float2*)(fx + (wr+g)*128 + d0)   = make_float2(dO[n][0], dO[n][1]);
            *(float2*)(fx + (wr+g+8)*128 + d0) = make_float2(dO[n][2], dO[n][3]);
        }
    }
    __syncthreads();

    if (jh == 0) {
        const float L0   = l0   + s_l[64 + wr+g];
        const float RP0  = rp0  + s_rp[64 + wr+g];
        const float RPM0 = rpm0 + s_rpm[64 + wr+g];
        const float L1   = l1   + s_l[64 + wr+g+8];
        const float RP1  = rp1  + s_rp[64 + wr+g+8];
        const float RPM1 = rpm1 + s_rpm[64 + wr+g+8];
        const float inv0 = (L0 > 0.f) ? __fdividef(1.f, L0) : 0.f;
        const float inv1 = (L1 > 0.f) ? __fdividef(1.f, L1) : 0.f;

        const size_t rbase0 = ((size_t)(b*NT + i0 + wr + g)) * NC;
        const size_t rbase1 = rbase0 + (size_t)8 * NC;
        #pragma unroll
        for (int n = 0; n < 16; n++) {
            const int d0 = n*8 + t*2;
            const float2 oA = *(const float2*)(fx + (wr+g)*128 + d0);
            const float2 vrA = *(const float2*)(g_vr + rbase0 + d0);
            float v0 = (dO[n][0] + oA.x + RP0*vrA.x - RPM0) * inv0;
            float v1 = (dO[n][1] + oA.y + RP0*vrA.y - RPM0) * inv0;
            v0 = v0 * s_nw[d0]   + s_nb[d0];
            v1 = v1 * s_nw[d0+1] + s_nb[d0+1];
            *(float2*)(g_on + rbase0 + d0) = make_float2(v0, v1);
            const float2 oB = *(const float2*)(fx + (wr+g+8)*128 + d0);
            const float2 vrB = *(const float2*)(g_vr + rbase1 + d0);
            float w0 = (dO[n][2] + oB.x + RP1*vrB.x - RPM1) * inv1;
            float w1 = (dO[n][3] + oB.y + RP1*vrB.y - RPM1) * inv1;
            w0 = w0 * s_nw[d0]   + s_nb[d0];
            w1 = w1 * s_nw[d0+1] + s_nb[d0+1];
            *(float2*)(g_on + rbase1 + d0) = make_float2(w0, w1);
        }
    }
}

// ======================= qkv projections via HMMA ===========================
#define QPLANE (128*PW)
#define QK_SMEM (4*QPLANE*4)

__global__ void __launch_bounds__(512, 1) qkv_mma(const float* __restrict__ x,
                                                  const float* __restrict__ recv,
                                                  const float* __restrict__ send,
                                                  const float* __restrict__ res_r,
                                                  const float* __restrict__ res_s,
                                                  const float* __restrict__ ra,
                                                  const float* __restrict__ qw)
{
    extern __shared__ __align__(16) uint32_t sm[];
    uint32_t* ah_ = sm;
    uint32_t* al_ = ah_ + QPLANE;
    uint32_t* wh_ = al_ + QPLANE;
    uint32_t* wl_ = wh_ + QPLANE;

    const int tid = threadIdx.x;
    const int wid = tid >> 5, lane = tid & 31;
    const int g = lane >> 2, t = lane & 3;
    const int wr = (wid & 3) * 32, wc = (wid >> 2) * 32;
    const int mode = blockIdx.y;
    const int r0 = blockIdx.x * 128;

    float acc[2][4][4];
    #pragma unroll
    for (int mt = 0; mt < 2; mt++)
        #pragma unroll
        for (int nt = 0; nt < 4; nt++)
            #pragma unroll
            for (int e = 0; e < 4; e++) acc[mt][nt][e] = 0.f;

    const int nsrc = (mode == 2) ? 1 : 2;
    for (int src = 0; src < nsrc; src++) {
        const float* A; const float* W; int ws;
        if (mode == 0)      { A = src ? recv : x; W = src ? ra : ra + NC;   ws = 3*NC; }
        else if (mode == 1) { A = src ? send : x; W = src ? ra : ra + 2*NC; ws = 3*NC; }
        else                { A = x; W = qw; ws = NC; }

        __syncthreads();
        for (int idx = tid; idx < 128*64; idx += 512) {
            const int row = idx >> 6, kp = idx & 63;
            const int r = r0 + row, bb = r / NT, n = r % NT;
            float2 v = ((const float2*)(A + (size_t)n*NB*NC + (size_t)bb*NC))[kp];
            uint32_t h, l;
            pack_both(v.x, v.y, h, l);
            ah_[row*PW + kp] = h;
            al_[row*PW + kp] = l;
            float2 w = ((const float2*)(W + (size_t)row*ws))[kp];
            pack_both(w.x, w.y, h, l);
            wh_[row*PW + kp] = h;
            wl_[row*PW + kp] = l;
        }
        __syncthreads();

        #pragma unroll
        for (int ks = 0; ks < 8; ks++) {
            const int kp0 = ks*8 + t;
            uint32_t Bh[4][2], Bl[4][2];
            #pragma unroll
            for (int nt = 0; nt < 4; nt++) {
                const int br = (wc + nt*8 + g)*PW;
                Bh[nt][0] = wh_[br+kp0]; Bh[nt][1] = wh_[br+kp0+4];
                Bl[nt][0] = wl_[br+kp0]; Bl[nt][1] = wl_[br+kp0+4];
            }
            #pragma unroll
            for (int mt = 0; mt < 2; mt++) {
                const int ar = (wr + mt*16 + g)*PW, ar8 = ar + 8*PW;
                uint32_t Ah[4] = { ah_[ar+kp0], ah_[ar8+kp0], ah_[ar+kp0+4], ah_[ar8+kp0+4] };
                uint32_t Al[4] = { al_[ar+kp0], al_[ar8+kp0], al_[ar+kp0+4], al_[ar8+kp0+4] };
                #pragma unroll
                for (int nt = 0; nt < 4; nt++) {
                    MMA16816(acc[mt][nt], Ah, Bh[nt]);
                    MMA16816(acc[mt][nt], Ah, Bl[nt]);
                    MMA16816(acc[mt][nt], Al, Bh[nt]);
                }
            }
        }
    }

    float* out = (mode == 0) ? g_vr : (mode == 1) ? g_vs : g_q;
    const float* res = (mode == 0) ? res_r : (mode == 1) ? res_s : nullptr;
    #pragma unroll
    for (int mt = 0; mt < 2; mt++) {
        #pragma unroll
        for (int rg = 0; rg < 2; rg++) {
            const int li = wr + mt*16 + g + rg*8;
            const int r = r0 + li, bb = r / NT, n = r % NT;
            #pragma unroll
            for (int nt = 0; nt < 4; nt++) {
                const int c = wc + nt*8 + t*2;
                float v0 = acc[mt][nt][rg*2+0];
                float v1 = acc[mt][nt][rg*2+1];
                if (res) {
                    float2 rr = *(const float2*)(res + (size_t)n*NB*NC + (size_t)bb*NC + c);
                    v0 += rr.x; v1 += rr.y;
                }
                *(float2*)(out + ((size_t)bb*NT + n)*NC + c) = make_float2(v0, v1);
            }
        }
    }
}

// ======================= output projections via HMMA ========================
__global__ void __launch_bounds__(512, 1) proj_mma(const float* __restrict__ pw,
                                                   const float* __restrict__ pb,
                                                   const float* __restrict__ rw,
                                                   const float* __restrict__ rb,
                                                   const float* __restrict__ sw,
                                                   const float* __restrict__ sb,
                                                   float* __restrict__ out)
{
    extern __shared__ __align__(16) uint32_t sm[];
    uint32_t* ah_ = sm;
    uint32_t* al_ = ah_ + QPLANE;
    uint32_t* wh_ = al_ + QPLANE;
    uint32_t* wl_ = wh_ + QPLANE;

    const int tid = threadIdx.x;
    const int wid = tid >> 5, lane = tid & 31;
    const int g = lane >> 2, t = lane & 3;
    const int wr = (wid & 3) * 32, wc = (wid >> 2) * 32;
    const int mode = blockIdx.y;
    const int r0 = blockIdx.x * 128;

    const float* src = (mode == 0) ? g_on : (mode == 1) ? g_vr : g_vs;
    const float* W   = (mode == 0) ? pw   : (mode == 1) ? rw   : sw;
    const float* bia = (mode == 0) ? pb   : (mode == 1) ? rb   : sb;

    for (int idx = tid; idx < 128*64; idx += 512) {
        const int row = idx >> 6, kp = idx & 63;
        float2 v = ((const float2*)(src + (size_t)(r0+row)*NC))[kp];
        uint32_t h, l;
        pack_both(v.x, v.y, h, l);
        ah_[row*PW + kp] = h;
        al_[row*PW + kp] = l;
        float2 w = ((const float2*)(W + (size_t)row*NC))[kp];
        pack_both(w.x, w.y, h, l);
        wh_[row*PW + kp] = h;
        wl_[row*PW + kp] = l;
    }
    __syncthreads();

    float acc[2][4][4];
    #pragma unroll
    for (int mt = 0; mt < 2; mt++)
        #pragma unroll
        for (int nt = 0; nt < 4; nt++)
            #pragma unroll
            for (int e = 0; e < 4; e++) acc[mt][nt][e] = 0.f;

    #pragma unroll
    for (int ks = 0; ks < 8; ks++) {
        const int kp0 = ks*8 + t;
        uint32_t Bh[4][2], Bl[4][2];
        #pragma unroll
        for (int nt = 0; nt < 4; nt++) {
            const int br = (wc + nt*8 + g)*PW;
            Bh[nt][0] = wh_[br+kp0]; Bh[nt][1] = wh_[br+kp0+4];
            Bl[nt][0] = wl_[br+kp0]; Bl[nt][1] = wl_[br+kp0+4];
        }
        #pragma unroll
        for (int mt = 0; mt < 2; mt++) {
            const int ar = (wr + mt*16 + g)*PW, ar8 = ar + 8*PW;
            uint32_t Ah[4] = { ah_[ar+kp0], ah_[ar8+kp0], ah_[ar+kp0+4], ah_[ar8+kp0+4] };
            uint32_t Al[4] = { al_[ar+kp0], al_[ar8+kp0], al_[ar+kp0+4], al_[ar8+kp0+4] };
            #pragma unroll
            for (int nt = 0; nt < 4; nt++) {
                MMA16816(acc[mt][nt], Ah, Bh[nt]);
                MMA16816(acc[mt][nt], Ah, Bl[nt]);
                MMA16816(acc[mt][nt], Al, Bh[nt]);
            }
        }
    }

    const size_t obase = (size_t)mode * MTOT * NC;
    #pragma unroll
    for (int mt = 0; mt < 2; mt++) {
        #pragma unroll
        for (int rg = 0; rg < 2; rg++) {
            const int li = wr + mt*16 + g + rg*8;
            const int r = r0 + li, bb = r / NT, n = r % NT;
            #pragma unroll
            for (int nt = 0; nt < 4; nt++) {
                const int c = wc + nt*8 + t*2;
                const float2 bb2 = *(const float2*)(bia + c);
                float v0 = acc[mt][nt][rg*2+0] + bb2.x;
                float v1 = acc[mt][nt][rg*2+1] + bb2.y;
                *(float2*)(out + obase + (size_t)n*NB*NC + (size_t)bb*NC + c) = make_float2(v0, v1);
            }
        }
    }
}

// ---------------- per-row stats ----------------------------------------------
__global__ void row_stats()
{
    const int r = blockIdx.x;
    const int c = threadIdx.x;           // 128 threads
    const size_t base = (size_t)r * NC + c;
    float vr = g_vr[base], vs = g_vs[base], q = g_q[base];
    __shared__ float sh[6][128];
    sh[0][c] = vr; sh[1][c] = vr*vr; sh[2][c] = vs;
    sh[3][c] = vs*vs; sh[4][c] = q; sh[5][c] = q*vr;
    __syncthreads();
    for (int off = 64; off > 0; off >>= 1) {
        if (c < off)
            #pragma unroll
            for (int i = 0; i < 6; i++) sh[i][c] += sh[i][c + off];
        __syncthreads();
    }
    if (c == 0) {
        float mr = sh[0][0] * (1.f/NC);
        float ms = sh[2][0] * (1.f/NC);
        g_mr[r] = mr;
        g_ms[r] = ms;
        g_varr[r] = sh[1][0] * (1.f/NC) - mr*mr;
        g_vars[r] = sh[3][0] * (1.f/NC) - ms*ms;
        g_sumq[r] = sh[4][0];
        g_qvr[r]  = sh[5][0];
    }
}

// ---------------- launch ----------------------------------------------------
extern "C" void kernel_launch(void* const* d_in, const int* in_sizes, int n_in,
                              void* d_out, int out_size)
{
    const float* x    = (const float*)d_in[0];
    const int*   mask = (const int*)d_in[1];      // bool uploaded as int32
    const float* recv = (const float*)d_in[2];
    const float* send = (const float*)d_in[3];
    const float* resr = (const float*)d_in[4];
    const float* ress = (const float*)d_in[5];
    const float* ra   = (const float*)d_in[6];
    const float* qw   = (const float*)d_in[7];
    const float* pw   = (const float*)d_in[8];
    const float* pb   = (const float*)d_in[9];
    const float* rw   = (const float*)d_in[10];
    const float* rb   = (const float*)d_in[11];
    const float* sw   = (const float*)d_in[12];
    const float* sb   = (const float*)d_in[13];
    const float* nw   = (const float*)d_in[14];
    const float* nb   = (const float*)d_in[15];
    float* out = (float*)d_out;

    cudaFuncSetAttribute(flash_mma, cudaFuncAttributeMaxDynamicSharedMemorySize, FL_SMEM);
    cudaFuncSetAttribute(qkv_mma,   cudaFuncAttributeMaxDynamicSharedMemorySize, QK_SMEM);
    cudaFuncSetAttribute(proj_mma,  cudaFuncAttributeMaxDynamicSharedMemorySize, QK_SMEM);

    qkv_mma<<<dim3(MTOT/128, 3), 512, QK_SMEM>>>(x, recv, send, resr, ress, ra, qw);
    row_stats<<<MTOT, 128>>>();
    flash_mma<<<dim3(NT/64, NB), 256, FL_SMEM>>>(mask, nw, nb);
    proj_mma<<<dim3(MTOT/128, 3), 512, QK_SMEM>>>(pw, pb, rw, rb, sw, sb, out);
}